// round 1
// baseline (speedup 1.0000x reference)
#include <cuda_runtime.h>
#include <cstdint>
#include <cstddef>

#define B_   2
#define S_   2048
#define DIM_ 4096
#define NH_  32
#define NKV_ 8
#define HD_  128

// ---------------- scratch (no allocations allowed) ----------------
__device__ float g_q[(size_t)B_ * S_ * NH_ * HD_];     // 16.7M floats = 64MB
__device__ float g_k[(size_t)B_ * S_ * NKV_ * HD_];    // 16MB
__device__ float g_v[(size_t)B_ * S_ * NKV_ * HD_];    // 16MB
__device__ float g_att[(size_t)B_ * S_ * NH_ * HD_];   // 64MB

// ============================================================================
// SGEMM: C[M,N] = A[M,K] @ B[K,N], all row-major fp32.
// Block 128x128, K-tile 16, 256 threads, 8x8 microtile, float4 everywhere.
// Requires M%128==0, N%128==0, K%16==0 (true for all our shapes).
// ============================================================================
__global__ __launch_bounds__(256) void sgemm128(const float* __restrict__ A,
                                                const float* __restrict__ Bm,
                                                float* __restrict__ C,
                                                int M, int N, int K)
{
    constexpr int BM = 128, BN = 128, BK = 16;
    __shared__ __align__(16) float As[BK][BM + 4];   // A stored transposed
    __shared__ __align__(16) float Bs[BK][BN + 4];

    const int tid = threadIdx.x;
    const int tx = tid & 15;        // 0..15
    const int ty = tid >> 4;        // 0..15
    const int row0 = blockIdx.y * BM;
    const int col0 = blockIdx.x * BN;

    float acc[8][8];
#pragma unroll
    for (int i = 0; i < 8; ++i)
#pragma unroll
        for (int j = 0; j < 8; ++j) acc[i][j] = 0.f;

    for (int k0 = 0; k0 < K; k0 += BK) {
#pragma unroll
        for (int it = 0; it < 2; ++it) {
            int id = tid + it * 256;
            // A tile: 128 rows x 16 k  (512 float4)
            int ar = id >> 2;            // 0..127
            int ac = (id & 3) << 2;      // 0,4,8,12
            const float4 a = *(const float4*)(A + (size_t)(row0 + ar) * K + k0 + ac);
            As[ac + 0][ar] = a.x;
            As[ac + 1][ar] = a.y;
            As[ac + 2][ar] = a.z;
            As[ac + 3][ar] = a.w;
            // B tile: 16 k x 128 cols (512 float4)
            int br = id >> 5;            // 0..15
            int bc = (id & 31) << 2;     // 0..124
            *(float4*)(&Bs[br][bc]) =
                *(const float4*)(Bm + (size_t)(k0 + br) * N + col0 + bc);
        }
        __syncthreads();

#pragma unroll
        for (int k = 0; k < BK; ++k) {
            float ra[8], rb[8];
            *(float4*)&ra[0] = *(const float4*)&As[k][ty * 8 + 0];
            *(float4*)&ra[4] = *(const float4*)&As[k][ty * 8 + 4];
            *(float4*)&rb[0] = *(const float4*)&Bs[k][tx * 8 + 0];
            *(float4*)&rb[4] = *(const float4*)&Bs[k][tx * 8 + 4];
#pragma unroll
            for (int i = 0; i < 8; ++i)
#pragma unroll
                for (int j = 0; j < 8; ++j)
                    acc[i][j] = fmaf(ra[i], rb[j], acc[i][j]);
        }
        __syncthreads();
    }

#pragma unroll
    for (int i = 0; i < 8; ++i) {
        float* c = C + (size_t)(row0 + ty * 8 + i) * N + col0 + tx * 8;
        *(float4*)(c + 0) = make_float4(acc[i][0], acc[i][1], acc[i][2], acc[i][3]);
        *(float4*)(c + 4) = make_float4(acc[i][4], acc[i][5], acc[i][6], acc[i][7]);
    }
}

// ============================================================================
// RoPE (interleaved-pair convention): t is [B, S, nh, 128]; pair p uses
// cos/sin[s, p]. One thread per pair.
// ============================================================================
__global__ __launch_bounds__(256) void rope_kernel(float* __restrict__ t,
                                                   const float* __restrict__ cs,
                                                   const float* __restrict__ sn,
                                                   int nh)
{
    int idx = blockIdx.x * blockDim.x + threadIdx.x;
    int total = B_ * S_ * nh * 64;
    if (idx >= total) return;
    int p = idx & 63;
    int s = (idx / (64 * nh)) & (S_ - 1);
    float c  = cs[(s << 6) + p];
    float si = sn[(s << 6) + p];
    float* v = t + ((size_t)idx << 1);
    float xr = v[0], xi = v[1];
    v[0] = fmaf(xr, c, -xi * si);
    v[1] = fmaf(xr, si,  xi * c);
}

// ============================================================================
// Attention (full, non-causal), flash-style online softmax.
// grid = (S/64, NH, B), block = 256 (16x16 thread tiling).
// Q: [B,S,32,128], K/V: [B,S,8,128]; out att: [B,S,32*128].
// smem: sS 16KB + union(QK d-chunks | V block) 32KB = 48KB exactly.
// ============================================================================
__global__ __launch_bounds__(256) void attn_kernel(const float* __restrict__ Q,
                                                   const float* __restrict__ K,
                                                   const float* __restrict__ V,
                                                   float* __restrict__ Oout)
{
    __shared__ __align__(16) float sS[64 * 64];       // 16KB: scores / P
    __shared__ __align__(16) float sBuf[64 * 128];    // 32KB: QK chunks, then V

    float* sQc = sBuf;              // 64 x 17 (padded)
    float* sKc = sBuf + 64 * 17;    // 64 x 17 (padded)

    const int tid = threadIdx.x;
    const int tx = tid & 15, ty = tid >> 4;
    const int ty4 = ty << 2, tx4 = tx << 2;
    const int q0 = blockIdx.x * 64;
    const int h  = blockIdx.y;
    const int b  = blockIdx.z;
    const int kvh = h >> 2;          // N_REP = 4
    const float scale = 0.08838834764831845f;  // 1/sqrt(128)

    float o[4][8];
    float m[4], l[4];
#pragma unroll
    for (int i = 0; i < 4; ++i) {
        m[i] = -1e30f; l[i] = 0.f;
#pragma unroll
        for (int u = 0; u < 8; ++u) o[i][u] = 0.f;
    }

    const int lr = tid >> 2;          // 0..63 (load row)
    const int lc = (tid & 3) << 2;    // 0,4,8,12 (load col within 16-chunk)

    for (int kb = 0; kb < S_ / 64; ++kb) {
        float sacc[4][4];
#pragma unroll
        for (int i = 0; i < 4; ++i)
#pragma unroll
            for (int j = 0; j < 4; ++j) sacc[i][j] = 0.f;

        // ---- S = Q K^T over 8 chunks of d=16 ----
        for (int dc = 0; dc < 8; ++dc) {
            {
                const float4 qv = *(const float4*)(Q +
                    (((size_t)(b * S_ + q0 + lr) * NH_ + h) << 7) + dc * 16 + lc);
                sQc[lr * 17 + lc + 0] = qv.x;
                sQc[lr * 17 + lc + 1] = qv.y;
                sQc[lr * 17 + lc + 2] = qv.z;
                sQc[lr * 17 + lc + 3] = qv.w;
                const float4 kv = *(const float4*)(K +
                    (((size_t)(b * S_ + kb * 64 + lr) * NKV_ + kvh) << 7) + dc * 16 + lc);
                sKc[lr * 17 + lc + 0] = kv.x;
                sKc[lr * 17 + lc + 1] = kv.y;
                sKc[lr * 17 + lc + 2] = kv.z;
                sKc[lr * 17 + lc + 3] = kv.w;
            }
            __syncthreads();
#pragma unroll
            for (int d = 0; d < 16; ++d) {
                float qf[4], kf[4];
#pragma unroll
                for (int i = 0; i < 4; ++i) qf[i] = sQc[(ty4 + i) * 17 + d];
#pragma unroll
                for (int j = 0; j < 4; ++j) kf[j] = sKc[(tx4 + j) * 17 + d];
#pragma unroll
                for (int i = 0; i < 4; ++i)
#pragma unroll
                    for (int j = 0; j < 4; ++j)
                        sacc[i][j] = fmaf(qf[i], kf[j], sacc[i][j]);
            }
            __syncthreads();
        }

        // ---- online softmax update (row stats via 16-lane shfl groups) ----
#pragma unroll
        for (int i = 0; i < 4; ++i) {
#pragma unroll
            for (int j = 0; j < 4; ++j) sacc[i][j] *= scale;
            float rmax = fmaxf(fmaxf(sacc[i][0], sacc[i][1]),
                               fmaxf(sacc[i][2], sacc[i][3]));
#pragma unroll
            for (int off = 8; off > 0; off >>= 1)
                rmax = fmaxf(rmax, __shfl_xor_sync(0xffffffffu, rmax, off));
            float nm = fmaxf(m[i], rmax);
            float f = __expf(m[i] - nm);
            m[i] = nm;
            float rs = 0.f;
#pragma unroll
            for (int j = 0; j < 4; ++j) {
                float p = __expf(sacc[i][j] - nm);
                sS[(ty4 + i) * 64 + tx4 + j] = p;
                rs += p;
            }
#pragma unroll
            for (int off = 8; off > 0; off >>= 1)
                rs += __shfl_xor_sync(0xffffffffu, rs, off);
            l[i] = l[i] * f + rs;
#pragma unroll
            for (int u = 0; u < 8; ++u) o[i][u] *= f;
        }

        // ---- load V block 64x128 (perfectly coalesced) ----
#pragma unroll
        for (int it = 0; it < 8; ++it) {
            int id = tid + it * 256;
            int r = id >> 5;             // 0..63
            int c = (id & 31) << 2;      // 0..124
            *(float4*)&sBuf[r * 128 + c] = *(const float4*)(V +
                (((size_t)(b * S_ + kb * 64 + r) * NKV_ + kvh) << 7) + c);
        }
        __syncthreads();   // covers sS writes + V loads

        // ---- O += P @ V ----
        const float4* sV4 = (const float4*)sBuf;
#pragma unroll 2
        for (int j = 0; j < 64; ++j) {
            float p[4];
#pragma unroll
            for (int i = 0; i < 4; ++i) p[i] = sS[(ty4 + i) * 64 + j];
            float4 va = sV4[j * 32 + tx * 2 + 0];
            float4 vb = sV4[j * 32 + tx * 2 + 1];
            float vv[8] = {va.x, va.y, va.z, va.w, vb.x, vb.y, vb.z, vb.w};
#pragma unroll
            for (int i = 0; i < 4; ++i)
#pragma unroll
                for (int u = 0; u < 8; ++u)
                    o[i][u] = fmaf(p[i], vv[u], o[i][u]);
        }
        __syncthreads();   // sS / sBuf reused next iteration
    }

    // ---- epilogue: normalize and store to att [B,S, H*HD] ----
#pragma unroll
    for (int i = 0; i < 4; ++i) {
        float inv = 1.0f / l[i];
        float* op = Oout + (size_t)(b * S_ + q0 + ty4 + i) * (NH_ * HD_) +
                    h * HD_ + tx * 8;
        *(float4*)(op + 0) = make_float4(o[i][0] * inv, o[i][1] * inv,
                                         o[i][2] * inv, o[i][3] * inv);
        *(float4*)(op + 4) = make_float4(o[i][4] * inv, o[i][5] * inv,
                                         o[i][6] * inv, o[i][7] * inv);
    }
}

// ============================================================================
// launch
// ============================================================================
extern "C" void kernel_launch(void* const* d_in, const int* in_sizes, int n_in,
                              void* d_out, int out_size)
{
    const float* x  = (const float*)d_in[0];
    const float* wq = (const float*)d_in[1];
    const float* wk = (const float*)d_in[2];
    const float* wv = (const float*)d_in[3];
    const float* wo = (const float*)d_in[4];
    const float* fc = (const float*)d_in[5];
    const float* fs = (const float*)d_in[6];
    // d_in[7] = start_pos (fixed 0 in this problem)
    float* out = (float*)d_out;

    float *qp, *kp, *vp, *ap;
    cudaGetSymbolAddress((void**)&qp, g_q);
    cudaGetSymbolAddress((void**)&kp, g_k);
    cudaGetSymbolAddress((void**)&vp, g_v);
    cudaGetSymbolAddress((void**)&ap, g_att);

    const int M = B_ * S_;               // 4096

    // Projections
    sgemm128<<<dim3(DIM_ / 128, M / 128), 256>>>(x, wq, qp, M, NH_ * HD_, DIM_);
    sgemm128<<<dim3((NKV_ * HD_) / 128, M / 128), 256>>>(x, wk, kp, M, NKV_ * HD_, DIM_);
    sgemm128<<<dim3((NKV_ * HD_) / 128, M / 128), 256>>>(x, wv, vp, M, NKV_ * HD_, DIM_);

    // RoPE on Q and K
    rope_kernel<<<(B_ * S_ * NH_ * 64 + 255) / 256, 256>>>(qp, fc, fs, NH_);
    rope_kernel<<<(B_ * S_ * NKV_ * 64 + 255) / 256, 256>>>(kp, fc, fs, NKV_);

    // Attention
    attn_kernel<<<dim3(S_ / 64, NH_, B_), 256>>>(qp, kp, vp, ap);

    // Output projection
    sgemm128<<<dim3(DIM_ / 128, M / 128), 256>>>(ap, wo, out, M, DIM_, DIM_);
}

// round 5
// speedup vs baseline: 1.5325x; 1.5325x over previous
#include <cuda_runtime.h>
#include <cuda_bf16.h>
#include <cstdint>
#include <cstddef>

#define B_   2
#define S_   2048
#define DIM_ 4096
#define NH_  32
#define NKV_ 8
#define HD_  128

// ---------------- scratch (no allocations allowed) ----------------
__device__ float g_q[(size_t)B_ * S_ * NH_ * HD_];     // 64MB
__device__ float g_k[(size_t)B_ * S_ * NKV_ * HD_];    // 16MB
__device__ float g_v[(size_t)B_ * S_ * NKV_ * HD_];    // 16MB

// bf16 hi/lo split operands
__device__ __nv_bfloat16 g_xh[(size_t)B_ * S_ * DIM_];
__device__ __nv_bfloat16 g_xl[(size_t)B_ * S_ * DIM_];
__device__ __nv_bfloat16 g_wqh[(size_t)DIM_ * DIM_];      // transposed [N,K]
__device__ __nv_bfloat16 g_wql[(size_t)DIM_ * DIM_];
__device__ __nv_bfloat16 g_wkh[(size_t)DIM_ * NKV_ * HD_];
__device__ __nv_bfloat16 g_wkl[(size_t)DIM_ * NKV_ * HD_];
__device__ __nv_bfloat16 g_wvh[(size_t)DIM_ * NKV_ * HD_];
__device__ __nv_bfloat16 g_wvl[(size_t)DIM_ * NKV_ * HD_];
__device__ __nv_bfloat16 g_woh[(size_t)DIM_ * DIM_];      // transposed [N,K]
__device__ __nv_bfloat16 g_wol[(size_t)DIM_ * DIM_];
__device__ __nv_bfloat16 g_ah[(size_t)B_ * S_ * DIM_];    // attention out hi
__device__ __nv_bfloat16 g_al[(size_t)B_ * S_ * DIM_];    // attention out lo

// ============================ PTX helpers (sm_80-portable) ============================
__device__ __forceinline__ uint32_t smem_u32(const void* p) {
    uint32_t a;
    asm("{ .reg .u64 t; cvta.to.shared.u64 t, %1; cvt.u32.u64 %0, t; }"
        : "=r"(a) : "l"(p));
    return a;
}

__device__ __forceinline__ void cp16(uint32_t dst, const void* src) {
    asm volatile("cp.async.cg.shared.global [%0], [%1], 16;" :: "r"(dst), "l"(src));
}

#define CP_COMMIT() asm volatile("cp.async.commit_group;" ::: "memory")
#define CP_WAIT1()  asm volatile("cp.async.wait_group 1;"  ::: "memory")
#define CP_WAIT0()  asm volatile("cp.async.wait_group 0;"  ::: "memory")

#define MMA_BF16(c, A, Bf)                                                        \
    asm volatile(                                                                 \
        "mma.sync.aligned.m16n8k16.row.col.f32.bf16.bf16.f32 "                    \
        "{%0,%1,%2,%3},{%4,%5,%6,%7},{%8,%9},{%0,%1,%2,%3};"                      \
        : "+f"((c)[0]), "+f"((c)[1]), "+f"((c)[2]), "+f"((c)[3])                  \
        : "r"((A)[0]), "r"((A)[1]), "r"((A)[2]), "r"((A)[3]),                     \
          "r"((Bf)[0]), "r"((Bf)[1]))

// ============================================================================
// mma.sync GEMM: C[M,N] fp32 = (Ah+Al)[M,K] @ (Bh+Bl)[N,K]^T  (bf16x2 split)
// CTA 128x128, BK=32, 256 threads (8 warps 2x4, warp tile 64x32).
// smem: 2 stages x 4 tiles x 128 rows x 40 bf16 (80B stride) = 80KB dynamic.
// ============================================================================
#define TILE_B   10240          // one 128x40 bf16 tile
#define STAGE_B  (4 * TILE_B)   // Ah, Al, Bh, Bl

__global__ __launch_bounds__(256) void gemm_mma(
    const __nv_bfloat16* __restrict__ Ah, const __nv_bfloat16* __restrict__ Al,
    const __nv_bfloat16* __restrict__ Bh, const __nv_bfloat16* __restrict__ Bl,
    float* __restrict__ C, int M, int N, int K)
{
    extern __shared__ __align__(16) char sm[];
    const uint32_t sm0 = smem_u32(sm);

    const int tid  = threadIdx.x;
    const int lane = tid & 31;
    const int wid  = tid >> 5;
    const int wm   = wid >> 2;       // 0..1
    const int wn   = wid & 3;        // 0..3
    const int q    = lane & 3;
    const int rb   = lane >> 2;      // 0..7
    const int row0 = blockIdx.y * 128;
    const int col0 = blockIdx.x * 128;

    const __nv_bfloat16* src_[4] = {
        Ah + (size_t)row0 * K, Al + (size_t)row0 * K,
        Bh + (size_t)col0 * K, Bl + (size_t)col0 * K };

    // per-thread fixed load slots: chunk ids tid and tid+256 (512 = 128 rows x 4)
    const int r1 = tid >> 2,          kc1 = tid & 3;
    const int r2 = (tid + 256) >> 2,  kc2 = (tid + 256) & 3;

    auto load_stage = [&](int it, int s) {
        const uint32_t base = sm0 + s * STAGE_B;
        const int kel = it * 32;   // bf16 element offset in K
#pragma unroll
        for (int t = 0; t < 4; ++t) {
            const __nv_bfloat16* g = src_[t] + kel;
            cp16(base + t * TILE_B + r1 * 80 + kc1 * 16,
                 g + (size_t)r1 * K + kc1 * 8);
            cp16(base + t * TILE_B + r2 * 80 + kc2 * 16,
                 g + (size_t)r2 * K + kc2 * 8);
        }
        CP_COMMIT();
    };

    float acc[4][4][4];
#pragma unroll
    for (int i = 0; i < 4; ++i)
#pragma unroll
        for (int j = 0; j < 4; ++j)
#pragma unroll
            for (int u = 0; u < 4; ++u) acc[i][j][u] = 0.f;

    const int KIT = K >> 5;
    load_stage(0, 0);

    for (int it = 0; it < KIT; ++it) {
        if (it + 1 < KIT) { load_stage(it + 1, (it + 1) & 1); CP_WAIT1(); }
        else              { CP_WAIT0(); }
        __syncthreads();

        const char* base = sm + (it & 1) * STAGE_B;
        const char* sAh = base;
        const char* sAl = base + TILE_B;
        const char* sBh = base + 2 * TILE_B;
        const char* sBl = base + 3 * TILE_B;

#pragma unroll
        for (int kk = 0; kk < 2; ++kk) {
            uint32_t ah[4][4], al[4][4], bh[4][2], bl[4][2];
#pragma unroll
            for (int mf = 0; mf < 4; ++mf) {
                int ao = (wm * 64 + mf * 16 + rb) * 80 + kk * 32 + q * 4;
                ah[mf][0] = *(const uint32_t*)(sAh + ao);
                ah[mf][1] = *(const uint32_t*)(sAh + ao + 640);
                ah[mf][2] = *(const uint32_t*)(sAh + ao + 16);
                ah[mf][3] = *(const uint32_t*)(sAh + ao + 656);
                al[mf][0] = *(const uint32_t*)(sAl + ao);
                al[mf][1] = *(const uint32_t*)(sAl + ao + 640);
                al[mf][2] = *(const uint32_t*)(sAl + ao + 16);
                al[mf][3] = *(const uint32_t*)(sAl + ao + 656);
            }
#pragma unroll
            for (int nf = 0; nf < 4; ++nf) {
                int bo = (wn * 32 + nf * 8 + rb) * 80 + kk * 32 + q * 4;
                bh[nf][0] = *(const uint32_t*)(sBh + bo);
                bh[nf][1] = *(const uint32_t*)(sBh + bo + 16);
                bl[nf][0] = *(const uint32_t*)(sBl + bo);
                bl[nf][1] = *(const uint32_t*)(sBl + bo + 16);
            }
#pragma unroll
            for (int mf = 0; mf < 4; ++mf)
#pragma unroll
                for (int nf = 0; nf < 4; ++nf) {
                    MMA_BF16(acc[mf][nf], ah[mf], bh[nf]);
                    MMA_BF16(acc[mf][nf], ah[mf], bl[nf]);
                    MMA_BF16(acc[mf][nf], al[mf], bh[nf]);
                }
        }
        __syncthreads();
    }

    // ---- epilogue ----
#pragma unroll
    for (int mf = 0; mf < 4; ++mf) {
        int row = row0 + wm * 64 + mf * 16 + rb;
#pragma unroll
        for (int nf = 0; nf < 4; ++nf) {
            int col = col0 + wn * 32 + nf * 8 + q * 2;
            *(float2*)(C + (size_t)row * N + col) =
                make_float2(acc[mf][nf][0], acc[mf][nf][1]);
            *(float2*)(C + (size_t)(row + 8) * N + col) =
                make_float2(acc[mf][nf][2], acc[mf][nf][3]);
        }
    }
}

// ============================================================================
// fp32 -> bf16 hi/lo split (same layout)
// ============================================================================
__global__ __launch_bounds__(256) void split_kernel(const float* __restrict__ in,
                                                    __nv_bfloat16* __restrict__ h,
                                                    __nv_bfloat16* __restrict__ l,
                                                    int n4)
{
    int i = blockIdx.x * blockDim.x + threadIdx.x;
    if (i >= n4) return;
    float4 v = ((const float4*)in)[i];
    __nv_bfloat16 h0 = __float2bfloat16_rn(v.x);
    __nv_bfloat16 h1 = __float2bfloat16_rn(v.y);
    __nv_bfloat16 h2 = __float2bfloat16_rn(v.z);
    __nv_bfloat16 h3 = __float2bfloat16_rn(v.w);
    __nv_bfloat16 l0 = __float2bfloat16_rn(v.x - __bfloat162float(h0));
    __nv_bfloat16 l1 = __float2bfloat16_rn(v.y - __bfloat162float(h1));
    __nv_bfloat16 l2 = __float2bfloat16_rn(v.z - __bfloat162float(h2));
    __nv_bfloat16 l3 = __float2bfloat16_rn(v.w - __bfloat162float(h3));
    ((__nv_bfloat162*)h)[2 * i + 0] = __nv_bfloat162(h0, h1);
    ((__nv_bfloat162*)h)[2 * i + 1] = __nv_bfloat162(h2, h3);
    ((__nv_bfloat162*)l)[2 * i + 0] = __nv_bfloat162(l0, l1);
    ((__nv_bfloat162*)l)[2 * i + 1] = __nv_bfloat162(l2, l3);
}

// ============================================================================
// w[K,N] fp32 -> wT hi/lo bf16 [N,K]
// ============================================================================
__global__ __launch_bounds__(256) void transpose_split(const float* __restrict__ w,
                                                       __nv_bfloat16* __restrict__ th,
                                                       __nv_bfloat16* __restrict__ tl,
                                                       int K, int N)
{
    __shared__ float s[32][33];
    int n0 = blockIdx.x * 32, k0 = blockIdx.y * 32;
    int tx = threadIdx.x, ty = threadIdx.y;
#pragma unroll
    for (int i = ty; i < 32; i += 8)
        s[i][tx] = w[(size_t)(k0 + i) * N + n0 + tx];
    __syncthreads();
#pragma unroll
    for (int i = ty; i < 32; i += 8) {
        float v = s[tx][i];
        __nv_bfloat16 hi = __float2bfloat16_rn(v);
        size_t o = (size_t)(n0 + i) * K + k0 + tx;
        th[o] = hi;
        tl[o] = __float2bfloat16_rn(v - __bfloat162float(hi));
    }
}

// ============================================================================
// RoPE (interleaved pairs), fp32 in place
// ============================================================================
__global__ __launch_bounds__(256) void rope_kernel(float* __restrict__ t,
                                                   const float* __restrict__ cs,
                                                   const float* __restrict__ sn,
                                                   int nh)
{
    int idx = blockIdx.x * blockDim.x + threadIdx.x;
    int total = B_ * S_ * nh * 64;
    if (idx >= total) return;
    int p = idx & 63;
    int s = (idx / (64 * nh)) & (S_ - 1);
    float c  = cs[(s << 6) + p];
    float si = sn[(s << 6) + p];
    float* v = t + ((size_t)idx << 1);
    float xr = v[0], xi = v[1];
    v[0] = fmaf(xr, c, -xi * si);
    v[1] = fmaf(xr, si,  xi * c);
}

// ============================================================================
// Attention (full, non-causal), flash-style online softmax (fp32 CUDA cores).
// Epilogue writes bf16 hi/lo split directly (feeds final mma GEMM).
// ============================================================================
__global__ __launch_bounds__(256) void attn_kernel(const float* __restrict__ Q,
                                                   const float* __restrict__ K,
                                                   const float* __restrict__ V,
                                                   __nv_bfloat16* __restrict__ Oh,
                                                   __nv_bfloat16* __restrict__ Ol)
{
    __shared__ __align__(16) float sS[64 * 64];
    __shared__ __align__(16) float sBuf[64 * 128];

    float* sQc = sBuf;
    float* sKc = sBuf + 64 * 17;

    const int tid = threadIdx.x;
    const int tx = tid & 15, ty = tid >> 4;
    const int ty4 = ty << 2, tx4 = tx << 2;
    const int q0 = blockIdx.x * 64;
    const int h  = blockIdx.y;
    const int b  = blockIdx.z;
    const int kvh = h >> 2;
    const float scale = 0.08838834764831845f;

    float o[4][8];
    float m[4], l[4];
#pragma unroll
    for (int i = 0; i < 4; ++i) {
        m[i] = -1e30f; l[i] = 0.f;
#pragma unroll
        for (int u = 0; u < 8; ++u) o[i][u] = 0.f;
    }

    const int lr = tid >> 2;
    const int lc = (tid & 3) << 2;

    for (int kb = 0; kb < S_ / 64; ++kb) {
        float sacc[4][4];
#pragma unroll
        for (int i = 0; i < 4; ++i)
#pragma unroll
            for (int j = 0; j < 4; ++j) sacc[i][j] = 0.f;

        for (int dc = 0; dc < 8; ++dc) {
            {
                const float4 qv = *(const float4*)(Q +
                    (((size_t)(b * S_ + q0 + lr) * NH_ + h) << 7) + dc * 16 + lc);
                sQc[lr * 17 + lc + 0] = qv.x;
                sQc[lr * 17 + lc + 1] = qv.y;
                sQc[lr * 17 + lc + 2] = qv.z;
                sQc[lr * 17 + lc + 3] = qv.w;
                const float4 kv = *(const float4*)(K +
                    (((size_t)(b * S_ + kb * 64 + lr) * NKV_ + kvh) << 7) + dc * 16 + lc);
                sKc[lr * 17 + lc + 0] = kv.x;
                sKc[lr * 17 + lc + 1] = kv.y;
                sKc[lr * 17 + lc + 2] = kv.z;
                sKc[lr * 17 + lc + 3] = kv.w;
            }
            __syncthreads();
#pragma unroll
            for (int d = 0; d < 16; ++d) {
                float qf[4], kf[4];
#pragma unroll
                for (int i = 0; i < 4; ++i) qf[i] = sQc[(ty4 + i) * 17 + d];
#pragma unroll
                for (int j = 0; j < 4; ++j) kf[j] = sKc[(tx4 + j) * 17 + d];
#pragma unroll
                for (int i = 0; i < 4; ++i)
#pragma unroll
                    for (int j = 0; j < 4; ++j)
                        sacc[i][j] = fmaf(qf[i], kf[j], sacc[i][j]);
            }
            __syncthreads();
        }

#pragma unroll
        for (int i = 0; i < 4; ++i) {
#pragma unroll
            for (int j = 0; j < 4; ++j) sacc[i][j] *= scale;
            float rmax = fmaxf(fmaxf(sacc[i][0], sacc[i][1]),
                               fmaxf(sacc[i][2], sacc[i][3]));
#pragma unroll
            for (int off = 8; off > 0; off >>= 1)
                rmax = fmaxf(rmax, __shfl_xor_sync(0xffffffffu, rmax, off));
            float nm = fmaxf(m[i], rmax);
            float f = __expf(m[i] - nm);
            m[i] = nm;
            float rs = 0.f;
#pragma unroll
            for (int j = 0; j < 4; ++j) {
                float p = __expf(sacc[i][j] - nm);
                sS[(ty4 + i) * 64 + tx4 + j] = p;
                rs += p;
            }
#pragma unroll
            for (int off = 8; off > 0; off >>= 1)
                rs += __shfl_xor_sync(0xffffffffu, rs, off);
            l[i] = l[i] * f + rs;
#pragma unroll
            for (int u = 0; u < 8; ++u) o[i][u] *= f;
        }

#pragma unroll
        for (int it = 0; it < 8; ++it) {
            int id = tid + it * 256;
            int r = id >> 5;
            int c = (id & 31) << 2;
            *(float4*)&sBuf[r * 128 + c] = *(const float4*)(V +
                (((size_t)(b * S_ + kb * 64 + r) * NKV_ + kvh) << 7) + c);
        }
        __syncthreads();

        const float4* sV4 = (const float4*)sBuf;
#pragma unroll 2
        for (int j = 0; j < 64; ++j) {
            float p[4];
#pragma unroll
            for (int i = 0; i < 4; ++i) p[i] = sS[(ty4 + i) * 64 + j];
            float4 va = sV4[j * 32 + tx * 2 + 0];
            float4 vb = sV4[j * 32 + tx * 2 + 1];
            float vv[8] = {va.x, va.y, va.z, va.w, vb.x, vb.y, vb.z, vb.w};
#pragma unroll
            for (int i = 0; i < 4; ++i)
#pragma unroll
                for (int u = 0; u < 8; ++u)
                    o[i][u] = fmaf(p[i], vv[u], o[i][u]);
        }
        __syncthreads();
    }

    // ---- epilogue: normalize, split to bf16 hi/lo ----
#pragma unroll
    for (int i = 0; i < 4; ++i) {
        float inv = 1.0f / l[i];
        size_t off = (size_t)(b * S_ + q0 + ty4 + i) * (NH_ * HD_) +
                     h * HD_ + tx * 8;
        __nv_bfloat162* ph = (__nv_bfloat162*)(Oh + off);
        __nv_bfloat162* pl = (__nv_bfloat162*)(Ol + off);
#pragma unroll
        for (int u = 0; u < 4; ++u) {
            float v0 = o[i][2 * u] * inv, v1 = o[i][2 * u + 1] * inv;
            __nv_bfloat16 h0 = __float2bfloat16_rn(v0);
            __nv_bfloat16 h1 = __float2bfloat16_rn(v1);
            ph[u] = __nv_bfloat162(h0, h1);
            pl[u] = __nv_bfloat162(
                __float2bfloat16_rn(v0 - __bfloat162float(h0)),
                __float2bfloat16_rn(v1 - __bfloat162float(h1)));
        }
    }
}

// ============================================================================
// launch
// ============================================================================
extern "C" void kernel_launch(void* const* d_in, const int* in_sizes, int n_in,
                              void* d_out, int out_size)
{
    const float* x  = (const float*)d_in[0];
    const float* wq = (const float*)d_in[1];
    const float* wk = (const float*)d_in[2];
    const float* wv = (const float*)d_in[3];
    const float* wo = (const float*)d_in[4];
    const float* fc = (const float*)d_in[5];
    const float* fs = (const float*)d_in[6];
    float* out = (float*)d_out;

    float *qp, *kp, *vp;
    cudaGetSymbolAddress((void**)&qp, g_q);
    cudaGetSymbolAddress((void**)&kp, g_k);
    cudaGetSymbolAddress((void**)&vp, g_v);
    __nv_bfloat16 *xh, *xl, *wqh, *wql, *wkh, *wkl, *wvh, *wvl, *woh, *wol, *ah, *al;
    cudaGetSymbolAddress((void**)&xh, g_xh);   cudaGetSymbolAddress((void**)&xl, g_xl);
    cudaGetSymbolAddress((void**)&wqh, g_wqh); cudaGetSymbolAddress((void**)&wql, g_wql);
    cudaGetSymbolAddress((void**)&wkh, g_wkh); cudaGetSymbolAddress((void**)&wkl, g_wkl);
    cudaGetSymbolAddress((void**)&wvh, g_wvh); cudaGetSymbolAddress((void**)&wvl, g_wvl);
    cudaGetSymbolAddress((void**)&woh, g_woh); cudaGetSymbolAddress((void**)&wol, g_wol);
    cudaGetSymbolAddress((void**)&ah, g_ah);   cudaGetSymbolAddress((void**)&al, g_al);

    const int SMEM_BYTES = 2 * STAGE_B;   // 81920
    cudaFuncSetAttribute(gemm_mma, cudaFuncAttributeMaxDynamicSharedMemorySize,
                         SMEM_BYTES);

    const int M = B_ * S_;               // 4096

    // operand prep
    split_kernel<<<((size_t)M * DIM_ / 4 + 255) / 256, 256>>>(x, xh, xl, M * DIM_ / 4);
    transpose_split<<<dim3(DIM_ / 32, DIM_ / 32), dim3(32, 8)>>>(wq, wqh, wql, DIM_, DIM_);
    transpose_split<<<dim3(NKV_ * HD_ / 32, DIM_ / 32), dim3(32, 8)>>>(wk, wkh, wkl, DIM_, NKV_ * HD_);
    transpose_split<<<dim3(NKV_ * HD_ / 32, DIM_ / 32), dim3(32, 8)>>>(wv, wvh, wvl, DIM_, NKV_ * HD_);
    transpose_split<<<dim3(DIM_ / 32, DIM_ / 32), dim3(32, 8)>>>(wo, woh, wol, DIM_, DIM_);

    // projections (tensor cores via mma.sync)
    gemm_mma<<<dim3(DIM_ / 128, M / 128), 256, SMEM_BYTES>>>(
        xh, xl, wqh, wql, qp, M, DIM_, DIM_);
    gemm_mma<<<dim3(NKV_ * HD_ / 128, M / 128), 256, SMEM_BYTES>>>(
        xh, xl, wkh, wkl, kp, M, NKV_ * HD_, DIM_);
    gemm_mma<<<dim3(NKV_ * HD_ / 128, M / 128), 256, SMEM_BYTES>>>(
        xh, xl, wvh, wvl, vp, M, NKV_ * HD_, DIM_);

    // RoPE
    rope_kernel<<<(B_ * S_ * NH_ * 64 + 255) / 256, 256>>>(qp, fc, fs, NH_);
    rope_kernel<<<(B_ * S_ * NKV_ * 64 + 255) / 256, 256>>>(kp, fc, fs, NKV_);

    // attention (writes bf16 hi/lo split directly)
    attn_kernel<<<dim3(S_ / 64, NH_, B_), 256>>>(qp, kp, vp, ah, al);

    // output projection
    gemm_mma<<<dim3(DIM_ / 128, M / 128), 256, SMEM_BYTES>>>(
        ah, al, woh, wol, out, M, DIM_, DIM_);
}

// round 6
// speedup vs baseline: 1.5348x; 1.0015x over previous
#include <cuda_runtime.h>
#include <cuda_bf16.h>
#include <cstdint>
#include <cstddef>

#define B_   2
#define S_   2048
#define DIM_ 4096
#define NH_  32
#define NKV_ 8
#define HD_  128

// ---------------- scratch (no allocations allowed) ----------------
__device__ float g_q[(size_t)B_ * S_ * NH_ * HD_];     // 64MB
__device__ float g_k[(size_t)B_ * S_ * NKV_ * HD_];    // 16MB
__device__ float g_v[(size_t)B_ * S_ * NKV_ * HD_];    // 16MB

// bf16 hi/lo split operands
__device__ __nv_bfloat16 g_xh[(size_t)B_ * S_ * DIM_];
__device__ __nv_bfloat16 g_xl[(size_t)B_ * S_ * DIM_];
__device__ __nv_bfloat16 g_wqh[(size_t)DIM_ * DIM_];      // transposed [N,K]
__device__ __nv_bfloat16 g_wql[(size_t)DIM_ * DIM_];
__device__ __nv_bfloat16 g_wkh[(size_t)DIM_ * NKV_ * HD_];
__device__ __nv_bfloat16 g_wkl[(size_t)DIM_ * NKV_ * HD_];
__device__ __nv_bfloat16 g_wvh[(size_t)DIM_ * NKV_ * HD_];
__device__ __nv_bfloat16 g_wvl[(size_t)DIM_ * NKV_ * HD_];
__device__ __nv_bfloat16 g_woh[(size_t)DIM_ * DIM_];      // transposed [N,K]
__device__ __nv_bfloat16 g_wol[(size_t)DIM_ * DIM_];
__device__ __nv_bfloat16 g_ah[(size_t)B_ * S_ * DIM_];    // attention out hi
__device__ __nv_bfloat16 g_al[(size_t)B_ * S_ * DIM_];    // attention out lo

// ============================ PTX helpers (sm_80-portable) ============================
__device__ __forceinline__ uint32_t smem_u32(const void* p) {
    uint32_t a;
    asm("{ .reg .u64 t; cvta.to.shared.u64 t, %1; cvt.u32.u64 %0, t; }"
        : "=r"(a) : "l"(p));
    return a;
}

__device__ __forceinline__ void cp16(uint32_t dst, const void* src) {
    asm volatile("cp.async.cg.shared.global [%0], [%1], 16;" :: "r"(dst), "l"(src));
}

#define CP_COMMIT() asm volatile("cp.async.commit_group;" ::: "memory")
#define CP_WAIT1()  asm volatile("cp.async.wait_group 1;"  ::: "memory")
#define CP_WAIT0()  asm volatile("cp.async.wait_group 0;"  ::: "memory")

#define MMA_BF16(c, A, Bf)                                                        \
    asm volatile(                                                                 \
        "mma.sync.aligned.m16n8k16.row.col.f32.bf16.bf16.f32 "                    \
        "{%0,%1,%2,%3},{%4,%5,%6,%7},{%8,%9},{%0,%1,%2,%3};"                      \
        : "+f"((c)[0]), "+f"((c)[1]), "+f"((c)[2]), "+f"((c)[3])                  \
        : "r"((A)[0]), "r"((A)[1]), "r"((A)[2]), "r"((A)[3]),                     \
          "r"((Bf)[0]), "r"((Bf)[1]))

// ============================================================================
// mma.sync GEMM: C[M,N] fp32 = (Ah+Al)[M,K] @ (Bh+Bl)[N,K]^T  (bf16x2 split)
// CTA 128x128, BK=32, 256 threads (8 warps 2x4, warp tile 64x32).
// smem: 2 stages x 4 tiles x 128 rows x 40 bf16 (80B stride) = 80KB dynamic.
// ============================================================================
#define TILE_B   10240          // one 128x40 bf16 tile
#define STAGE_B  (4 * TILE_B)   // Ah, Al, Bh, Bl

__global__ __launch_bounds__(256) void gemm_mma(
    const __nv_bfloat16* __restrict__ Ah, const __nv_bfloat16* __restrict__ Al,
    const __nv_bfloat16* __restrict__ Bh, const __nv_bfloat16* __restrict__ Bl,
    float* __restrict__ C, int M, int N, int K)
{
    extern __shared__ __align__(16) char sm[];
    const uint32_t sm0 = smem_u32(sm);

    const int tid  = threadIdx.x;
    const int lane = tid & 31;
    const int wid  = tid >> 5;
    const int wm   = wid >> 2;       // 0..1
    const int wn   = wid & 3;        // 0..3
    const int q    = lane & 3;
    const int rb   = lane >> 2;      // 0..7
    const int row0 = blockIdx.y * 128;
    const int col0 = blockIdx.x * 128;

    const __nv_bfloat16* src_[4] = {
        Ah + (size_t)row0 * K, Al + (size_t)row0 * K,
        Bh + (size_t)col0 * K, Bl + (size_t)col0 * K };

    // per-thread fixed load slots: chunk ids tid and tid+256 (512 = 128 rows x 4)
    const int r1 = tid >> 2,          kc1 = tid & 3;
    const int r2 = (tid + 256) >> 2,  kc2 = (tid + 256) & 3;

    auto load_stage = [&](int it, int s) {
        const uint32_t base = sm0 + s * STAGE_B;
        const int kel = it * 32;   // bf16 element offset in K
#pragma unroll
        for (int t = 0; t < 4; ++t) {
            const __nv_bfloat16* g = src_[t] + kel;
            cp16(base + t * TILE_B + r1 * 80 + kc1 * 16,
                 g + (size_t)r1 * K + kc1 * 8);
            cp16(base + t * TILE_B + r2 * 80 + kc2 * 16,
                 g + (size_t)r2 * K + kc2 * 8);
        }
        CP_COMMIT();
    };

    float acc[4][4][4];
#pragma unroll
    for (int i = 0; i < 4; ++i)
#pragma unroll
        for (int j = 0; j < 4; ++j)
#pragma unroll
            for (int u = 0; u < 4; ++u) acc[i][j][u] = 0.f;

    const int KIT = K >> 5;
    load_stage(0, 0);

    for (int it = 0; it < KIT; ++it) {
        if (it + 1 < KIT) { load_stage(it + 1, (it + 1) & 1); CP_WAIT1(); }
        else              { CP_WAIT0(); }
        __syncthreads();

        const char* base = sm + (it & 1) * STAGE_B;
        const char* sAh = base;
        const char* sAl = base + TILE_B;
        const char* sBh = base + 2 * TILE_B;
        const char* sBl = base + 3 * TILE_B;

#pragma unroll
        for (int kk = 0; kk < 2; ++kk) {
            uint32_t ah[4][4], al[4][4], bh[4][2], bl[4][2];
#pragma unroll
            for (int mf = 0; mf < 4; ++mf) {
                int ao = (wm * 64 + mf * 16 + rb) * 80 + kk * 32 + q * 4;
                ah[mf][0] = *(const uint32_t*)(sAh + ao);
                ah[mf][1] = *(const uint32_t*)(sAh + ao + 640);
                ah[mf][2] = *(const uint32_t*)(sAh + ao + 16);
                ah[mf][3] = *(const uint32_t*)(sAh + ao + 656);
                al[mf][0] = *(const uint32_t*)(sAl + ao);
                al[mf][1] = *(const uint32_t*)(sAl + ao + 640);
                al[mf][2] = *(const uint32_t*)(sAl + ao + 16);
                al[mf][3] = *(const uint32_t*)(sAl + ao + 656);
            }
#pragma unroll
            for (int nf = 0; nf < 4; ++nf) {
                int bo = (wn * 32 + nf * 8 + rb) * 80 + kk * 32 + q * 4;
                bh[nf][0] = *(const uint32_t*)(sBh + bo);
                bh[nf][1] = *(const uint32_t*)(sBh + bo + 16);
                bl[nf][0] = *(const uint32_t*)(sBl + bo);
                bl[nf][1] = *(const uint32_t*)(sBl + bo + 16);
            }
#pragma unroll
            for (int mf = 0; mf < 4; ++mf)
#pragma unroll
                for (int nf = 0; nf < 4; ++nf) {
                    MMA_BF16(acc[mf][nf], ah[mf], bh[nf]);
                    MMA_BF16(acc[mf][nf], ah[mf], bl[nf]);
                    MMA_BF16(acc[mf][nf], al[mf], bh[nf]);
                }
        }
        __syncthreads();
    }

    // ---- epilogue ----
#pragma unroll
    for (int mf = 0; mf < 4; ++mf) {
        int row = row0 + wm * 64 + mf * 16 + rb;
#pragma unroll
        for (int nf = 0; nf < 4; ++nf) {
            int col = col0 + wn * 32 + nf * 8 + q * 2;
            *(float2*)(C + (size_t)row * N + col) =
                make_float2(acc[mf][nf][0], acc[mf][nf][1]);
            *(float2*)(C + (size_t)(row + 8) * N + col) =
                make_float2(acc[mf][nf][2], acc[mf][nf][3]);
        }
    }
}

// ============================================================================
// fp32 -> bf16 hi/lo split (same layout)
// ============================================================================
__global__ __launch_bounds__(256) void split_kernel(const float* __restrict__ in,
                                                    __nv_bfloat16* __restrict__ h,
                                                    __nv_bfloat16* __restrict__ l,
                                                    int n4)
{
    int i = blockIdx.x * blockDim.x + threadIdx.x;
    if (i >= n4) return;
    float4 v = ((const float4*)in)[i];
    __nv_bfloat16 h0 = __float2bfloat16_rn(v.x);
    __nv_bfloat16 h1 = __float2bfloat16_rn(v.y);
    __nv_bfloat16 h2 = __float2bfloat16_rn(v.z);
    __nv_bfloat16 h3 = __float2bfloat16_rn(v.w);
    __nv_bfloat16 l0 = __float2bfloat16_rn(v.x - __bfloat162float(h0));
    __nv_bfloat16 l1 = __float2bfloat16_rn(v.y - __bfloat162float(h1));
    __nv_bfloat16 l2 = __float2bfloat16_rn(v.z - __bfloat162float(h2));
    __nv_bfloat16 l3 = __float2bfloat16_rn(v.w - __bfloat162float(h3));
    ((__nv_bfloat162*)h)[2 * i + 0] = __nv_bfloat162(h0, h1);
    ((__nv_bfloat162*)h)[2 * i + 1] = __nv_bfloat162(h2, h3);
    ((__nv_bfloat162*)l)[2 * i + 0] = __nv_bfloat162(l0, l1);
    ((__nv_bfloat162*)l)[2 * i + 1] = __nv_bfloat162(l2, l3);
}

// ============================================================================
// w[K,N] fp32 -> wT hi/lo bf16 [N,K]
// ============================================================================
__global__ __launch_bounds__(256) void transpose_split(const float* __restrict__ w,
                                                       __nv_bfloat16* __restrict__ th,
                                                       __nv_bfloat16* __restrict__ tl,
                                                       int K, int N)
{
    __shared__ float s[32][33];
    int n0 = blockIdx.x * 32, k0 = blockIdx.y * 32;
    int tx = threadIdx.x, ty = threadIdx.y;
#pragma unroll
    for (int i = ty; i < 32; i += 8)
        s[i][tx] = w[(size_t)(k0 + i) * N + n0 + tx];
    __syncthreads();
#pragma unroll
    for (int i = ty; i < 32; i += 8) {
        float v = s[tx][i];
        __nv_bfloat16 hi = __float2bfloat16_rn(v);
        size_t o = (size_t)(n0 + i) * K + k0 + tx;
        th[o] = hi;
        tl[o] = __float2bfloat16_rn(v - __bfloat162float(hi));
    }
}

// ============================================================================
// RoPE (interleaved pairs), fp32 in place
// ============================================================================
__global__ __launch_bounds__(256) void rope_kernel(float* __restrict__ t,
                                                   const float* __restrict__ cs,
                                                   const float* __restrict__ sn,
                                                   int nh)
{
    int idx = blockIdx.x * blockDim.x + threadIdx.x;
    int total = B_ * S_ * nh * 64;
    if (idx >= total) return;
    int p = idx & 63;
    int s = (idx / (64 * nh)) & (S_ - 1);
    float c  = cs[(s << 6) + p];
    float si = sn[(s << 6) + p];
    float* v = t + ((size_t)idx << 1);
    float xr = v[0], xi = v[1];
    v[0] = fmaf(xr, c, -xi * si);
    v[1] = fmaf(xr, si,  xi * c);
}

// ============================================================================
// Attention (full, non-causal), flash-style online softmax (fp32 CUDA cores).
// Epilogue writes bf16 hi/lo split directly (feeds final mma GEMM).
// ============================================================================
__global__ __launch_bounds__(256) void attn_kernel(const float* __restrict__ Q,
                                                   const float* __restrict__ K,
                                                   const float* __restrict__ V,
                                                   __nv_bfloat16* __restrict__ Oh,
                                                   __nv_bfloat16* __restrict__ Ol)
{
    __shared__ __align__(16) float sS[64 * 64];
    __shared__ __align__(16) float sBuf[64 * 128];

    float* sQc = sBuf;
    float* sKc = sBuf + 64 * 17;

    const int tid = threadIdx.x;
    const int tx = tid & 15, ty = tid >> 4;
    const int ty4 = ty << 2, tx4 = tx << 2;
    const int q0 = blockIdx.x * 64;
    const int h  = blockIdx.y;
    const int b  = blockIdx.z;
    const int kvh = h >> 2;
    const float scale = 0.08838834764831845f;

    float o[4][8];
    float m[4], l[4];
#pragma unroll
    for (int i = 0; i < 4; ++i) {
        m[i] = -1e30f; l[i] = 0.f;
#pragma unroll
        for (int u = 0; u < 8; ++u) o[i][u] = 0.f;
    }

    const int lr = tid >> 2;
    const int lc = (tid & 3) << 2;

    for (int kb = 0; kb < S_ / 64; ++kb) {
        float sacc[4][4];
#pragma unroll
        for (int i = 0; i < 4; ++i)
#pragma unroll
            for (int j = 0; j < 4; ++j) sacc[i][j] = 0.f;

        for (int dc = 0; dc < 8; ++dc) {
            {
                const float4 qv = *(const float4*)(Q +
                    (((size_t)(b * S_ + q0 + lr) * NH_ + h) << 7) + dc * 16 + lc);
                sQc[lr * 17 + lc + 0] = qv.x;
                sQc[lr * 17 + lc + 1] = qv.y;
                sQc[lr * 17 + lc + 2] = qv.z;
                sQc[lr * 17 + lc + 3] = qv.w;
                const float4 kv = *(const float4*)(K +
                    (((size_t)(b * S_ + kb * 64 + lr) * NKV_ + kvh) << 7) + dc * 16 + lc);
                sKc[lr * 17 + lc + 0] = kv.x;
                sKc[lr * 17 + lc + 1] = kv.y;
                sKc[lr * 17 + lc + 2] = kv.z;
                sKc[lr * 17 + lc + 3] = kv.w;
            }
            __syncthreads();
#pragma unroll
            for (int d = 0; d < 16; ++d) {
                float qf[4], kf[4];
#pragma unroll
                for (int i = 0; i < 4; ++i) qf[i] = sQc[(ty4 + i) * 17 + d];
#pragma unroll
                for (int j = 0; j < 4; ++j) kf[j] = sKc[(tx4 + j) * 17 + d];
#pragma unroll
                for (int i = 0; i < 4; ++i)
#pragma unroll
                    for (int j = 0; j < 4; ++j)
                        sacc[i][j] = fmaf(qf[i], kf[j], sacc[i][j]);
            }
            __syncthreads();
        }

#pragma unroll
        for (int i = 0; i < 4; ++i) {
#pragma unroll
            for (int j = 0; j < 4; ++j) sacc[i][j] *= scale;
            float rmax = fmaxf(fmaxf(sacc[i][0], sacc[i][1]),
                               fmaxf(sacc[i][2], sacc[i][3]));
#pragma unroll
            for (int off = 8; off > 0; off >>= 1)
                rmax = fmaxf(rmax, __shfl_xor_sync(0xffffffffu, rmax, off));
            float nm = fmaxf(m[i], rmax);
            float f = __expf(m[i] - nm);
            m[i] = nm;
            float rs = 0.f;
#pragma unroll
            for (int j = 0; j < 4; ++j) {
                float p = __expf(sacc[i][j] - nm);
                sS[(ty4 + i) * 64 + tx4 + j] = p;
                rs += p;
            }
#pragma unroll
            for (int off = 8; off > 0; off >>= 1)
                rs += __shfl_xor_sync(0xffffffffu, rs, off);
            l[i] = l[i] * f + rs;
#pragma unroll
            for (int u = 0; u < 8; ++u) o[i][u] *= f;
        }

#pragma unroll
        for (int it = 0; it < 8; ++it) {
            int id = tid + it * 256;
            int r = id >> 5;
            int c = (id & 31) << 2;
            *(float4*)&sBuf[r * 128 + c] = *(const float4*)(V +
                (((size_t)(b * S_ + kb * 64 + r) * NKV_ + kvh) << 7) + c);
        }
        __syncthreads();

        const float4* sV4 = (const float4*)sBuf;
#pragma unroll 2
        for (int j = 0; j < 64; ++j) {
            float p[4];
#pragma unroll
            for (int i = 0; i < 4; ++i) p[i] = sS[(ty4 + i) * 64 + j];
            float4 va = sV4[j * 32 + tx * 2 + 0];
            float4 vb = sV4[j * 32 + tx * 2 + 1];
            float vv[8] = {va.x, va.y, va.z, va.w, vb.x, vb.y, vb.z, vb.w};
#pragma unroll
            for (int i = 0; i < 4; ++i)
#pragma unroll
                for (int u = 0; u < 8; ++u)
                    o[i][u] = fmaf(p[i], vv[u], o[i][u]);
        }
        __syncthreads();
    }

    // ---- epilogue: normalize, split to bf16 hi/lo ----
#pragma unroll
    for (int i = 0; i < 4; ++i) {
        float inv = 1.0f / l[i];
        size_t off = (size_t)(b * S_ + q0 + ty4 + i) * (NH_ * HD_) +
                     h * HD_ + tx * 8;
        __nv_bfloat162* ph = (__nv_bfloat162*)(Oh + off);
        __nv_bfloat162* pl = (__nv_bfloat162*)(Ol + off);
#pragma unroll
        for (int u = 0; u < 4; ++u) {
            float v0 = o[i][2 * u] * inv, v1 = o[i][2 * u + 1] * inv;
            __nv_bfloat16 h0 = __float2bfloat16_rn(v0);
            __nv_bfloat16 h1 = __float2bfloat16_rn(v1);
            ph[u] = __nv_bfloat162(h0, h1);
            pl[u] = __nv_bfloat162(
                __float2bfloat16_rn(v0 - __bfloat162float(h0)),
                __float2bfloat16_rn(v1 - __bfloat162float(h1)));
        }
    }
}

// ============================================================================
// launch
// ============================================================================
extern "C" void kernel_launch(void* const* d_in, const int* in_sizes, int n_in,
                              void* d_out, int out_size)
{
    const float* x  = (const float*)d_in[0];
    const float* wq = (const float*)d_in[1];
    const float* wk = (const float*)d_in[2];
    const float* wv = (const float*)d_in[3];
    const float* wo = (const float*)d_in[4];
    const float* fc = (const float*)d_in[5];
    const float* fs = (const float*)d_in[6];
    float* out = (float*)d_out;

    float *qp, *kp, *vp;
    cudaGetSymbolAddress((void**)&qp, g_q);
    cudaGetSymbolAddress((void**)&kp, g_k);
    cudaGetSymbolAddress((void**)&vp, g_v);
    __nv_bfloat16 *xh, *xl, *wqh, *wql, *wkh, *wkl, *wvh, *wvl, *woh, *wol, *ah, *al;
    cudaGetSymbolAddress((void**)&xh, g_xh);   cudaGetSymbolAddress((void**)&xl, g_xl);
    cudaGetSymbolAddress((void**)&wqh, g_wqh); cudaGetSymbolAddress((void**)&wql, g_wql);
    cudaGetSymbolAddress((void**)&wkh, g_wkh); cudaGetSymbolAddress((void**)&wkl, g_wkl);
    cudaGetSymbolAddress((void**)&wvh, g_wvh); cudaGetSymbolAddress((void**)&wvl, g_wvl);
    cudaGetSymbolAddress((void**)&woh, g_woh); cudaGetSymbolAddress((void**)&wol, g_wol);
    cudaGetSymbolAddress((void**)&ah, g_ah);   cudaGetSymbolAddress((void**)&al, g_al);

    const int SMEM_BYTES = 2 * STAGE_B;   // 81920
    cudaFuncSetAttribute(gemm_mma, cudaFuncAttributeMaxDynamicSharedMemorySize,
                         SMEM_BYTES);

    const int M = B_ * S_;               // 4096

    // operand prep
    split_kernel<<<((size_t)M * DIM_ / 4 + 255) / 256, 256>>>(x, xh, xl, M * DIM_ / 4);
    transpose_split<<<dim3(DIM_ / 32, DIM_ / 32), dim3(32, 8)>>>(wq, wqh, wql, DIM_, DIM_);
    transpose_split<<<dim3(NKV_ * HD_ / 32, DIM_ / 32), dim3(32, 8)>>>(wk, wkh, wkl, DIM_, NKV_ * HD_);
    transpose_split<<<dim3(NKV_ * HD_ / 32, DIM_ / 32), dim3(32, 8)>>>(wv, wvh, wvl, DIM_, NKV_ * HD_);
    transpose_split<<<dim3(DIM_ / 32, DIM_ / 32), dim3(32, 8)>>>(wo, woh, wol, DIM_, DIM_);

    // projections (tensor cores via mma.sync)
    gemm_mma<<<dim3(DIM_ / 128, M / 128), 256, SMEM_BYTES>>>(
        xh, xl, wqh, wql, qp, M, DIM_, DIM_);
    gemm_mma<<<dim3(NKV_ * HD_ / 128, M / 128), 256, SMEM_BYTES>>>(
        xh, xl, wkh, wkl, kp, M, NKV_ * HD_, DIM_);
    gemm_mma<<<dim3(NKV_ * HD_ / 128, M / 128), 256, SMEM_BYTES>>>(
        xh, xl, wvh, wvl, vp, M, NKV_ * HD_, DIM_);

    // RoPE
    rope_kernel<<<(B_ * S_ * NH_ * 64 + 255) / 256, 256>>>(qp, fc, fs, NH_);
    rope_kernel<<<(B_ * S_ * NKV_ * 64 + 255) / 256, 256>>>(kp, fc, fs, NKV_);

    // attention (writes bf16 hi/lo split directly)
    attn_kernel<<<dim3(S_ / 64, NH_, B_), 256>>>(qp, kp, vp, ah, al);

    // output projection
    gemm_mma<<<dim3(DIM_ / 128, M / 128), 256, SMEM_BYTES>>>(
        ah, al, woh, wol, out, M, DIM_, DIM_);
}

// round 8
// speedup vs baseline: 2.7105x; 1.7660x over previous
#include <cuda_runtime.h>
#include <cuda_bf16.h>
#include <cstdint>
#include <cstddef>

#define B_   2
#define S_   2048
#define DIM_ 4096
#define NH_  32
#define NKV_ 8
#define HD_  128

// ---------------- scratch (no allocations allowed) ----------------
__device__ float g_q[(size_t)B_ * S_ * NH_ * HD_];     // fp32 Q (pre-rope)
__device__ float g_k[(size_t)B_ * S_ * NKV_ * HD_];
__device__ float g_v[(size_t)B_ * S_ * NKV_ * HD_];

// bf16 hi/lo split operands
__device__ __nv_bfloat16 g_xh[(size_t)B_ * S_ * DIM_];
__device__ __nv_bfloat16 g_xl[(size_t)B_ * S_ * DIM_];
__device__ __nv_bfloat16 g_wqh[(size_t)DIM_ * DIM_];
__device__ __nv_bfloat16 g_wql[(size_t)DIM_ * DIM_];
__device__ __nv_bfloat16 g_wkh[(size_t)DIM_ * NKV_ * HD_];
__device__ __nv_bfloat16 g_wkl[(size_t)DIM_ * NKV_ * HD_];
__device__ __nv_bfloat16 g_wvh[(size_t)DIM_ * NKV_ * HD_];
__device__ __nv_bfloat16 g_wvl[(size_t)DIM_ * NKV_ * HD_];
__device__ __nv_bfloat16 g_woh[(size_t)DIM_ * DIM_];
__device__ __nv_bfloat16 g_wol[(size_t)DIM_ * DIM_];
__device__ __nv_bfloat16 g_ah[(size_t)B_ * S_ * DIM_];
__device__ __nv_bfloat16 g_al[(size_t)B_ * S_ * DIM_];

// attention operands (post-rope, bf16 hi/lo)
__device__ __nv_bfloat16 g_qsh[(size_t)B_ * S_ * NH_ * HD_];
__device__ __nv_bfloat16 g_qsl[(size_t)B_ * S_ * NH_ * HD_];
__device__ __nv_bfloat16 g_ksh[(size_t)B_ * S_ * NKV_ * HD_];
__device__ __nv_bfloat16 g_ksl[(size_t)B_ * S_ * NKV_ * HD_];
__device__ __nv_bfloat16 g_vth[(size_t)B_ * NKV_ * HD_ * S_];   // V^T [b][kv][d][s]
__device__ __nv_bfloat16 g_vtl[(size_t)B_ * NKV_ * HD_ * S_];

// ============================ PTX helpers (sm_80-portable) ============================
__device__ __forceinline__ uint32_t smem_u32(const void* p) {
    uint32_t a;
    asm("{ .reg .u64 t; cvta.to.shared.u64 t, %1; cvt.u32.u64 %0, t; }"
        : "=r"(a) : "l"(p));
    return a;
}

__device__ __forceinline__ void cp16(uint32_t dst, const void* src) {
    asm volatile("cp.async.cg.shared.global [%0], [%1], 16;" :: "r"(dst), "l"(src));
}

__device__ __forceinline__ uint32_t lds32(uint32_t a) {
    uint32_t v;
    asm volatile("ld.shared.b32 %0, [%1];" : "=r"(v) : "r"(a));
    return v;
}

#define CP_COMMIT() asm volatile("cp.async.commit_group;" ::: "memory")
#define CP_WAIT1()  asm volatile("cp.async.wait_group 1;"  ::: "memory")
#define CP_WAIT0()  asm volatile("cp.async.wait_group 0;"  ::: "memory")

#define MMA_BF16(c, A, Bf)                                                        \
    asm volatile(                                                                 \
        "mma.sync.aligned.m16n8k16.row.col.f32.bf16.bf16.f32 "                    \
        "{%0,%1,%2,%3},{%4,%5,%6,%7},{%8,%9},{%0,%1,%2,%3};"                      \
        : "+f"((c)[0]), "+f"((c)[1]), "+f"((c)[2]), "+f"((c)[3])                  \
        : "r"((A)[0]), "r"((A)[1]), "r"((A)[2]), "r"((A)[3]),                     \
          "r"((Bf)[0]), "r"((Bf)[1]))

#define MMA_BF16S(c, A, b0, b1)                                                   \
    asm volatile(                                                                 \
        "mma.sync.aligned.m16n8k16.row.col.f32.bf16.bf16.f32 "                    \
        "{%0,%1,%2,%3},{%4,%5,%6,%7},{%8,%9},{%0,%1,%2,%3};"                      \
        : "+f"((c)[0]), "+f"((c)[1]), "+f"((c)[2]), "+f"((c)[3])                  \
        : "r"((A)[0]), "r"((A)[1]), "r"((A)[2]), "r"((A)[3]),                     \
          "r"(b0), "r"(b1))

// ============================================================================
// mma.sync GEMM: C fp32 = (Ah+Al) @ (Bh+Bl)^T
// ============================================================================
#define TILE_B   10240
#define STAGE_B  (4 * TILE_B)

__global__ __launch_bounds__(256) void gemm_mma(
    const __nv_bfloat16* __restrict__ Ah, const __nv_bfloat16* __restrict__ Al,
    const __nv_bfloat16* __restrict__ Bh, const __nv_bfloat16* __restrict__ Bl,
    float* __restrict__ C, int M, int N, int K)
{
    extern __shared__ __align__(16) char sm[];
    const uint32_t sm0 = smem_u32(sm);

    const int tid  = threadIdx.x;
    const int lane = tid & 31;
    const int wid  = tid >> 5;
    const int wm   = wid >> 2;
    const int wn   = wid & 3;
    const int q    = lane & 3;
    const int rb   = lane >> 2;
    const int row0 = blockIdx.y * 128;
    const int col0 = blockIdx.x * 128;

    const __nv_bfloat16* src_[4] = {
        Ah + (size_t)row0 * K, Al + (size_t)row0 * K,
        Bh + (size_t)col0 * K, Bl + (size_t)col0 * K };

    const int r1 = tid >> 2,          kc1 = tid & 3;
    const int r2 = (tid + 256) >> 2,  kc2 = (tid + 256) & 3;

    auto load_stage = [&](int it, int s) {
        const uint32_t base = sm0 + s * STAGE_B;
        const int kel = it * 32;
#pragma unroll
        for (int t = 0; t < 4; ++t) {
            const __nv_bfloat16* g = src_[t] + kel;
            cp16(base + t * TILE_B + r1 * 80 + kc1 * 16,
                 g + (size_t)r1 * K + kc1 * 8);
            cp16(base + t * TILE_B + r2 * 80 + kc2 * 16,
                 g + (size_t)r2 * K + kc2 * 8);
        }
        CP_COMMIT();
    };

    float acc[4][4][4];
#pragma unroll
    for (int i = 0; i < 4; ++i)
#pragma unroll
        for (int j = 0; j < 4; ++j)
#pragma unroll
            for (int u = 0; u < 4; ++u) acc[i][j][u] = 0.f;

    const int KIT = K >> 5;
    load_stage(0, 0);

    for (int it = 0; it < KIT; ++it) {
        if (it + 1 < KIT) { load_stage(it + 1, (it + 1) & 1); CP_WAIT1(); }
        else              { CP_WAIT0(); }
        __syncthreads();

        const char* base = sm + (it & 1) * STAGE_B;
        const char* sAh = base;
        const char* sAl = base + TILE_B;
        const char* sBh = base + 2 * TILE_B;
        const char* sBl = base + 3 * TILE_B;

#pragma unroll
        for (int kk = 0; kk < 2; ++kk) {
            uint32_t ah[4][4], al[4][4], bh[4][2], bl[4][2];
#pragma unroll
            for (int mf = 0; mf < 4; ++mf) {
                int ao = (wm * 64 + mf * 16 + rb) * 80 + kk * 32 + q * 4;
                ah[mf][0] = *(const uint32_t*)(sAh + ao);
                ah[mf][1] = *(const uint32_t*)(sAh + ao + 640);
                ah[mf][2] = *(const uint32_t*)(sAh + ao + 16);
                ah[mf][3] = *(const uint32_t*)(sAh + ao + 656);
                al[mf][0] = *(const uint32_t*)(sAl + ao);
                al[mf][1] = *(const uint32_t*)(sAl + ao + 640);
                al[mf][2] = *(const uint32_t*)(sAl + ao + 16);
                al[mf][3] = *(const uint32_t*)(sAl + ao + 656);
            }
#pragma unroll
            for (int nf = 0; nf < 4; ++nf) {
                int bo = (wn * 32 + nf * 8 + rb) * 80 + kk * 32 + q * 4;
                bh[nf][0] = *(const uint32_t*)(sBh + bo);
                bh[nf][1] = *(const uint32_t*)(sBh + bo + 16);
                bl[nf][0] = *(const uint32_t*)(sBl + bo);
                bl[nf][1] = *(const uint32_t*)(sBl + bo + 16);
            }
#pragma unroll
            for (int mf = 0; mf < 4; ++mf)
#pragma unroll
                for (int nf = 0; nf < 4; ++nf) {
                    MMA_BF16(acc[mf][nf], ah[mf], bh[nf]);
                    MMA_BF16(acc[mf][nf], ah[mf], bl[nf]);
                    MMA_BF16(acc[mf][nf], al[mf], bh[nf]);
                }
        }
        __syncthreads();
    }

#pragma unroll
    for (int mf = 0; mf < 4; ++mf) {
        int row = row0 + wm * 64 + mf * 16 + rb;
#pragma unroll
        for (int nf = 0; nf < 4; ++nf) {
            int col = col0 + wn * 32 + nf * 8 + q * 2;
            *(float2*)(C + (size_t)row * N + col) =
                make_float2(acc[mf][nf][0], acc[mf][nf][1]);
            *(float2*)(C + (size_t)(row + 8) * N + col) =
                make_float2(acc[mf][nf][2], acc[mf][nf][3]);
        }
    }
}

// ============================================================================
// fp32 -> bf16 hi/lo split
// ============================================================================
__global__ __launch_bounds__(256) void split_kernel(const float* __restrict__ in,
                                                    __nv_bfloat16* __restrict__ h,
                                                    __nv_bfloat16* __restrict__ l,
                                                    int n4)
{
    int i = blockIdx.x * blockDim.x + threadIdx.x;
    if (i >= n4) return;
    float4 v = ((const float4*)in)[i];
    __nv_bfloat16 h0 = __float2bfloat16_rn(v.x);
    __nv_bfloat16 h1 = __float2bfloat16_rn(v.y);
    __nv_bfloat16 h2 = __float2bfloat16_rn(v.z);
    __nv_bfloat16 h3 = __float2bfloat16_rn(v.w);
    __nv_bfloat16 l0 = __float2bfloat16_rn(v.x - __bfloat162float(h0));
    __nv_bfloat16 l1 = __float2bfloat16_rn(v.y - __bfloat162float(h1));
    __nv_bfloat16 l2 = __float2bfloat16_rn(v.z - __bfloat162float(h2));
    __nv_bfloat16 l3 = __float2bfloat16_rn(v.w - __bfloat162float(h3));
    ((__nv_bfloat162*)h)[2 * i + 0] = __nv_bfloat162(h0, h1);
    ((__nv_bfloat162*)h)[2 * i + 1] = __nv_bfloat162(h2, h3);
    ((__nv_bfloat162*)l)[2 * i + 0] = __nv_bfloat162(l0, l1);
    ((__nv_bfloat162*)l)[2 * i + 1] = __nv_bfloat162(l2, l3);
}

// ============================================================================
// w[K,N] fp32 -> wT hi/lo bf16 [N,K]
// ============================================================================
__global__ __launch_bounds__(256) void transpose_split(const float* __restrict__ w,
                                                       __nv_bfloat16* __restrict__ th,
                                                       __nv_bfloat16* __restrict__ tl,
                                                       int K, int N)
{
    __shared__ float s[32][33];
    int n0 = blockIdx.x * 32, k0 = blockIdx.y * 32;
    int tx = threadIdx.x, ty = threadIdx.y;
#pragma unroll
    for (int i = ty; i < 32; i += 8)
        s[i][tx] = w[(size_t)(k0 + i) * N + n0 + tx];
    __syncthreads();
#pragma unroll
    for (int i = ty; i < 32; i += 8) {
        float v = s[tx][i];
        __nv_bfloat16 hi = __float2bfloat16_rn(v);
        size_t o = (size_t)(n0 + i) * K + k0 + tx;
        th[o] = hi;
        tl[o] = __float2bfloat16_rn(v - __bfloat162float(hi));
    }
}

// ============================================================================
// RoPE + optional scale + bf16 hi/lo split.  t: fp32 [B,S,nh,128]
// ============================================================================
__global__ __launch_bounds__(256) void rope_split(const float* __restrict__ t,
                                                  const float* __restrict__ cs,
                                                  const float* __restrict__ sn,
                                                  __nv_bfloat16* __restrict__ oh,
                                                  __nv_bfloat16* __restrict__ ol,
                                                  int nh, float scale)
{
    int idx = blockIdx.x * blockDim.x + threadIdx.x;
    int total = B_ * S_ * nh * 64;
    if (idx >= total) return;
    int p = idx & 63;
    int s = (idx / (64 * nh)) & (S_ - 1);
    float c  = cs[(s << 6) + p];
    float si = sn[(s << 6) + p];
    const float* v = t + ((size_t)idx << 1);
    float xr = v[0], xi = v[1];
    float r0 = fmaf(xr, c, -xi * si) * scale;
    float r1 = fmaf(xr, si,  xi * c) * scale;
    __nv_bfloat16 h0 = __float2bfloat16_rn(r0);
    __nv_bfloat16 h1 = __float2bfloat16_rn(r1);
    ((__nv_bfloat162*)oh)[idx] = __nv_bfloat162(h0, h1);
    ((__nv_bfloat162*)ol)[idx] = __nv_bfloat162(
        __float2bfloat16_rn(r0 - __bfloat162float(h0)),
        __float2bfloat16_rn(r1 - __bfloat162float(h1)));
}

// ============================================================================
// V fp32 [b][s][kv][d] -> V^T bf16 hi/lo [b][kv][d][s]
// ============================================================================
__global__ __launch_bounds__(256) void transpose_v(const float* __restrict__ v,
                                                   __nv_bfloat16* __restrict__ th,
                                                   __nv_bfloat16* __restrict__ tl)
{
    __shared__ float s[32][33];
    int s0 = blockIdx.x * 32, d0 = blockIdx.y * 32;
    int b = blockIdx.z / NKV_, kv = blockIdx.z % NKV_;
    int tx = threadIdx.x, ty = threadIdx.y;
#pragma unroll
    for (int i = ty; i < 32; i += 8)
        s[i][tx] = v[(((size_t)(b * S_ + s0 + i) * NKV_) + kv) * HD_ + d0 + tx];
    __syncthreads();
#pragma unroll
    for (int i = ty; i < 32; i += 8) {
        float val = s[tx][i];
        __nv_bfloat16 hi = __float2bfloat16_rn(val);
        size_t o = ((size_t)(b * NKV_ + kv) * HD_ + d0 + i) * S_ + s0 + tx;
        th[o] = hi;
        tl[o] = __float2bfloat16_rn(val - __bfloat162float(hi));
    }
}

// ============================================================================
// Tensor-core flash attention.
// grid (S/128, NH, B), 256 threads (8 warps; warp w owns q rows w*16..+15).
// QK^T: 3-pass hi/lo. P: hi/lo split (register repack). P@V: 3-pass
// (Ph*Vh + Ph*Vl + Pl*Vh). fp32 online softmax.
// ============================================================================
#define AK       64
#define NKB      (S_ / AK)
#define KSTRIDE  272           // 136 bf16
#define VSTRIDE  144           // 72 bf16
#define OFF_KL   17408
#define OFF_VH   34816
#define OFF_VL   53248
#define STG      71680

__global__ __launch_bounds__(256, 1) void attn_mma(
    const __nv_bfloat16* __restrict__ Qh, const __nv_bfloat16* __restrict__ Ql,
    const __nv_bfloat16* __restrict__ Kh, const __nv_bfloat16* __restrict__ Kl,
    const __nv_bfloat16* __restrict__ Vh, const __nv_bfloat16* __restrict__ Vl,
    __nv_bfloat16* __restrict__ Oh, __nv_bfloat16* __restrict__ Ol)
{
    extern __shared__ __align__(16) char sm[];
    const uint32_t sm0 = smem_u32(sm);
    const int tid = threadIdx.x, lane = tid & 31, w = tid >> 5;
    const int g = lane >> 2, q = lane & 3;
    const int q0 = blockIdx.x * 128;
    const int h = blockIdx.y, b = blockIdx.z;
    const int kvh = h >> 2;

    // ---- stage Q through smem, build register fragments ----
    uint32_t fqh[8][4], fql[8][4];
    {
        const __nv_bfloat16* srcs[2] = { Qh, Ql };
#pragma unroll
        for (int rep = 0; rep < 2; ++rep) {
#pragma unroll
            for (int i = 0; i < 8; ++i) {
                int c = tid + i * 256;
                int r = c >> 4, cc = c & 15;
                cp16(sm0 + r * KSTRIDE + cc * 16,
                     srcs[rep] + ((size_t)((b * S_ + q0 + r) * NH_) + h) * HD_ + cc * 8);
            }
            CP_COMMIT(); CP_WAIT0();
            __syncthreads();
            uint32_t base = sm0 + (w * 16 + g) * KSTRIDE + q * 4;
#pragma unroll
            for (int t = 0; t < 8; ++t) {
                uint32_t a = base + t * 32;
                uint32_t* f = rep ? fql[t] : fqh[t];
                f[0] = lds32(a);
                f[1] = lds32(a + 8 * KSTRIDE);
                f[2] = lds32(a + 16);
                f[3] = lds32(a + 8 * KSTRIDE + 16);
            }
            __syncthreads();
        }
    }

    auto prefetch = [&](int kb, int s) {
        uint32_t st = sm0 + s * STG;
#pragma unroll
        for (int i = 0; i < 4; ++i) {
            int c = tid + i * 256;
            int r = c >> 4, cc = c & 15;
            size_t go = ((size_t)((b * S_ + kb * AK + r) * NKV_) + kvh) * HD_ + cc * 8;
            cp16(st + r * KSTRIDE + cc * 16, Kh + go);
            cp16(st + OFF_KL + r * KSTRIDE + cc * 16, Kl + go);
        }
#pragma unroll
        for (int i = 0; i < 4; ++i) {
            int c = tid + i * 256;
            int d = c >> 3, cc = c & 7;
            size_t go = ((size_t)(b * NKV_ + kvh) * HD_ + d) * S_ + kb * AK + cc * 8;
            cp16(st + OFF_VH + d * VSTRIDE + cc * 16, Vh + go);
            cp16(st + OFF_VL + d * VSTRIDE + cc * 16, Vl + go);
        }
        CP_COMMIT();
    };

    float oacc[16][4];
#pragma unroll
    for (int i = 0; i < 16; ++i)
#pragma unroll
        for (int u = 0; u < 4; ++u) oacc[i][u] = 0.f;
    float m0 = -1e30f, m1 = -1e30f, l0 = 0.f, l1 = 0.f;

    prefetch(0, 0);

    for (int kb = 0; kb < NKB; ++kb) {
        const int s = kb & 1;
        if (kb + 1 < NKB) { prefetch(kb + 1, s ^ 1); CP_WAIT1(); }
        else              { CP_WAIT0(); }
        __syncthreads();

        const uint32_t st = sm0 + s * STG;

        // ---- S = Q K^T (3-pass split) ----
        float sacc[8][4];
#pragma unroll
        for (int n = 0; n < 8; ++n)
#pragma unroll
            for (int u = 0; u < 4; ++u) sacc[n][u] = 0.f;

#pragma unroll
        for (int t = 0; t < 8; ++t) {
#pragma unroll
            for (int n = 0; n < 8; ++n) {
                uint32_t bo = st + (n * 8 + g) * KSTRIDE + t * 32 + q * 4;
                uint32_t bh0 = lds32(bo),            bh1 = lds32(bo + 16);
                uint32_t bl0 = lds32(bo + OFF_KL),   bl1 = lds32(bo + OFF_KL + 16);
                MMA_BF16S(sacc[n], fqh[t], bh0, bh1);
                MMA_BF16S(sacc[n], fqh[t], bl0, bl1);
                MMA_BF16S(sacc[n], fql[t], bh0, bh1);
            }
        }

        // ---- online softmax (rows r0 = w*16+g, r1 = r0+8) ----
        float rmax0 = -1e30f, rmax1 = -1e30f;
#pragma unroll
        for (int n = 0; n < 8; ++n) {
            rmax0 = fmaxf(rmax0, fmaxf(sacc[n][0], sacc[n][1]));
            rmax1 = fmaxf(rmax1, fmaxf(sacc[n][2], sacc[n][3]));
        }
        rmax0 = fmaxf(rmax0, __shfl_xor_sync(0xffffffffu, rmax0, 1));
        rmax0 = fmaxf(rmax0, __shfl_xor_sync(0xffffffffu, rmax0, 2));
        rmax1 = fmaxf(rmax1, __shfl_xor_sync(0xffffffffu, rmax1, 1));
        rmax1 = fmaxf(rmax1, __shfl_xor_sync(0xffffffffu, rmax1, 2));

        float nm0 = fmaxf(m0, rmax0), nm1 = fmaxf(m1, rmax1);
        float f0 = __expf(m0 - nm0),  f1 = __expf(m1 - nm1);
        m0 = nm0; m1 = nm1;

        float sum0 = 0.f, sum1 = 0.f;
#pragma unroll
        for (int n = 0; n < 8; ++n) {
            float p0 = __expf(sacc[n][0] - nm0);
            float p1 = __expf(sacc[n][1] - nm0);
            float p2 = __expf(sacc[n][2] - nm1);
            float p3 = __expf(sacc[n][3] - nm1);
            sum0 += p0 + p1; sum1 += p2 + p3;
            sacc[n][0] = p0; sacc[n][1] = p1; sacc[n][2] = p2; sacc[n][3] = p3;
        }
        sum0 += __shfl_xor_sync(0xffffffffu, sum0, 1);
        sum0 += __shfl_xor_sync(0xffffffffu, sum0, 2);
        sum1 += __shfl_xor_sync(0xffffffffu, sum1, 1);
        sum1 += __shfl_xor_sync(0xffffffffu, sum1, 2);
        l0 = l0 * f0 + sum0;
        l1 = l1 * f1 + sum1;

        // P -> hi/lo A fragments (register repack, no smem)
        uint32_t pah[4][4], pal[4][4];
#pragma unroll
        for (int t = 0; t < 4; ++t) {
#pragma unroll
            for (int hw = 0; hw < 2; ++hw) {       // which of the two n-frags
                const float* pv = sacc[2 * t + hw];
#pragma unroll
                for (int uu = 0; uu < 2; ++uu) {   // row pair (c0c1 / c2c3)
                    float v0 = pv[2 * uu], v1 = pv[2 * uu + 1];
                    __nv_bfloat16 hh0 = __float2bfloat16_rn(v0);
                    __nv_bfloat16 hh1 = __float2bfloat16_rn(v1);
                    __nv_bfloat162 hp = __nv_bfloat162(hh0, hh1);
                    __nv_bfloat162 lp = __nv_bfloat162(
                        __float2bfloat16_rn(v0 - __bfloat162float(hh0)),
                        __float2bfloat16_rn(v1 - __bfloat162float(hh1)));
                    pah[t][hw * 2 + uu] = *(uint32_t*)&hp;
                    pal[t][hw * 2 + uu] = *(uint32_t*)&lp;
                }
            }
        }

#pragma unroll
        for (int nf = 0; nf < 16; ++nf) {
            oacc[nf][0] *= f0; oacc[nf][1] *= f0;
            oacc[nf][2] *= f1; oacc[nf][3] *= f1;
        }

        // ---- O += Ph*(Vh+Vl) + Pl*Vh ----
#pragma unroll
        for (int t = 0; t < 4; ++t) {
#pragma unroll
            for (int nf = 0; nf < 16; ++nf) {
                uint32_t vo = st + OFF_VH + (nf * 8 + g) * VSTRIDE + t * 32 + q * 4;
                uint32_t vh0 = lds32(vo),          vh1 = lds32(vo + 16);
                uint32_t vl0 = lds32(vo + 18432),  vl1 = lds32(vo + 18432 + 16);
                MMA_BF16S(oacc[nf], pah[t], vh0, vh1);
                MMA_BF16S(oacc[nf], pah[t], vl0, vl1);
                MMA_BF16S(oacc[nf], pal[t], vh0, vh1);
            }
        }
        __syncthreads();
    }

    // ---- epilogue: normalize, split to bf16 hi/lo ----
    float inv0 = 1.0f / l0, inv1 = 1.0f / l1;
    int r0 = q0 + w * 16 + g;
#pragma unroll
    for (int nf = 0; nf < 16; ++nf) {
        int col = nf * 8 + 2 * q;
        {
            float v0 = oacc[nf][0] * inv0, v1 = oacc[nf][1] * inv0;
            __nv_bfloat16 h0 = __float2bfloat16_rn(v0);
            __nv_bfloat16 h1 = __float2bfloat16_rn(v1);
            size_t off = (size_t)(b * S_ + r0) * DIM_ + h * HD_ + col;
            *(__nv_bfloat162*)(Oh + off) = __nv_bfloat162(h0, h1);
            *(__nv_bfloat162*)(Ol + off) = __nv_bfloat162(
                __float2bfloat16_rn(v0 - __bfloat162float(h0)),
                __float2bfloat16_rn(v1 - __bfloat162float(h1)));
        }
        {
            float v0 = oacc[nf][2] * inv1, v1 = oacc[nf][3] * inv1;
            __nv_bfloat16 h0 = __float2bfloat16_rn(v0);
            __nv_bfloat16 h1 = __float2bfloat16_rn(v1);
            size_t off = (size_t)(b * S_ + r0 + 8) * DIM_ + h * HD_ + col;
            *(__nv_bfloat162*)(Oh + off) = __nv_bfloat162(h0, h1);
            *(__nv_bfloat162*)(Ol + off) = __nv_bfloat162(
                __float2bfloat16_rn(v0 - __bfloat162float(h0)),
                __float2bfloat16_rn(v1 - __bfloat162float(h1)));
        }
    }
}

// ============================================================================
// launch
// ============================================================================
extern "C" void kernel_launch(void* const* d_in, const int* in_sizes, int n_in,
                              void* d_out, int out_size)
{
    const float* x  = (const float*)d_in[0];
    const float* wq = (const float*)d_in[1];
    const float* wk = (const float*)d_in[2];
    const float* wv = (const float*)d_in[3];
    const float* wo = (const float*)d_in[4];
    const float* fc = (const float*)d_in[5];
    const float* fs = (const float*)d_in[6];
    float* out = (float*)d_out;

    float *qp, *kp, *vp;
    cudaGetSymbolAddress((void**)&qp, g_q);
    cudaGetSymbolAddress((void**)&kp, g_k);
    cudaGetSymbolAddress((void**)&vp, g_v);
    __nv_bfloat16 *xh, *xl, *wqh, *wql, *wkh, *wkl, *wvh, *wvl, *woh, *wol, *ah, *al;
    __nv_bfloat16 *qsh, *qsl, *ksh, *ksl, *vth, *vtl;
    cudaGetSymbolAddress((void**)&xh, g_xh);   cudaGetSymbolAddress((void**)&xl, g_xl);
    cudaGetSymbolAddress((void**)&wqh, g_wqh); cudaGetSymbolAddress((void**)&wql, g_wql);
    cudaGetSymbolAddress((void**)&wkh, g_wkh); cudaGetSymbolAddress((void**)&wkl, g_wkl);
    cudaGetSymbolAddress((void**)&wvh, g_wvh); cudaGetSymbolAddress((void**)&wvl, g_wvl);
    cudaGetSymbolAddress((void**)&woh, g_woh); cudaGetSymbolAddress((void**)&wol, g_wol);
    cudaGetSymbolAddress((void**)&ah, g_ah);   cudaGetSymbolAddress((void**)&al, g_al);
    cudaGetSymbolAddress((void**)&qsh, g_qsh); cudaGetSymbolAddress((void**)&qsl, g_qsl);
    cudaGetSymbolAddress((void**)&ksh, g_ksh); cudaGetSymbolAddress((void**)&ksl, g_ksl);
    cudaGetSymbolAddress((void**)&vth, g_vth); cudaGetSymbolAddress((void**)&vtl, g_vtl);

    const int GEMM_SMEM = 2 * STAGE_B;   // 81920
    cudaFuncSetAttribute(gemm_mma, cudaFuncAttributeMaxDynamicSharedMemorySize,
                         GEMM_SMEM);
    const int ATTN_SMEM = 2 * STG;       // 143360
    cudaFuncSetAttribute(attn_mma, cudaFuncAttributeMaxDynamicSharedMemorySize,
                         ATTN_SMEM);

    const int M = B_ * S_;               // 4096

    // operand prep
    split_kernel<<<((size_t)M * DIM_ / 4 + 255) / 256, 256>>>(x, xh, xl, M * DIM_ / 4);
    transpose_split<<<dim3(DIM_ / 32, DIM_ / 32), dim3(32, 8)>>>(wq, wqh, wql, DIM_, DIM_);
    transpose_split<<<dim3(NKV_ * HD_ / 32, DIM_ / 32), dim3(32, 8)>>>(wk, wkh, wkl, DIM_, NKV_ * HD_);
    transpose_split<<<dim3(NKV_ * HD_ / 32, DIM_ / 32), dim3(32, 8)>>>(wv, wvh, wvl, DIM_, NKV_ * HD_);
    transpose_split<<<dim3(DIM_ / 32, DIM_ / 32), dim3(32, 8)>>>(wo, woh, wol, DIM_, DIM_);

    // projections (tensor cores)
    gemm_mma<<<dim3(DIM_ / 128, M / 128), 256, GEMM_SMEM>>>(
        xh, xl, wqh, wql, qp, M, DIM_, DIM_);
    gemm_mma<<<dim3(NKV_ * HD_ / 128, M / 128), 256, GEMM_SMEM>>>(
        xh, xl, wkh, wkl, kp, M, NKV_ * HD_, DIM_);
    gemm_mma<<<dim3(NKV_ * HD_ / 128, M / 128), 256, GEMM_SMEM>>>(
        xh, xl, wvh, wvl, vp, M, NKV_ * HD_, DIM_);

    // RoPE + split (Q pre-scaled by 1/sqrt(HD)); V transpose+split
    rope_split<<<(B_ * S_ * NH_ * 64 + 255) / 256, 256>>>(
        qp, fc, fs, qsh, qsl, NH_, 0.08838834764831845f);
    rope_split<<<(B_ * S_ * NKV_ * 64 + 255) / 256, 256>>>(
        kp, fc, fs, ksh, ksl, NKV_, 1.0f);
    transpose_v<<<dim3(S_ / 32, HD_ / 32, B_ * NKV_), dim3(32, 8)>>>(vp, vth, vtl);

    // attention (tensor cores)
    attn_mma<<<dim3(S_ / 128, NH_, B_), 256, ATTN_SMEM>>>(
        qsh, qsl, ksh, ksl, vth, vtl, ah, al);

    // output projection
    gemm_mma<<<dim3(DIM_ / 128, M / 128), 256, GEMM_SMEM>>>(
        ah, al, woh, wol, out, M, DIM_, DIM_);
}

// round 9
// speedup vs baseline: 3.0303x; 1.1180x over previous
#include <cuda_runtime.h>
#include <cuda_bf16.h>
#include <cstdint>
#include <cstddef>

#define B_   2
#define S_   2048
#define DIM_ 4096
#define NH_  32
#define NKV_ 8
#define HD_  128

// ---------------- scratch (no allocations allowed) ----------------
__device__ float g_v[(size_t)B_ * S_ * NKV_ * HD_];    // fp32 V (pre-transpose)

__device__ __nv_bfloat16 g_xh[(size_t)B_ * S_ * DIM_];
__device__ __nv_bfloat16 g_xl[(size_t)B_ * S_ * DIM_];
__device__ __nv_bfloat16 g_wqh[(size_t)DIM_ * DIM_];
__device__ __nv_bfloat16 g_wql[(size_t)DIM_ * DIM_];
__device__ __nv_bfloat16 g_wkh[(size_t)DIM_ * NKV_ * HD_];
__device__ __nv_bfloat16 g_wkl[(size_t)DIM_ * NKV_ * HD_];
__device__ __nv_bfloat16 g_wvh[(size_t)DIM_ * NKV_ * HD_];
__device__ __nv_bfloat16 g_wvl[(size_t)DIM_ * NKV_ * HD_];
__device__ __nv_bfloat16 g_woh[(size_t)DIM_ * DIM_];
__device__ __nv_bfloat16 g_wol[(size_t)DIM_ * DIM_];
__device__ __nv_bfloat16 g_ah[(size_t)B_ * S_ * DIM_];
__device__ __nv_bfloat16 g_al[(size_t)B_ * S_ * DIM_];

__device__ __nv_bfloat16 g_qsh[(size_t)B_ * S_ * NH_ * HD_];
__device__ __nv_bfloat16 g_qsl[(size_t)B_ * S_ * NH_ * HD_];
__device__ __nv_bfloat16 g_ksh[(size_t)B_ * S_ * NKV_ * HD_];
__device__ __nv_bfloat16 g_ksl[(size_t)B_ * S_ * NKV_ * HD_];
__device__ __nv_bfloat16 g_vth[(size_t)B_ * NKV_ * HD_ * S_];   // V^T [b][kv][d][s]
__device__ __nv_bfloat16 g_vtl[(size_t)B_ * NKV_ * HD_ * S_];

// ============================ PTX helpers (sm_80-portable) ============================
__device__ __forceinline__ uint32_t smem_u32(const void* p) {
    uint32_t a;
    asm("{ .reg .u64 t; cvta.to.shared.u64 t, %1; cvt.u32.u64 %0, t; }"
        : "=r"(a) : "l"(p));
    return a;
}

__device__ __forceinline__ void cp16(uint32_t dst, const void* src) {
    asm volatile("cp.async.cg.shared.global [%0], [%1], 16;" :: "r"(dst), "l"(src));
}

__device__ __forceinline__ uint32_t lds32(uint32_t a) {
    uint32_t v;
    asm volatile("ld.shared.b32 %0, [%1];" : "=r"(v) : "r"(a));
    return v;
}

__device__ __forceinline__ void ldmx4(uint32_t* r, uint32_t addr) {
    asm volatile("ldmatrix.sync.aligned.m8n8.x4.shared.b16 {%0,%1,%2,%3}, [%4];"
        : "=r"(r[0]), "=r"(r[1]), "=r"(r[2]), "=r"(r[3]) : "r"(addr));
}

#define CP_COMMIT() asm volatile("cp.async.commit_group;" ::: "memory")
#define CP_WAIT1()  asm volatile("cp.async.wait_group 1;"  ::: "memory")
#define CP_WAIT0()  asm volatile("cp.async.wait_group 0;"  ::: "memory")

#define MMA_BF16(c, A, Bf)                                                        \
    asm volatile(                                                                 \
        "mma.sync.aligned.m16n8k16.row.col.f32.bf16.bf16.f32 "                    \
        "{%0,%1,%2,%3},{%4,%5,%6,%7},{%8,%9},{%0,%1,%2,%3};"                      \
        : "+f"((c)[0]), "+f"((c)[1]), "+f"((c)[2]), "+f"((c)[3])                  \
        : "r"((A)[0]), "r"((A)[1]), "r"((A)[2]), "r"((A)[3]),                     \
          "r"((Bf)[0]), "r"((Bf)[1]))

#define MMA_BF16S(c, A, b0, b1)                                                   \
    asm volatile(                                                                 \
        "mma.sync.aligned.m16n8k16.row.col.f32.bf16.bf16.f32 "                    \
        "{%0,%1,%2,%3},{%4,%5,%6,%7},{%8,%9},{%0,%1,%2,%3};"                      \
        : "+f"((c)[0]), "+f"((c)[1]), "+f"((c)[2]), "+f"((c)[3])                  \
        : "r"((A)[0]), "r"((A)[1]), "r"((A)[2]), "r"((A)[3]),                     \
          "r"(b0), "r"(b1))

// ============================================================================
// Shared GEMM mainloop machinery (CTA 128x128, BK=32, 8 warps 2x4, ldmatrix)
// ============================================================================
#define TILE_B   10240
#define STAGE_B  (4 * TILE_B)

struct GemmCore {
    uint32_t sm0;
    int tid, lane, wid, wm, wn, q, rb;
    int row0, col0;
    const __nv_bfloat16* src_[4];
    int r1, kc1, r2, kc2;
    int K;

    __device__ __forceinline__ void init(char* sm,
        const __nv_bfloat16* Ah, const __nv_bfloat16* Al,
        const __nv_bfloat16* Bh, const __nv_bfloat16* Bl, int K_) {
        sm0 = smem_u32(sm);
        tid = threadIdx.x; lane = tid & 31; wid = tid >> 5;
        wm = wid >> 2; wn = wid & 3; q = lane & 3; rb = lane >> 2;
        row0 = blockIdx.y * 128; col0 = blockIdx.x * 128;
        K = K_;
        src_[0] = Ah + (size_t)row0 * K;
        src_[1] = Al + (size_t)row0 * K;
        src_[2] = Bh + (size_t)col0 * K;
        src_[3] = Bl + (size_t)col0 * K;
        r1 = tid >> 2; kc1 = tid & 3;
        r2 = (tid + 256) >> 2; kc2 = (tid + 256) & 3;
    }

    __device__ __forceinline__ void load_stage(int it, int s) {
        const uint32_t base = sm0 + s * STAGE_B;
        const int kel = it * 32;
#pragma unroll
        for (int t = 0; t < 4; ++t) {
            const __nv_bfloat16* g = src_[t] + kel;
            cp16(base + t * TILE_B + r1 * 80 + kc1 * 16, g + (size_t)r1 * K + kc1 * 8);
            cp16(base + t * TILE_B + r2 * 80 + kc2 * 16, g + (size_t)r2 * K + kc2 * 8);
        }
        CP_COMMIT();
    }

    __device__ __forceinline__ void mainloop(float acc[4][4][4]) {
#pragma unroll
        for (int i = 0; i < 4; ++i)
#pragma unroll
            for (int j = 0; j < 4; ++j)
#pragma unroll
                for (int u = 0; u < 4; ++u) acc[i][j][u] = 0.f;

        const int KIT = K >> 5;
        load_stage(0, 0);

        // ldmatrix lane-address components
        const int a_row = lane & 15;            // A: row within 16-row frag
        const int a_off = (lane >> 4) * 16;     // A: k-half byte offset
        const int b_row = (lane & 7) + (lane >> 4) * 8;   // B: n row within 16
        const int b_off = ((lane >> 3) & 1) * 16;         // B: k-half byte

        for (int it = 0; it < KIT; ++it) {
            if (it + 1 < KIT) { load_stage(it + 1, (it + 1) & 1); CP_WAIT1(); }
            else              { CP_WAIT0(); }
            __syncthreads();

            const uint32_t base = sm0 + (it & 1) * STAGE_B;
#pragma unroll
            for (int kk = 0; kk < 2; ++kk) {
                const int kb = kk * 32;
                uint32_t ah[4][4], al[4][4], bh[4][2], bl[4][2];
#pragma unroll
                for (int mf = 0; mf < 4; ++mf) {
                    uint32_t ra = base + (wm * 64 + mf * 16 + a_row) * 80 + kb + a_off;
                    ldmx4(ah[mf], ra);
                    ldmx4(al[mf], ra + TILE_B);
                }
#pragma unroll
                for (int np = 0; np < 2; ++np) {
                    uint32_t rbq = base + 2 * TILE_B +
                                   (wn * 32 + np * 16 + b_row) * 80 + kb + b_off;
                    uint32_t t4[4];
                    ldmx4(t4, rbq);
                    bh[2*np][0] = t4[0]; bh[2*np][1] = t4[1];
                    bh[2*np+1][0] = t4[2]; bh[2*np+1][1] = t4[3];
                    ldmx4(t4, rbq + TILE_B);
                    bl[2*np][0] = t4[0]; bl[2*np][1] = t4[1];
                    bl[2*np+1][0] = t4[2]; bl[2*np+1][1] = t4[3];
                }
#pragma unroll
                for (int mf = 0; mf < 4; ++mf)
#pragma unroll
                    for (int nf = 0; nf < 4; ++nf) {
                        MMA_BF16(acc[mf][nf], ah[mf], bh[nf]);
                        MMA_BF16(acc[mf][nf], ah[mf], bl[nf]);
                        MMA_BF16(acc[mf][nf], al[mf], bh[nf]);
                    }
            }
            __syncthreads();
        }
    }
};

// ---- plain GEMM: fp32 output ----
__global__ __launch_bounds__(256) void gemm_mma(
    const __nv_bfloat16* __restrict__ Ah, const __nv_bfloat16* __restrict__ Al,
    const __nv_bfloat16* __restrict__ Bh, const __nv_bfloat16* __restrict__ Bl,
    float* __restrict__ C, int M, int N, int K)
{
    extern __shared__ __align__(16) char sm[];
    GemmCore gc; gc.init(sm, Ah, Al, Bh, Bl, K);
    float acc[4][4][4];
    gc.mainloop(acc);
#pragma unroll
    for (int mf = 0; mf < 4; ++mf) {
        int row = gc.row0 + gc.wm * 64 + mf * 16 + gc.rb;
#pragma unroll
        for (int nf = 0; nf < 4; ++nf) {
            int col = gc.col0 + gc.wn * 32 + nf * 8 + gc.q * 2;
            *(float2*)(C + (size_t)row * N + col) =
                make_float2(acc[mf][nf][0], acc[mf][nf][1]);
            *(float2*)(C + (size_t)(row + 8) * N + col) =
                make_float2(acc[mf][nf][2], acc[mf][nf][3]);
        }
    }
}

// ---- GEMM + fused RoPE + scale + bf16 hi/lo split output ----
__global__ __launch_bounds__(256) void gemm_rope(
    const __nv_bfloat16* __restrict__ Ah, const __nv_bfloat16* __restrict__ Al,
    const __nv_bfloat16* __restrict__ Bh, const __nv_bfloat16* __restrict__ Bl,
    const float* __restrict__ cs, const float* __restrict__ sn,
    __nv_bfloat16* __restrict__ Oh, __nv_bfloat16* __restrict__ Ol,
    int M, int N, int K, float scale)
{
    extern __shared__ __align__(16) char sm[];
    GemmCore gc; gc.init(sm, Ah, Al, Bh, Bl, K);
    float acc[4][4][4];
    gc.mainloop(acc);
#pragma unroll
    for (int mf = 0; mf < 4; ++mf) {
        int row = gc.row0 + gc.wm * 64 + mf * 16 + gc.rb;
        int s0 = row & (S_ - 1);
#pragma unroll
        for (int nf = 0; nf < 4; ++nf) {
            int col = gc.col0 + gc.wn * 32 + nf * 8 + gc.q * 2;
            int p = (col & (HD_ - 1)) >> 1;
#pragma unroll
            for (int half = 0; half < 2; ++half) {
                int s = s0 + half * 8;
                float c = cs[(s << 6) + p];
                float si = sn[(s << 6) + p];
                float xr = acc[mf][nf][2 * half];
                float xi = acc[mf][nf][2 * half + 1];
                float o0 = fmaf(xr, c, -xi * si) * scale;
                float o1 = fmaf(xr, si,  xi * c) * scale;
                __nv_bfloat16 h0 = __float2bfloat16_rn(o0);
                __nv_bfloat16 h1 = __float2bfloat16_rn(o1);
                size_t off = (size_t)(row + half * 8) * N + col;
                *(__nv_bfloat162*)(Oh + off) = __nv_bfloat162(h0, h1);
                *(__nv_bfloat162*)(Ol + off) = __nv_bfloat162(
                    __float2bfloat16_rn(o0 - __bfloat162float(h0)),
                    __float2bfloat16_rn(o1 - __bfloat162float(h1)));
            }
        }
    }
}

// ============================================================================
// fp32 -> bf16 hi/lo split
// ============================================================================
__global__ __launch_bounds__(256) void split_kernel(const float* __restrict__ in,
                                                    __nv_bfloat16* __restrict__ h,
                                                    __nv_bfloat16* __restrict__ l,
                                                    int n4)
{
    int i = blockIdx.x * blockDim.x + threadIdx.x;
    if (i >= n4) return;
    float4 v = ((const float4*)in)[i];
    __nv_bfloat16 h0 = __float2bfloat16_rn(v.x);
    __nv_bfloat16 h1 = __float2bfloat16_rn(v.y);
    __nv_bfloat16 h2 = __float2bfloat16_rn(v.z);
    __nv_bfloat16 h3 = __float2bfloat16_rn(v.w);
    __nv_bfloat16 l0 = __float2bfloat16_rn(v.x - __bfloat162float(h0));
    __nv_bfloat16 l1 = __float2bfloat16_rn(v.y - __bfloat162float(h1));
    __nv_bfloat16 l2 = __float2bfloat16_rn(v.z - __bfloat162float(h2));
    __nv_bfloat16 l3 = __float2bfloat16_rn(v.w - __bfloat162float(h3));
    ((__nv_bfloat162*)h)[2 * i + 0] = __nv_bfloat162(h0, h1);
    ((__nv_bfloat162*)h)[2 * i + 1] = __nv_bfloat162(h2, h3);
    ((__nv_bfloat162*)l)[2 * i + 0] = __nv_bfloat162(l0, l1);
    ((__nv_bfloat162*)l)[2 * i + 1] = __nv_bfloat162(l2, l3);
}

// ============================================================================
// w[K,N] fp32 -> wT hi/lo bf16 [N,K]
// ============================================================================
__global__ __launch_bounds__(256) void transpose_split(const float* __restrict__ w,
                                                       __nv_bfloat16* __restrict__ th,
                                                       __nv_bfloat16* __restrict__ tl,
                                                       int K, int N)
{
    __shared__ float s[32][33];
    int n0 = blockIdx.x * 32, k0 = blockIdx.y * 32;
    int tx = threadIdx.x, ty = threadIdx.y;
#pragma unroll
    for (int i = ty; i < 32; i += 8)
        s[i][tx] = w[(size_t)(k0 + i) * N + n0 + tx];
    __syncthreads();
#pragma unroll
    for (int i = ty; i < 32; i += 8) {
        float v = s[tx][i];
        __nv_bfloat16 hi = __float2bfloat16_rn(v);
        size_t o = (size_t)(n0 + i) * K + k0 + tx;
        th[o] = hi;
        tl[o] = __float2bfloat16_rn(v - __bfloat162float(hi));
    }
}

// ============================================================================
// V fp32 [b][s][kv][d] -> V^T bf16 hi/lo [b][kv][d][s]
// ============================================================================
__global__ __launch_bounds__(256) void transpose_v(const float* __restrict__ v,
                                                   __nv_bfloat16* __restrict__ th,
                                                   __nv_bfloat16* __restrict__ tl)
{
    __shared__ float s[32][33];
    int s0 = blockIdx.x * 32, d0 = blockIdx.y * 32;
    int b = blockIdx.z / NKV_, kv = blockIdx.z % NKV_;
    int tx = threadIdx.x, ty = threadIdx.y;
#pragma unroll
    for (int i = ty; i < 32; i += 8)
        s[i][tx] = v[(((size_t)(b * S_ + s0 + i) * NKV_) + kv) * HD_ + d0 + tx];
    __syncthreads();
#pragma unroll
    for (int i = ty; i < 32; i += 8) {
        float val = s[tx][i];
        __nv_bfloat16 hi = __float2bfloat16_rn(val);
        size_t o = ((size_t)(b * NKV_ + kv) * HD_ + d0 + i) * S_ + s0 + tx;
        th[o] = hi;
        tl[o] = __float2bfloat16_rn(val - __bfloat162float(hi));
    }
}

// ============================================================================
// Tensor-core flash attention (ldmatrix fragment loads).
// ============================================================================
#define AK       64
#define NKB      (S_ / AK)
#define KSTRIDE  272
#define VSTRIDE  144
#define OFF_KL   17408
#define OFF_VH   34816
#define OFF_VL   53248
#define STG      71680

__global__ __launch_bounds__(256, 1) void attn_mma(
    const __nv_bfloat16* __restrict__ Qh, const __nv_bfloat16* __restrict__ Ql,
    const __nv_bfloat16* __restrict__ Kh, const __nv_bfloat16* __restrict__ Kl,
    const __nv_bfloat16* __restrict__ Vh, const __nv_bfloat16* __restrict__ Vl,
    __nv_bfloat16* __restrict__ Oh, __nv_bfloat16* __restrict__ Ol)
{
    extern __shared__ __align__(16) char sm[];
    const uint32_t sm0 = smem_u32(sm);
    const int tid = threadIdx.x, lane = tid & 31, w = tid >> 5;
    const int g = lane >> 2, q = lane & 3;
    const int q0 = blockIdx.x * 128;
    const int h = blockIdx.y, b = blockIdx.z;
    const int kvh = h >> 2;

    const int rowlane = lane & 7;
    const int part = lane >> 3;         // 0..3: {hi k0, hi k8, lo k0, lo k8}
    const int poff16 = (part & 1) * 16;
    const int plo = part >> 1;

    // ---- stage Q through smem, build register fragments ----
    uint32_t fqh[8][4], fql[8][4];
    {
        const __nv_bfloat16* srcs[2] = { Qh, Ql };
#pragma unroll
        for (int rep = 0; rep < 2; ++rep) {
#pragma unroll
            for (int i = 0; i < 8; ++i) {
                int c = tid + i * 256;
                int r = c >> 4, cc = c & 15;
                cp16(sm0 + r * KSTRIDE + cc * 16,
                     srcs[rep] + ((size_t)((b * S_ + q0 + r) * NH_) + h) * HD_ + cc * 8);
            }
            CP_COMMIT(); CP_WAIT0();
            __syncthreads();
            // A-fragment ldmatrix: rows w*16 + (lane&15), k-half (lane>>4)
            uint32_t base = sm0 + (w * 16 + (lane & 15)) * KSTRIDE + (lane >> 4) * 16;
#pragma unroll
            for (int t = 0; t < 8; ++t)
                ldmx4(rep ? fql[t] : fqh[t], base + t * 32);
            __syncthreads();
        }
    }

    auto prefetch = [&](int kb, int s) {
        uint32_t st = sm0 + s * STG;
#pragma unroll
        for (int i = 0; i < 4; ++i) {
            int c = tid + i * 256;
            int r = c >> 4, cc = c & 15;
            size_t go = ((size_t)((b * S_ + kb * AK + r) * NKV_) + kvh) * HD_ + cc * 8;
            cp16(st + r * KSTRIDE + cc * 16, Kh + go);
            cp16(st + OFF_KL + r * KSTRIDE + cc * 16, Kl + go);
        }
#pragma unroll
        for (int i = 0; i < 4; ++i) {
            int c = tid + i * 256;
            int d = c >> 3, cc = c & 7;
            size_t go = ((size_t)(b * NKV_ + kvh) * HD_ + d) * S_ + kb * AK + cc * 8;
            cp16(st + OFF_VH + d * VSTRIDE + cc * 16, Vh + go);
            cp16(st + OFF_VL + d * VSTRIDE + cc * 16, Vl + go);
        }
        CP_COMMIT();
    };

    float oacc[16][4];
#pragma unroll
    for (int i = 0; i < 16; ++i)
#pragma unroll
        for (int u = 0; u < 4; ++u) oacc[i][u] = 0.f;
    float m0 = -1e30f, m1 = -1e30f, l0 = 0.f, l1 = 0.f;

    prefetch(0, 0);

    for (int kb = 0; kb < NKB; ++kb) {
        const int s = kb & 1;
        if (kb + 1 < NKB) { prefetch(kb + 1, s ^ 1); CP_WAIT1(); }
        else              { CP_WAIT0(); }
        __syncthreads();

        const uint32_t st = sm0 + s * STG;

        // ---- S = Q K^T (3-pass split) ----
        float sacc[8][4];
#pragma unroll
        for (int n = 0; n < 8; ++n)
#pragma unroll
            for (int u = 0; u < 4; ++u) sacc[n][u] = 0.f;

#pragma unroll
        for (int t = 0; t < 8; ++t) {
#pragma unroll
            for (int n = 0; n < 8; ++n) {
                // one ldmatrix.x4 -> {Kh b0, Kh b1, Kl b0, Kl b1}
                uint32_t r4[4];
                ldmx4(r4, st + (n * 8 + rowlane) * KSTRIDE + t * 32 + poff16 +
                          plo * OFF_KL);
                MMA_BF16S(sacc[n], fqh[t], r4[0], r4[1]);
                MMA_BF16S(sacc[n], fqh[t], r4[2], r4[3]);
                MMA_BF16S(sacc[n], fql[t], r4[0], r4[1]);
            }
        }

        // ---- online softmax ----
        float rmax0 = -1e30f, rmax1 = -1e30f;
#pragma unroll
        for (int n = 0; n < 8; ++n) {
            rmax0 = fmaxf(rmax0, fmaxf(sacc[n][0], sacc[n][1]));
            rmax1 = fmaxf(rmax1, fmaxf(sacc[n][2], sacc[n][3]));
        }
        rmax0 = fmaxf(rmax0, __shfl_xor_sync(0xffffffffu, rmax0, 1));
        rmax0 = fmaxf(rmax0, __shfl_xor_sync(0xffffffffu, rmax0, 2));
        rmax1 = fmaxf(rmax1, __shfl_xor_sync(0xffffffffu, rmax1, 1));
        rmax1 = fmaxf(rmax1, __shfl_xor_sync(0xffffffffu, rmax1, 2));

        float nm0 = fmaxf(m0, rmax0), nm1 = fmaxf(m1, rmax1);
        float f0 = __expf(m0 - nm0),  f1 = __expf(m1 - nm1);
        m0 = nm0; m1 = nm1;

        float sum0 = 0.f, sum1 = 0.f;
#pragma unroll
        for (int n = 0; n < 8; ++n) {
            float p0 = __expf(sacc[n][0] - nm0);
            float p1 = __expf(sacc[n][1] - nm0);
            float p2 = __expf(sacc[n][2] - nm1);
            float p3 = __expf(sacc[n][3] - nm1);
            sum0 += p0 + p1; sum1 += p2 + p3;
            sacc[n][0] = p0; sacc[n][1] = p1; sacc[n][2] = p2; sacc[n][3] = p3;
        }
        sum0 += __shfl_xor_sync(0xffffffffu, sum0, 1);
        sum0 += __shfl_xor_sync(0xffffffffu, sum0, 2);
        sum1 += __shfl_xor_sync(0xffffffffu, sum1, 1);
        sum1 += __shfl_xor_sync(0xffffffffu, sum1, 2);
        l0 = l0 * f0 + sum0;
        l1 = l1 * f1 + sum1;

        // P -> hi/lo A fragments (register repack)
        uint32_t pah[4][4], pal[4][4];
#pragma unroll
        for (int t = 0; t < 4; ++t) {
#pragma unroll
            for (int hw = 0; hw < 2; ++hw) {
                const float* pv = sacc[2 * t + hw];
#pragma unroll
                for (int uu = 0; uu < 2; ++uu) {
                    float v0 = pv[2 * uu], v1 = pv[2 * uu + 1];
                    __nv_bfloat16 hh0 = __float2bfloat16_rn(v0);
                    __nv_bfloat16 hh1 = __float2bfloat16_rn(v1);
                    __nv_bfloat162 hp = __nv_bfloat162(hh0, hh1);
                    __nv_bfloat162 lp = __nv_bfloat162(
                        __float2bfloat16_rn(v0 - __bfloat162float(hh0)),
                        __float2bfloat16_rn(v1 - __bfloat162float(hh1)));
                    pah[t][hw * 2 + uu] = *(uint32_t*)&hp;
                    pal[t][hw * 2 + uu] = *(uint32_t*)&lp;
                }
            }
        }

#pragma unroll
        for (int nf = 0; nf < 16; ++nf) {
            oacc[nf][0] *= f0; oacc[nf][1] *= f0;
            oacc[nf][2] *= f1; oacc[nf][3] *= f1;
        }

        // ---- O += Ph*(Vh+Vl) + Pl*Vh ----
#pragma unroll
        for (int t = 0; t < 4; ++t) {
#pragma unroll
            for (int nf = 0; nf < 16; ++nf) {
                uint32_t r4[4];
                ldmx4(r4, st + OFF_VH + (nf * 8 + rowlane) * VSTRIDE + t * 32 +
                          poff16 + plo * (OFF_VL - OFF_VH));
                MMA_BF16S(oacc[nf], pah[t], r4[0], r4[1]);
                MMA_BF16S(oacc[nf], pah[t], r4[2], r4[3]);
                MMA_BF16S(oacc[nf], pal[t], r4[0], r4[1]);
            }
        }
        __syncthreads();
    }

    // ---- epilogue: normalize, split to bf16 hi/lo ----
    float inv0 = 1.0f / l0, inv1 = 1.0f / l1;
    int r0 = q0 + w * 16 + g;
#pragma unroll
    for (int nf = 0; nf < 16; ++nf) {
        int col = nf * 8 + 2 * q;
        {
            float v0 = oacc[nf][0] * inv0, v1 = oacc[nf][1] * inv0;
            __nv_bfloat16 h0 = __float2bfloat16_rn(v0);
            __nv_bfloat16 h1 = __float2bfloat16_rn(v1);
            size_t off = (size_t)(b * S_ + r0) * DIM_ + h * HD_ + col;
            *(__nv_bfloat162*)(Oh + off) = __nv_bfloat162(h0, h1);
            *(__nv_bfloat162*)(Ol + off) = __nv_bfloat162(
                __float2bfloat16_rn(v0 - __bfloat162float(h0)),
                __float2bfloat16_rn(v1 - __bfloat162float(h1)));
        }
        {
            float v0 = oacc[nf][2] * inv1, v1 = oacc[nf][3] * inv1;
            __nv_bfloat16 h0 = __float2bfloat16_rn(v0);
            __nv_bfloat16 h1 = __float2bfloat16_rn(v1);
            size_t off = (size_t)(b * S_ + r0 + 8) * DIM_ + h * HD_ + col;
            *(__nv_bfloat162*)(Oh + off) = __nv_bfloat162(h0, h1);
            *(__nv_bfloat162*)(Ol + off) = __nv_bfloat162(
                __float2bfloat16_rn(v0 - __bfloat162float(h0)),
                __float2bfloat16_rn(v1 - __bfloat162float(h1)));
        }
    }
}

// ============================================================================
// launch
// ============================================================================
extern "C" void kernel_launch(void* const* d_in, const int* in_sizes, int n_in,
                              void* d_out, int out_size)
{
    const float* x  = (const float*)d_in[0];
    const float* wq = (const float*)d_in[1];
    const float* wk = (const float*)d_in[2];
    const float* wv = (const float*)d_in[3];
    const float* wo = (const float*)d_in[4];
    const float* fc = (const float*)d_in[5];
    const float* fs = (const float*)d_in[6];
    float* out = (float*)d_out;

    float* vp;
    cudaGetSymbolAddress((void**)&vp, g_v);
    __nv_bfloat16 *xh, *xl, *wqh, *wql, *wkh, *wkl, *wvh, *wvl, *woh, *wol, *ah, *al;
    __nv_bfloat16 *qsh, *qsl, *ksh, *ksl, *vth, *vtl;
    cudaGetSymbolAddress((void**)&xh, g_xh);   cudaGetSymbolAddress((void**)&xl, g_xl);
    cudaGetSymbolAddress((void**)&wqh, g_wqh); cudaGetSymbolAddress((void**)&wql, g_wql);
    cudaGetSymbolAddress((void**)&wkh, g_wkh); cudaGetSymbolAddress((void**)&wkl, g_wkl);
    cudaGetSymbolAddress((void**)&wvh, g_wvh); cudaGetSymbolAddress((void**)&wvl, g_wvl);
    cudaGetSymbolAddress((void**)&woh, g_woh); cudaGetSymbolAddress((void**)&wol, g_wol);
    cudaGetSymbolAddress((void**)&ah, g_ah);   cudaGetSymbolAddress((void**)&al, g_al);
    cudaGetSymbolAddress((void**)&qsh, g_qsh); cudaGetSymbolAddress((void**)&qsl, g_qsl);
    cudaGetSymbolAddress((void**)&ksh, g_ksh); cudaGetSymbolAddress((void**)&ksl, g_ksl);
    cudaGetSymbolAddress((void**)&vth, g_vth); cudaGetSymbolAddress((void**)&vtl, g_vtl);

    const int GEMM_SMEM = 2 * STAGE_B;   // 81920
    cudaFuncSetAttribute(gemm_mma, cudaFuncAttributeMaxDynamicSharedMemorySize,
                         GEMM_SMEM);
    cudaFuncSetAttribute(gemm_rope, cudaFuncAttributeMaxDynamicSharedMemorySize,
                         GEMM_SMEM);
    const int ATTN_SMEM = 2 * STG;       // 143360
    cudaFuncSetAttribute(attn_mma, cudaFuncAttributeMaxDynamicSharedMemorySize,
                         ATTN_SMEM);

    const int M = B_ * S_;               // 4096

    // operand prep
    split_kernel<<<((size_t)M * DIM_ / 4 + 255) / 256, 256>>>(x, xh, xl, M * DIM_ / 4);
    transpose_split<<<dim3(DIM_ / 32, DIM_ / 32), dim3(32, 8)>>>(wq, wqh, wql, DIM_, DIM_);
    transpose_split<<<dim3(NKV_ * HD_ / 32, DIM_ / 32), dim3(32, 8)>>>(wk, wkh, wkl, DIM_, NKV_ * HD_);
    transpose_split<<<dim3(NKV_ * HD_ / 32, DIM_ / 32), dim3(32, 8)>>>(wv, wvh, wvl, DIM_, NKV_ * HD_);
    transpose_split<<<dim3(DIM_ / 32, DIM_ / 32), dim3(32, 8)>>>(wo, woh, wol, DIM_, DIM_);

    // Q/K projections with fused RoPE+scale+split
    gemm_rope<<<dim3(DIM_ / 128, M / 128), 256, GEMM_SMEM>>>(
        xh, xl, wqh, wql, fc, fs, qsh, qsl, M, DIM_, DIM_, 0.08838834764831845f);
    gemm_rope<<<dim3(NKV_ * HD_ / 128, M / 128), 256, GEMM_SMEM>>>(
        xh, xl, wkh, wkl, fc, fs, ksh, ksl, M, NKV_ * HD_, DIM_, 1.0f);

    // V projection (fp32) + transpose/split
    gemm_mma<<<dim3(NKV_ * HD_ / 128, M / 128), 256, GEMM_SMEM>>>(
        xh, xl, wvh, wvl, vp, M, NKV_ * HD_, DIM_);
    transpose_v<<<dim3(S_ / 32, HD_ / 32, B_ * NKV_), dim3(32, 8)>>>(vp, vth, vtl);

    // attention (tensor cores, ldmatrix)
    attn_mma<<<dim3(S_ / 128, NH_, B_), 256, ATTN_SMEM>>>(
        qsh, qsl, ksh, ksl, vth, vtl, ah, al);

    // output projection
    gemm_mma<<<dim3(DIM_ / 128, M / 128), 256, GEMM_SMEM>>>(
        ah, al, woh, wol, out, M, DIM_, DIM_);
}

// round 10
// speedup vs baseline: 4.0493x; 1.3363x over previous
#include <cuda_runtime.h>
#include <cuda_fp16.h>
#include <cstdint>
#include <cstddef>

#define B_   2
#define S_   2048
#define DIM_ 4096
#define NH_  32
#define NKV_ 8
#define HD_  128

// ---------------- scratch (no allocations allowed) ----------------
__device__ float g_v[(size_t)B_ * S_ * NKV_ * HD_];    // fp32 V (pre-transpose)

__device__ __half g_xh[(size_t)B_ * S_ * DIM_];        // x in fp16 (hi only)
__device__ __half g_wqh[(size_t)DIM_ * DIM_];
__device__ __half g_wql[(size_t)DIM_ * DIM_];
__device__ __half g_wkh[(size_t)DIM_ * NKV_ * HD_];
__device__ __half g_wkl[(size_t)DIM_ * NKV_ * HD_];
__device__ __half g_wvh[(size_t)DIM_ * NKV_ * HD_];
__device__ __half g_wvl[(size_t)DIM_ * NKV_ * HD_];
__device__ __half g_woh[(size_t)DIM_ * DIM_];
__device__ __half g_wol[(size_t)DIM_ * DIM_];
__device__ __half g_ah[(size_t)B_ * S_ * DIM_];        // attention out (hi only)

__device__ __half g_qsh[(size_t)B_ * S_ * NH_ * HD_];  // post-rope Q hi/lo
__device__ __half g_qsl[(size_t)B_ * S_ * NH_ * HD_];
__device__ __half g_ksh[(size_t)B_ * S_ * NKV_ * HD_];
__device__ __half g_ksl[(size_t)B_ * S_ * NKV_ * HD_];
__device__ __half g_vth[(size_t)B_ * NKV_ * HD_ * S_]; // V^T [b][kv][d][s] hi/lo
__device__ __half g_vtl[(size_t)B_ * NKV_ * HD_ * S_];

// ============================ PTX helpers (sm_80-portable) ============================
__device__ __forceinline__ uint32_t smem_u32(const void* p) {
    uint32_t a;
    asm("{ .reg .u64 t; cvta.to.shared.u64 t, %1; cvt.u32.u64 %0, t; }"
        : "=r"(a) : "l"(p));
    return a;
}

__device__ __forceinline__ void cp16(uint32_t dst, const void* src) {
    asm volatile("cp.async.cg.shared.global [%0], [%1], 16;" :: "r"(dst), "l"(src));
}

__device__ __forceinline__ void ldmx4(uint32_t* r, uint32_t addr) {
    asm volatile("ldmatrix.sync.aligned.m8n8.x4.shared.b16 {%0,%1,%2,%3}, [%4];"
        : "=r"(r[0]), "=r"(r[1]), "=r"(r[2]), "=r"(r[3]) : "r"(addr));
}

#define CP_COMMIT() asm volatile("cp.async.commit_group;" ::: "memory")
#define CP_WAIT1()  asm volatile("cp.async.wait_group 1;"  ::: "memory")
#define CP_WAIT0()  asm volatile("cp.async.wait_group 0;"  ::: "memory")

#define MMA_F16(c, A, Bf)                                                         \
    asm volatile(                                                                 \
        "mma.sync.aligned.m16n8k16.row.col.f32.f16.f16.f32 "                      \
        "{%0,%1,%2,%3},{%4,%5,%6,%7},{%8,%9},{%0,%1,%2,%3};"                      \
        : "+f"((c)[0]), "+f"((c)[1]), "+f"((c)[2]), "+f"((c)[3])                  \
        : "r"((A)[0]), "r"((A)[1]), "r"((A)[2]), "r"((A)[3]),                     \
          "r"((Bf)[0]), "r"((Bf)[1]))

#define MMA_F16S(c, A, b0, b1)                                                    \
    asm volatile(                                                                 \
        "mma.sync.aligned.m16n8k16.row.col.f32.f16.f16.f32 "                      \
        "{%0,%1,%2,%3},{%4,%5,%6,%7},{%8,%9},{%0,%1,%2,%3};"                      \
        : "+f"((c)[0]), "+f"((c)[1]), "+f"((c)[2]), "+f"((c)[3])                  \
        : "r"((A)[0]), "r"((A)[1]), "r"((A)[2]), "r"((A)[3]),                     \
          "r"(b0), "r"(b1))

// ============================================================================
// GEMM mainloop: C fp32 = Ah @ (Bh+Bl)^T  (A fp16, B fp16 hi/lo, 2-pass)
// CTA 128x128, BK=32, 8 warps 2x4, ldmatrix, 2 CTAs/SM.
// smem: 2 stages x 3 tiles x 128 rows x 80B = 61440B.
// ============================================================================
#define TILE_B   10240
#define STAGE_B  (3 * TILE_B)

struct GemmCore {
    uint32_t sm0;
    int tid, lane, wid, wm, wn, q, rb;
    int row0, col0;
    const __half* src_[3];
    int r1, kc1, r2, kc2;
    int K;

    __device__ __forceinline__ void init(char* sm,
        const __half* Ah, const __half* Bh, const __half* Bl, int K_) {
        sm0 = smem_u32(sm);
        tid = threadIdx.x; lane = tid & 31; wid = tid >> 5;
        wm = wid >> 2; wn = wid & 3; q = lane & 3; rb = lane >> 2;
        row0 = blockIdx.y * 128; col0 = blockIdx.x * 128;
        K = K_;
        src_[0] = Ah + (size_t)row0 * K;
        src_[1] = Bh + (size_t)col0 * K;
        src_[2] = Bl + (size_t)col0 * K;
        r1 = tid >> 2; kc1 = tid & 3;
        r2 = (tid + 256) >> 2; kc2 = (tid + 256) & 3;
    }

    __device__ __forceinline__ void load_stage(int it, int s) {
        const uint32_t base = sm0 + s * STAGE_B;
        const int kel = it * 32;
#pragma unroll
        for (int t = 0; t < 3; ++t) {
            const __half* g = src_[t] + kel;
            cp16(base + t * TILE_B + r1 * 80 + kc1 * 16, g + (size_t)r1 * K + kc1 * 8);
            cp16(base + t * TILE_B + r2 * 80 + kc2 * 16, g + (size_t)r2 * K + kc2 * 8);
        }
        CP_COMMIT();
    }

    __device__ __forceinline__ void mainloop(float acc[4][4][4]) {
#pragma unroll
        for (int i = 0; i < 4; ++i)
#pragma unroll
            for (int j = 0; j < 4; ++j)
#pragma unroll
                for (int u = 0; u < 4; ++u) acc[i][j][u] = 0.f;

        const int KIT = K >> 5;
        load_stage(0, 0);

        const int a_row = lane & 15;
        const int a_off = (lane >> 4) * 16;
        const int b_row = (lane & 7) + (lane >> 4) * 8;
        const int b_off = ((lane >> 3) & 1) * 16;

        for (int it = 0; it < KIT; ++it) {
            if (it + 1 < KIT) { load_stage(it + 1, (it + 1) & 1); CP_WAIT1(); }
            else              { CP_WAIT0(); }
            __syncthreads();

            const uint32_t base = sm0 + (it & 1) * STAGE_B;
#pragma unroll
            for (int kk = 0; kk < 2; ++kk) {
                const int kb = kk * 32;
                uint32_t ah[4][4], bh[4][2], bl[4][2];
#pragma unroll
                for (int mf = 0; mf < 4; ++mf)
                    ldmx4(ah[mf], base + (wm * 64 + mf * 16 + a_row) * 80 + kb + a_off);
#pragma unroll
                for (int np = 0; np < 2; ++np) {
                    uint32_t rbq = base + TILE_B +
                                   (wn * 32 + np * 16 + b_row) * 80 + kb + b_off;
                    uint32_t t4[4];
                    ldmx4(t4, rbq);
                    bh[2*np][0] = t4[0]; bh[2*np][1] = t4[1];
                    bh[2*np+1][0] = t4[2]; bh[2*np+1][1] = t4[3];
                    ldmx4(t4, rbq + TILE_B);
                    bl[2*np][0] = t4[0]; bl[2*np][1] = t4[1];
                    bl[2*np+1][0] = t4[2]; bl[2*np+1][1] = t4[3];
                }
#pragma unroll
                for (int mf = 0; mf < 4; ++mf)
#pragma unroll
                    for (int nf = 0; nf < 4; ++nf) {
                        MMA_F16(acc[mf][nf], ah[mf], bh[nf]);
                        MMA_F16(acc[mf][nf], ah[mf], bl[nf]);
                    }
            }
            __syncthreads();
        }
    }
};

// ---- plain GEMM: fp32 output ----
__global__ __launch_bounds__(256, 2) void gemm_mma(
    const __half* __restrict__ Ah,
    const __half* __restrict__ Bh, const __half* __restrict__ Bl,
    float* __restrict__ C, int M, int N, int K)
{
    extern __shared__ __align__(16) char sm[];
    GemmCore gc; gc.init(sm, Ah, Bh, Bl, K);
    float acc[4][4][4];
    gc.mainloop(acc);
#pragma unroll
    for (int mf = 0; mf < 4; ++mf) {
        int row = gc.row0 + gc.wm * 64 + mf * 16 + gc.rb;
#pragma unroll
        for (int nf = 0; nf < 4; ++nf) {
            int col = gc.col0 + gc.wn * 32 + nf * 8 + gc.q * 2;
            *(float2*)(C + (size_t)row * N + col) =
                make_float2(acc[mf][nf][0], acc[mf][nf][1]);
            *(float2*)(C + (size_t)(row + 8) * N + col) =
                make_float2(acc[mf][nf][2], acc[mf][nf][3]);
        }
    }
}

// ---- GEMM + fused RoPE + scale + fp16 hi/lo split output ----
__global__ __launch_bounds__(256, 2) void gemm_rope(
    const __half* __restrict__ Ah,
    const __half* __restrict__ Bh, const __half* __restrict__ Bl,
    const float* __restrict__ cs, const float* __restrict__ sn,
    __half* __restrict__ Oh, __half* __restrict__ Ol,
    int M, int N, int K, float scale)
{
    extern __shared__ __align__(16) char sm[];
    GemmCore gc; gc.init(sm, Ah, Bh, Bl, K);
    float acc[4][4][4];
    gc.mainloop(acc);
#pragma unroll
    for (int mf = 0; mf < 4; ++mf) {
        int row = gc.row0 + gc.wm * 64 + mf * 16 + gc.rb;
        int s0 = row & (S_ - 1);
#pragma unroll
        for (int nf = 0; nf < 4; ++nf) {
            int col = gc.col0 + gc.wn * 32 + nf * 8 + gc.q * 2;
            int p = (col & (HD_ - 1)) >> 1;
#pragma unroll
            for (int half = 0; half < 2; ++half) {
                int s = s0 + half * 8;
                float c = cs[(s << 6) + p];
                float si = sn[(s << 6) + p];
                float xr = acc[mf][nf][2 * half];
                float xi = acc[mf][nf][2 * half + 1];
                float o0 = fmaf(xr, c, -xi * si) * scale;
                float o1 = fmaf(xr, si,  xi * c) * scale;
                __half h0 = __float2half_rn(o0);
                __half h1 = __float2half_rn(o1);
                size_t off = (size_t)(row + half * 8) * N + col;
                *(__half2*)(Oh + off) = __halves2half2(h0, h1);
                *(__half2*)(Ol + off) = __halves2half2(
                    __float2half_rn(o0 - __half2float(h0)),
                    __float2half_rn(o1 - __half2float(h1)));
            }
        }
    }
}

// ============================================================================
// fp32 -> fp16 (hi only)
// ============================================================================
__global__ __launch_bounds__(256) void split_h(const float* __restrict__ in,
                                               __half* __restrict__ h, int n4)
{
    int i = blockIdx.x * blockDim.x + threadIdx.x;
    if (i >= n4) return;
    float4 v = ((const float4*)in)[i];
    ((__half2*)h)[2 * i + 0] = __floats2half2_rn(v.x, v.y);
    ((__half2*)h)[2 * i + 1] = __floats2half2_rn(v.z, v.w);
}

// ============================================================================
// w[K,N] fp32 -> wT hi/lo fp16 [N,K]
// ============================================================================
__global__ __launch_bounds__(256) void transpose_split(const float* __restrict__ w,
                                                       __half* __restrict__ th,
                                                       __half* __restrict__ tl,
                                                       int K, int N)
{
    __shared__ float s[32][33];
    int n0 = blockIdx.x * 32, k0 = blockIdx.y * 32;
    int tx = threadIdx.x, ty = threadIdx.y;
#pragma unroll
    for (int i = ty; i < 32; i += 8)
        s[i][tx] = w[(size_t)(k0 + i) * N + n0 + tx];
    __syncthreads();
#pragma unroll
    for (int i = ty; i < 32; i += 8) {
        float v = s[tx][i];
        __half hi = __float2half_rn(v);
        size_t o = (size_t)(n0 + i) * K + k0 + tx;
        th[o] = hi;
        tl[o] = __float2half_rn(v - __half2float(hi));
    }
}

// ============================================================================
// V fp32 [b][s][kv][d] -> V^T fp16 hi/lo [b][kv][d][s]
// ============================================================================
__global__ __launch_bounds__(256) void transpose_v(const float* __restrict__ v,
                                                   __half* __restrict__ th,
                                                   __half* __restrict__ tl)
{
    __shared__ float s[32][33];
    int s0 = blockIdx.x * 32, d0 = blockIdx.y * 32;
    int b = blockIdx.z / NKV_, kv = blockIdx.z % NKV_;
    int tx = threadIdx.x, ty = threadIdx.y;
#pragma unroll
    for (int i = ty; i < 32; i += 8)
        s[i][tx] = v[(((size_t)(b * S_ + s0 + i) * NKV_) + kv) * HD_ + d0 + tx];
    __syncthreads();
#pragma unroll
    for (int i = ty; i < 32; i += 8) {
        float val = s[tx][i];
        __half hi = __float2half_rn(val);
        size_t o = ((size_t)(b * NKV_ + kv) * HD_ + d0 + i) * S_ + s0 + tx;
        th[o] = hi;
        tl[o] = __float2half_rn(val - __half2float(hi));
    }
}

// ============================================================================
// Tensor-core flash attention (fp16, 3-pass QK and PV, ldmatrix).
// ============================================================================
#define AK       64
#define NKB      (S_ / AK)
#define KSTRIDE  272
#define VSTRIDE  144
#define OFF_KL   17408
#define OFF_VH   34816
#define OFF_VL   53248
#define STG      71680

__global__ __launch_bounds__(256, 1) void attn_mma(
    const __half* __restrict__ Qh, const __half* __restrict__ Ql,
    const __half* __restrict__ Kh, const __half* __restrict__ Kl,
    const __half* __restrict__ Vh, const __half* __restrict__ Vl,
    __half* __restrict__ Oh)
{
    extern __shared__ __align__(16) char sm[];
    const uint32_t sm0 = smem_u32(sm);
    const int tid = threadIdx.x, lane = tid & 31, w = tid >> 5;
    const int g = lane >> 2, q = lane & 3;
    const int q0 = blockIdx.x * 128;
    const int h = blockIdx.y, b = blockIdx.z;
    const int kvh = h >> 2;

    const int rowlane = lane & 7;
    const int part = lane >> 3;
    const int poff16 = (part & 1) * 16;
    const int plo = part >> 1;

    // ---- stage Q through smem, build register fragments ----
    uint32_t fqh[8][4], fql[8][4];
    {
        const __half* srcs[2] = { Qh, Ql };
#pragma unroll
        for (int rep = 0; rep < 2; ++rep) {
#pragma unroll
            for (int i = 0; i < 8; ++i) {
                int c = tid + i * 256;
                int r = c >> 4, cc = c & 15;
                cp16(sm0 + r * KSTRIDE + cc * 16,
                     srcs[rep] + ((size_t)((b * S_ + q0 + r) * NH_) + h) * HD_ + cc * 8);
            }
            CP_COMMIT(); CP_WAIT0();
            __syncthreads();
            uint32_t base = sm0 + (w * 16 + (lane & 15)) * KSTRIDE + (lane >> 4) * 16;
#pragma unroll
            for (int t = 0; t < 8; ++t)
                ldmx4(rep ? fql[t] : fqh[t], base + t * 32);
            __syncthreads();
        }
    }

    auto prefetch = [&](int kb, int s) {
        uint32_t st = sm0 + s * STG;
#pragma unroll
        for (int i = 0; i < 4; ++i) {
            int c = tid + i * 256;
            int r = c >> 4, cc = c & 15;
            size_t go = ((size_t)((b * S_ + kb * AK + r) * NKV_) + kvh) * HD_ + cc * 8;
            cp16(st + r * KSTRIDE + cc * 16, Kh + go);
            cp16(st + OFF_KL + r * KSTRIDE + cc * 16, Kl + go);
        }
#pragma unroll
        for (int i = 0; i < 4; ++i) {
            int c = tid + i * 256;
            int d = c >> 3, cc = c & 7;
            size_t go = ((size_t)(b * NKV_ + kvh) * HD_ + d) * S_ + kb * AK + cc * 8;
            cp16(st + OFF_VH + d * VSTRIDE + cc * 16, Vh + go);
            cp16(st + OFF_VL + d * VSTRIDE + cc * 16, Vl + go);
        }
        CP_COMMIT();
    };

    float oacc[16][4];
#pragma unroll
    for (int i = 0; i < 16; ++i)
#pragma unroll
        for (int u = 0; u < 4; ++u) oacc[i][u] = 0.f;
    float m0 = -1e30f, m1 = -1e30f, l0 = 0.f, l1 = 0.f;

    prefetch(0, 0);

    for (int kb = 0; kb < NKB; ++kb) {
        const int s = kb & 1;
        if (kb + 1 < NKB) { prefetch(kb + 1, s ^ 1); CP_WAIT1(); }
        else              { CP_WAIT0(); }
        __syncthreads();

        const uint32_t st = sm0 + s * STG;

        // ---- S = Q K^T (3-pass split) ----
        float sacc[8][4];
#pragma unroll
        for (int n = 0; n < 8; ++n)
#pragma unroll
            for (int u = 0; u < 4; ++u) sacc[n][u] = 0.f;

#pragma unroll
        for (int t = 0; t < 8; ++t) {
#pragma unroll
            for (int n = 0; n < 8; ++n) {
                uint32_t r4[4];
                ldmx4(r4, st + (n * 8 + rowlane) * KSTRIDE + t * 32 + poff16 +
                          plo * OFF_KL);
                MMA_F16S(sacc[n], fqh[t], r4[0], r4[1]);
                MMA_F16S(sacc[n], fqh[t], r4[2], r4[3]);
                MMA_F16S(sacc[n], fql[t], r4[0], r4[1]);
            }
        }

        // ---- online softmax ----
        float rmax0 = -1e30f, rmax1 = -1e30f;
#pragma unroll
        for (int n = 0; n < 8; ++n) {
            rmax0 = fmaxf(rmax0, fmaxf(sacc[n][0], sacc[n][1]));
            rmax1 = fmaxf(rmax1, fmaxf(sacc[n][2], sacc[n][3]));
        }
        rmax0 = fmaxf(rmax0, __shfl_xor_sync(0xffffffffu, rmax0, 1));
        rmax0 = fmaxf(rmax0, __shfl_xor_sync(0xffffffffu, rmax0, 2));
        rmax1 = fmaxf(rmax1, __shfl_xor_sync(0xffffffffu, rmax1, 1));
        rmax1 = fmaxf(rmax1, __shfl_xor_sync(0xffffffffu, rmax1, 2));

        float nm0 = fmaxf(m0, rmax0), nm1 = fmaxf(m1, rmax1);
        float f0 = __expf(m0 - nm0),  f1 = __expf(m1 - nm1);
        m0 = nm0; m1 = nm1;

        float sum0 = 0.f, sum1 = 0.f;
#pragma unroll
        for (int n = 0; n < 8; ++n) {
            float p0 = __expf(sacc[n][0] - nm0);
            float p1 = __expf(sacc[n][1] - nm0);
            float p2 = __expf(sacc[n][2] - nm1);
            float p3 = __expf(sacc[n][3] - nm1);
            sum0 += p0 + p1; sum1 += p2 + p3;
            sacc[n][0] = p0; sacc[n][1] = p1; sacc[n][2] = p2; sacc[n][3] = p3;
        }
        sum0 += __shfl_xor_sync(0xffffffffu, sum0, 1);
        sum0 += __shfl_xor_sync(0xffffffffu, sum0, 2);
        sum1 += __shfl_xor_sync(0xffffffffu, sum1, 1);
        sum1 += __shfl_xor_sync(0xffffffffu, sum1, 2);
        l0 = l0 * f0 + sum0;
        l1 = l1 * f1 + sum1;

        // P -> hi/lo A fragments (register repack)
        uint32_t pah[4][4], pal[4][4];
#pragma unroll
        for (int t = 0; t < 4; ++t) {
#pragma unroll
            for (int hw = 0; hw < 2; ++hw) {
                const float* pv = sacc[2 * t + hw];
#pragma unroll
                for (int uu = 0; uu < 2; ++uu) {
                    float v0 = pv[2 * uu], v1 = pv[2 * uu + 1];
                    __half hh0 = __float2half_rn(v0);
                    __half hh1 = __float2half_rn(v1);
                    __half2 hp = __halves2half2(hh0, hh1);
                    __half2 lp = __halves2half2(
                        __float2half_rn(v0 - __half2float(hh0)),
                        __float2half_rn(v1 - __half2float(hh1)));
                    pah[t][hw * 2 + uu] = *(uint32_t*)&hp;
                    pal[t][hw * 2 + uu] = *(uint32_t*)&lp;
                }
            }
        }

#pragma unroll
        for (int nf = 0; nf < 16; ++nf) {
            oacc[nf][0] *= f0; oacc[nf][1] *= f0;
            oacc[nf][2] *= f1; oacc[nf][3] *= f1;
        }

        // ---- O += Ph*(Vh+Vl) + Pl*Vh ----
#pragma unroll
        for (int t = 0; t < 4; ++t) {
#pragma unroll
            for (int nf = 0; nf < 16; ++nf) {
                uint32_t r4[4];
                ldmx4(r4, st + OFF_VH + (nf * 8 + rowlane) * VSTRIDE + t * 32 +
                          poff16 + plo * (OFF_VL - OFF_VH));
                MMA_F16S(oacc[nf], pah[t], r4[0], r4[1]);
                MMA_F16S(oacc[nf], pah[t], r4[2], r4[3]);
                MMA_F16S(oacc[nf], pal[t], r4[0], r4[1]);
            }
        }
        __syncthreads();
    }

    // ---- epilogue: normalize, store fp16 hi only ----
    float inv0 = 1.0f / l0, inv1 = 1.0f / l1;
    int r0 = q0 + w * 16 + g;
#pragma unroll
    for (int nf = 0; nf < 16; ++nf) {
        int col = nf * 8 + 2 * q;
        {
            size_t off = (size_t)(b * S_ + r0) * DIM_ + h * HD_ + col;
            *(__half2*)(Oh + off) =
                __floats2half2_rn(oacc[nf][0] * inv0, oacc[nf][1] * inv0);
        }
        {
            size_t off = (size_t)(b * S_ + r0 + 8) * DIM_ + h * HD_ + col;
            *(__half2*)(Oh + off) =
                __floats2half2_rn(oacc[nf][2] * inv1, oacc[nf][3] * inv1);
        }
    }
}

// ============================================================================
// launch
// ============================================================================
extern "C" void kernel_launch(void* const* d_in, const int* in_sizes, int n_in,
                              void* d_out, int out_size)
{
    const float* x  = (const float*)d_in[0];
    const float* wq = (const float*)d_in[1];
    const float* wk = (const float*)d_in[2];
    const float* wv = (const float*)d_in[3];
    const float* wo = (const float*)d_in[4];
    const float* fc = (const float*)d_in[5];
    const float* fs = (const float*)d_in[6];
    float* out = (float*)d_out;

    float* vp;
    cudaGetSymbolAddress((void**)&vp, g_v);
    __half *xh, *wqh, *wql, *wkh, *wkl, *wvh, *wvl, *woh, *wol, *ah;
    __half *qsh, *qsl, *ksh, *ksl, *vth, *vtl;
    cudaGetSymbolAddress((void**)&xh, g_xh);
    cudaGetSymbolAddress((void**)&wqh, g_wqh); cudaGetSymbolAddress((void**)&wql, g_wql);
    cudaGetSymbolAddress((void**)&wkh, g_wkh); cudaGetSymbolAddress((void**)&wkl, g_wkl);
    cudaGetSymbolAddress((void**)&wvh, g_wvh); cudaGetSymbolAddress((void**)&wvl, g_wvl);
    cudaGetSymbolAddress((void**)&woh, g_woh); cudaGetSymbolAddress((void**)&wol, g_wol);
    cudaGetSymbolAddress((void**)&ah, g_ah);
    cudaGetSymbolAddress((void**)&qsh, g_qsh); cudaGetSymbolAddress((void**)&qsl, g_qsl);
    cudaGetSymbolAddress((void**)&ksh, g_ksh); cudaGetSymbolAddress((void**)&ksl, g_ksl);
    cudaGetSymbolAddress((void**)&vth, g_vth); cudaGetSymbolAddress((void**)&vtl, g_vtl);

    const int GEMM_SMEM = 2 * STAGE_B;   // 61440
    cudaFuncSetAttribute(gemm_mma, cudaFuncAttributeMaxDynamicSharedMemorySize,
                         GEMM_SMEM);
    cudaFuncSetAttribute(gemm_rope, cudaFuncAttributeMaxDynamicSharedMemorySize,
                         GEMM_SMEM);
    const int ATTN_SMEM = 2 * STG;       // 143360
    cudaFuncSetAttribute(attn_mma, cudaFuncAttributeMaxDynamicSharedMemorySize,
                         ATTN_SMEM);

    const int M = B_ * S_;               // 4096

    // operand prep
    split_h<<<((size_t)M * DIM_ / 4 + 255) / 256, 256>>>(x, xh, M * DIM_ / 4);
    transpose_split<<<dim3(DIM_ / 32, DIM_ / 32), dim3(32, 8)>>>(wq, wqh, wql, DIM_, DIM_);
    transpose_split<<<dim3(NKV_ * HD_ / 32, DIM_ / 32), dim3(32, 8)>>>(wk, wkh, wkl, DIM_, NKV_ * HD_);
    transpose_split<<<dim3(NKV_ * HD_ / 32, DIM_ / 32), dim3(32, 8)>>>(wv, wvh, wvl, DIM_, NKV_ * HD_);
    transpose_split<<<dim3(DIM_ / 32, DIM_ / 32), dim3(32, 8)>>>(wo, woh, wol, DIM_, DIM_);

    // Q/K projections with fused RoPE+scale+split
    gemm_rope<<<dim3(DIM_ / 128, M / 128), 256, GEMM_SMEM>>>(
        xh, wqh, wql, fc, fs, qsh, qsl, M, DIM_, DIM_, 0.08838834764831845f);
    gemm_rope<<<dim3(NKV_ * HD_ / 128, M / 128), 256, GEMM_SMEM>>>(
        xh, wkh, wkl, fc, fs, ksh, ksl, M, NKV_ * HD_, DIM_, 1.0f);

    // V projection (fp32) + transpose/split
    gemm_mma<<<dim3(NKV_ * HD_ / 128, M / 128), 256, GEMM_SMEM>>>(
        xh, wvh, wvl, vp, M, NKV_ * HD_, DIM_);
    transpose_v<<<dim3(S_ / 32, HD_ / 32, B_ * NKV_), dim3(32, 8)>>>(vp, vth, vtl);

    // attention
    attn_mma<<<dim3(S_ / 128, NH_, B_), 256, ATTN_SMEM>>>(
        qsh, qsl, ksh, ksl, vth, vtl, ah);

    // output projection
    gemm_mma<<<dim3(DIM_ / 128, M / 128), 256, GEMM_SMEM>>>(
        ah, woh, wol, out, M, DIM_, DIM_);
}

// round 11
// speedup vs baseline: 4.2379x; 1.0466x over previous
#include <cuda_runtime.h>
#include <cuda_fp16.h>
#include <cstdint>
#include <cstddef>

#define B_   2
#define S_   2048
#define DIM_ 4096
#define NH_  32
#define NKV_ 8
#define HD_  128

// ---------------- scratch (no allocations allowed) ----------------
__device__ float g_v[(size_t)B_ * S_ * NKV_ * HD_];    // fp32 V (pre-transpose)

__device__ __half g_xh[(size_t)B_ * S_ * DIM_];        // x in fp16 (hi only)
__device__ __half g_wqh[(size_t)DIM_ * DIM_];
__device__ __half g_wql[(size_t)DIM_ * DIM_];
__device__ __half g_wkh[(size_t)DIM_ * NKV_ * HD_];
__device__ __half g_wkl[(size_t)DIM_ * NKV_ * HD_];
__device__ __half g_wvh[(size_t)DIM_ * NKV_ * HD_];
__device__ __half g_wvl[(size_t)DIM_ * NKV_ * HD_];
__device__ __half g_woh[(size_t)DIM_ * DIM_];
__device__ __half g_wol[(size_t)DIM_ * DIM_];
__device__ __half g_ah[(size_t)B_ * S_ * DIM_];        // attention out (hi only)

__device__ __half g_qsh[(size_t)B_ * S_ * NH_ * HD_];  // post-rope Q hi/lo
__device__ __half g_qsl[(size_t)B_ * S_ * NH_ * HD_];
__device__ __half g_ksh[(size_t)B_ * S_ * NKV_ * HD_];
__device__ __half g_ksl[(size_t)B_ * S_ * NKV_ * HD_];
__device__ __half g_vth[(size_t)B_ * NKV_ * HD_ * S_]; // V^T [b][kv][d][s] hi/lo
__device__ __half g_vtl[(size_t)B_ * NKV_ * HD_ * S_];

// ============================ PTX helpers (sm_80-portable) ============================
__device__ __forceinline__ uint32_t smem_u32(const void* p) {
    uint32_t a;
    asm("{ .reg .u64 t; cvta.to.shared.u64 t, %1; cvt.u32.u64 %0, t; }"
        : "=r"(a) : "l"(p));
    return a;
}

__device__ __forceinline__ void cp16(uint32_t dst, const void* src) {
    asm volatile("cp.async.cg.shared.global [%0], [%1], 16;" :: "r"(dst), "l"(src));
}

__device__ __forceinline__ void ldmx4(uint32_t* r, uint32_t addr) {
    asm volatile("ldmatrix.sync.aligned.m8n8.x4.shared.b16 {%0,%1,%2,%3}, [%4];"
        : "=r"(r[0]), "=r"(r[1]), "=r"(r[2]), "=r"(r[3]) : "r"(addr));
}

#define CP_COMMIT() asm volatile("cp.async.commit_group;" ::: "memory")
#define CP_WAIT1()  asm volatile("cp.async.wait_group 1;"  ::: "memory")
#define CP_WAIT0()  asm volatile("cp.async.wait_group 0;"  ::: "memory")

#define MMA_F16(c, A, Bf)                                                         \
    asm volatile(                                                                 \
        "mma.sync.aligned.m16n8k16.row.col.f32.f16.f16.f32 "                      \
        "{%0,%1,%2,%3},{%4,%5,%6,%7},{%8,%9},{%0,%1,%2,%3};"                      \
        : "+f"((c)[0]), "+f"((c)[1]), "+f"((c)[2]), "+f"((c)[3])                  \
        : "r"((A)[0]), "r"((A)[1]), "r"((A)[2]), "r"((A)[3]),                     \
          "r"((Bf)[0]), "r"((Bf)[1]))

#define MMA_F16S(c, A, b0, b1)                                                    \
    asm volatile(                                                                 \
        "mma.sync.aligned.m16n8k16.row.col.f32.f16.f16.f32 "                      \
        "{%0,%1,%2,%3},{%4,%5,%6,%7},{%8,%9},{%0,%1,%2,%3};"                      \
        : "+f"((c)[0]), "+f"((c)[1]), "+f"((c)[2]), "+f"((c)[3])                  \
        : "r"((A)[0]), "r"((A)[1]), "r"((A)[2]), "r"((A)[3]),                     \
          "r"(b0), "r"(b1))

// ============================================================================
// GEMM mainloop: C fp32 = Ah @ (Bh+Bl)^T  (A fp16, B fp16 hi/lo, 2-pass)
// CTA 128x128, BK=64, 8 warps 2x4, ldmatrix, 2 CTAs/SM.
// smem: 2 stages x 3 tiles x 128 rows x 144B = 110592B.
// ============================================================================
#define TILE_B   18432          // 128 x 144
#define STAGE_B  (3 * TILE_B)   // 55296

struct GemmCore {
    uint32_t sm0;
    int tid, lane, wid, wm, wn, q, rb;
    int row0, col0;
    const __half* src_[3];
    int K;

    __device__ __forceinline__ void init(char* sm,
        const __half* Ah, const __half* Bh, const __half* Bl, int K_) {
        sm0 = smem_u32(sm);
        tid = threadIdx.x; lane = tid & 31; wid = tid >> 5;
        wm = wid >> 2; wn = wid & 3; q = lane & 3; rb = lane >> 2;
        row0 = blockIdx.y * 128; col0 = blockIdx.x * 128;
        K = K_;
        src_[0] = Ah + (size_t)row0 * K;
        src_[1] = Bh + (size_t)col0 * K;
        src_[2] = Bl + (size_t)col0 * K;
    }

    __device__ __forceinline__ void load_stage(int it, int s) {
        const uint32_t base = sm0 + s * STAGE_B;
        const int kel = it * 64;
#pragma unroll
        for (int t = 0; t < 3; ++t) {
            const __half* g = src_[t] + kel;
#pragma unroll
            for (int i = 0; i < 4; ++i) {
                int idx = tid + i * 256;
                int r = idx >> 3, kc = idx & 7;
                cp16(base + t * TILE_B + r * 144 + kc * 16,
                     g + (size_t)r * K + kc * 8);
            }
        }
        CP_COMMIT();
    }

    __device__ __forceinline__ void mainloop(float acc[4][4][4]) {
#pragma unroll
        for (int i = 0; i < 4; ++i)
#pragma unroll
            for (int j = 0; j < 4; ++j)
#pragma unroll
                for (int u = 0; u < 4; ++u) acc[i][j][u] = 0.f;

        const int KIT = K >> 6;
        load_stage(0, 0);

        const int a_row = lane & 15;
        const int a_off = (lane >> 4) * 16;
        const int b_row = (lane & 7) + (lane >> 4) * 8;
        const int b_off = ((lane >> 3) & 1) * 16;

        for (int it = 0; it < KIT; ++it) {
            if (it + 1 < KIT) { load_stage(it + 1, (it + 1) & 1); CP_WAIT1(); }
            else              { CP_WAIT0(); }
            __syncthreads();

            const uint32_t base = sm0 + (it & 1) * STAGE_B;
#pragma unroll
            for (int kk = 0; kk < 4; ++kk) {
                const int kb = kk * 32;
                uint32_t ah[4][4], bh[4][2], bl[4][2];
#pragma unroll
                for (int mf = 0; mf < 4; ++mf)
                    ldmx4(ah[mf], base + (wm * 64 + mf * 16 + a_row) * 144 + kb + a_off);
#pragma unroll
                for (int np = 0; np < 2; ++np) {
                    uint32_t rbq = base + TILE_B +
                                   (wn * 32 + np * 16 + b_row) * 144 + kb + b_off;
                    uint32_t t4[4];
                    ldmx4(t4, rbq);
                    bh[2*np][0] = t4[0]; bh[2*np][1] = t4[1];
                    bh[2*np+1][0] = t4[2]; bh[2*np+1][1] = t4[3];
                    ldmx4(t4, rbq + TILE_B);
                    bl[2*np][0] = t4[0]; bl[2*np][1] = t4[1];
                    bl[2*np+1][0] = t4[2]; bl[2*np+1][1] = t4[3];
                }
#pragma unroll
                for (int mf = 0; mf < 4; ++mf)
#pragma unroll
                    for (int nf = 0; nf < 4; ++nf) {
                        MMA_F16(acc[mf][nf], ah[mf], bh[nf]);
                        MMA_F16(acc[mf][nf], ah[mf], bl[nf]);
                    }
            }
            __syncthreads();
        }
    }
};

// ---- plain GEMM: fp32 output ----
__global__ __launch_bounds__(256, 2) void gemm_mma(
    const __half* __restrict__ Ah,
    const __half* __restrict__ Bh, const __half* __restrict__ Bl,
    float* __restrict__ C, int M, int N, int K)
{
    extern __shared__ __align__(16) char sm[];
    GemmCore gc; gc.init(sm, Ah, Bh, Bl, K);
    float acc[4][4][4];
    gc.mainloop(acc);
#pragma unroll
    for (int mf = 0; mf < 4; ++mf) {
        int row = gc.row0 + gc.wm * 64 + mf * 16 + gc.rb;
#pragma unroll
        for (int nf = 0; nf < 4; ++nf) {
            int col = gc.col0 + gc.wn * 32 + nf * 8 + gc.q * 2;
            *(float2*)(C + (size_t)row * N + col) =
                make_float2(acc[mf][nf][0], acc[mf][nf][1]);
            *(float2*)(C + (size_t)(row + 8) * N + col) =
                make_float2(acc[mf][nf][2], acc[mf][nf][3]);
        }
    }
}

// ---- GEMM + fused RoPE + scale + fp16 hi/lo split output ----
__global__ __launch_bounds__(256, 2) void gemm_rope(
    const __half* __restrict__ Ah,
    const __half* __restrict__ Bh, const __half* __restrict__ Bl,
    const float* __restrict__ cs, const float* __restrict__ sn,
    __half* __restrict__ Oh, __half* __restrict__ Ol,
    int M, int N, int K, float scale)
{
    extern __shared__ __align__(16) char sm[];
    GemmCore gc; gc.init(sm, Ah, Bh, Bl, K);
    float acc[4][4][4];
    gc.mainloop(acc);
#pragma unroll
    for (int mf = 0; mf < 4; ++mf) {
        int row = gc.row0 + gc.wm * 64 + mf * 16 + gc.rb;
        int s0 = row & (S_ - 1);
#pragma unroll
        for (int nf = 0; nf < 4; ++nf) {
            int col = gc.col0 + gc.wn * 32 + nf * 8 + gc.q * 2;
            int p = (col & (HD_ - 1)) >> 1;
#pragma unroll
            for (int half = 0; half < 2; ++half) {
                int s = s0 + half * 8;
                float c = cs[(s << 6) + p];
                float si = sn[(s << 6) + p];
                float xr = acc[mf][nf][2 * half];
                float xi = acc[mf][nf][2 * half + 1];
                float o0 = fmaf(xr, c, -xi * si) * scale;
                float o1 = fmaf(xr, si,  xi * c) * scale;
                __half h0 = __float2half_rn(o0);
                __half h1 = __float2half_rn(o1);
                size_t off = (size_t)(row + half * 8) * N + col;
                *(__half2*)(Oh + off) = __halves2half2(h0, h1);
                *(__half2*)(Ol + off) = __halves2half2(
                    __float2half_rn(o0 - __half2float(h0)),
                    __float2half_rn(o1 - __half2float(h1)));
            }
        }
    }
}

// ============================================================================
// Fused prep: z=0..3 transpose+split the 4 weight matrices, z=4 x->fp16.
// grid (128,128,5), block (32,8).
// ============================================================================
__global__ __launch_bounds__(256) void prep_all(
    const float* __restrict__ x,
    const float* __restrict__ wq, const float* __restrict__ wk,
    const float* __restrict__ wv, const float* __restrict__ wo,
    __half* __restrict__ xh,
    __half* __restrict__ wqh, __half* __restrict__ wql,
    __half* __restrict__ wkh, __half* __restrict__ wkl,
    __half* __restrict__ wvh, __half* __restrict__ wvl,
    __half* __restrict__ woh, __half* __restrict__ wol)
{
    const int z = blockIdx.z;
    const int tx = threadIdx.x, ty = threadIdx.y;

    if (z == 4) {
        // x fp32 -> fp16, float4-vectorized
        int i = (blockIdx.y * 128 + blockIdx.x) * 256 + ty * 32 + tx;
        float4 v = ((const float4*)x)[i];
        ((__half2*)xh)[2 * i + 0] = __floats2half2_rn(v.x, v.y);
        ((__half2*)xh)[2 * i + 1] = __floats2half2_rn(v.z, v.w);
        return;
    }

    const float* w; __half* th; __half* tl; int N;
    switch (z) {
        case 0: w = wq; th = wqh; tl = wql; N = DIM_; break;
        case 1: w = wk; th = wkh; tl = wkl; N = NKV_ * HD_; break;
        case 2: w = wv; th = wvh; tl = wvl; N = NKV_ * HD_; break;
        default: w = wo; th = woh; tl = wol; N = DIM_; break;
    }
    const int K = DIM_;
    int n0 = blockIdx.x * 32, k0 = blockIdx.y * 32;
    if (n0 >= N) return;

    __shared__ float s[32][33];
#pragma unroll
    for (int i = ty; i < 32; i += 8)
        s[i][tx] = w[(size_t)(k0 + i) * N + n0 + tx];
    __syncthreads();
#pragma unroll
    for (int i = ty; i < 32; i += 8) {
        float v = s[tx][i];
        __half hi = __float2half_rn(v);
        size_t o = (size_t)(n0 + i) * K + k0 + tx;
        th[o] = hi;
        tl[o] = __float2half_rn(v - __half2float(hi));
    }
}

// ============================================================================
// V fp32 [b][s][kv][d] -> V^T fp16 hi/lo [b][kv][d][s]
// ============================================================================
__global__ __launch_bounds__(256) void transpose_v(const float* __restrict__ v,
                                                   __half* __restrict__ th,
                                                   __half* __restrict__ tl)
{
    __shared__ float s[32][33];
    int s0 = blockIdx.x * 32, d0 = blockIdx.y * 32;
    int b = blockIdx.z / NKV_, kv = blockIdx.z % NKV_;
    int tx = threadIdx.x, ty = threadIdx.y;
#pragma unroll
    for (int i = ty; i < 32; i += 8)
        s[i][tx] = v[(((size_t)(b * S_ + s0 + i) * NKV_) + kv) * HD_ + d0 + tx];
    __syncthreads();
#pragma unroll
    for (int i = ty; i < 32; i += 8) {
        float val = s[tx][i];
        __half hi = __float2half_rn(val);
        size_t o = ((size_t)(b * NKV_ + kv) * HD_ + d0 + i) * S_ + s0 + tx;
        th[o] = hi;
        tl[o] = __float2half_rn(val - __half2float(hi));
    }
}

// ============================================================================
// Tensor-core flash attention (fp16, 3-pass QK and PV, ldmatrix).
// ============================================================================
#define AK       64
#define NKB      (S_ / AK)
#define KSTRIDE  272
#define VSTRIDE  144
#define OFF_KL   17408
#define OFF_VH   34816
#define OFF_VL   53248
#define STG      71680

__global__ __launch_bounds__(256, 1) void attn_mma(
    const __half* __restrict__ Qh, const __half* __restrict__ Ql,
    const __half* __restrict__ Kh, const __half* __restrict__ Kl,
    const __half* __restrict__ Vh, const __half* __restrict__ Vl,
    __half* __restrict__ Oh)
{
    extern __shared__ __align__(16) char sm[];
    const uint32_t sm0 = smem_u32(sm);
    const int tid = threadIdx.x, lane = tid & 31, w = tid >> 5;
    const int g = lane >> 2, q = lane & 3;
    const int q0 = blockIdx.x * 128;
    const int h = blockIdx.y, b = blockIdx.z;
    const int kvh = h >> 2;

    const int rowlane = lane & 7;
    const int part = lane >> 3;
    const int poff16 = (part & 1) * 16;
    const int plo = part >> 1;

    // ---- stage Q through smem, build register fragments ----
    uint32_t fqh[8][4], fql[8][4];
    {
        const __half* srcs[2] = { Qh, Ql };
#pragma unroll
        for (int rep = 0; rep < 2; ++rep) {
#pragma unroll
            for (int i = 0; i < 8; ++i) {
                int c = tid + i * 256;
                int r = c >> 4, cc = c & 15;
                cp16(sm0 + r * KSTRIDE + cc * 16,
                     srcs[rep] + ((size_t)((b * S_ + q0 + r) * NH_) + h) * HD_ + cc * 8);
            }
            CP_COMMIT(); CP_WAIT0();
            __syncthreads();
            uint32_t base = sm0 + (w * 16 + (lane & 15)) * KSTRIDE + (lane >> 4) * 16;
#pragma unroll
            for (int t = 0; t < 8; ++t)
                ldmx4(rep ? fql[t] : fqh[t], base + t * 32);
            __syncthreads();
        }
    }

    auto prefetch = [&](int kb, int s) {
        uint32_t st = sm0 + s * STG;
#pragma unroll
        for (int i = 0; i < 4; ++i) {
            int c = tid + i * 256;
            int r = c >> 4, cc = c & 15;
            size_t go = ((size_t)((b * S_ + kb * AK + r) * NKV_) + kvh) * HD_ + cc * 8;
            cp16(st + r * KSTRIDE + cc * 16, Kh + go);
            cp16(st + OFF_KL + r * KSTRIDE + cc * 16, Kl + go);
        }
#pragma unroll
        for (int i = 0; i < 4; ++i) {
            int c = tid + i * 256;
            int d = c >> 3, cc = c & 7;
            size_t go = ((size_t)(b * NKV_ + kvh) * HD_ + d) * S_ + kb * AK + cc * 8;
            cp16(st + OFF_VH + d * VSTRIDE + cc * 16, Vh + go);
            cp16(st + OFF_VL + d * VSTRIDE + cc * 16, Vl + go);
        }
        CP_COMMIT();
    };

    float oacc[16][4];
#pragma unroll
    for (int i = 0; i < 16; ++i)
#pragma unroll
        for (int u = 0; u < 4; ++u) oacc[i][u] = 0.f;
    float m0 = -1e30f, m1 = -1e30f, l0 = 0.f, l1 = 0.f;

    prefetch(0, 0);

    for (int kb = 0; kb < NKB; ++kb) {
        const int s = kb & 1;
        if (kb + 1 < NKB) { prefetch(kb + 1, s ^ 1); CP_WAIT1(); }
        else              { CP_WAIT0(); }
        __syncthreads();

        const uint32_t st = sm0 + s * STG;

        // ---- S = Q K^T (3-pass split) ----
        float sacc[8][4];
#pragma unroll
        for (int n = 0; n < 8; ++n)
#pragma unroll
            for (int u = 0; u < 4; ++u) sacc[n][u] = 0.f;

#pragma unroll
        for (int t = 0; t < 8; ++t) {
#pragma unroll
            for (int n = 0; n < 8; ++n) {
                uint32_t r4[4];
                ldmx4(r4, st + (n * 8 + rowlane) * KSTRIDE + t * 32 + poff16 +
                          plo * OFF_KL);
                MMA_F16S(sacc[n], fqh[t], r4[0], r4[1]);
                MMA_F16S(sacc[n], fqh[t], r4[2], r4[3]);
                MMA_F16S(sacc[n], fql[t], r4[0], r4[1]);
            }
        }

        // ---- online softmax ----
        float rmax0 = -1e30f, rmax1 = -1e30f;
#pragma unroll
        for (int n = 0; n < 8; ++n) {
            rmax0 = fmaxf(rmax0, fmaxf(sacc[n][0], sacc[n][1]));
            rmax1 = fmaxf(rmax1, fmaxf(sacc[n][2], sacc[n][3]));
        }
        rmax0 = fmaxf(rmax0, __shfl_xor_sync(0xffffffffu, rmax0, 1));
        rmax0 = fmaxf(rmax0, __shfl_xor_sync(0xffffffffu, rmax0, 2));
        rmax1 = fmaxf(rmax1, __shfl_xor_sync(0xffffffffu, rmax1, 1));
        rmax1 = fmaxf(rmax1, __shfl_xor_sync(0xffffffffu, rmax1, 2));

        float nm0 = fmaxf(m0, rmax0), nm1 = fmaxf(m1, rmax1);
        float f0 = __expf(m0 - nm0),  f1 = __expf(m1 - nm1);
        m0 = nm0; m1 = nm1;

        float sum0 = 0.f, sum1 = 0.f;
#pragma unroll
        for (int n = 0; n < 8; ++n) {
            float p0 = __expf(sacc[n][0] - nm0);
            float p1 = __expf(sacc[n][1] - nm0);
            float p2 = __expf(sacc[n][2] - nm1);
            float p3 = __expf(sacc[n][3] - nm1);
            sum0 += p0 + p1; sum1 += p2 + p3;
            sacc[n][0] = p0; sacc[n][1] = p1; sacc[n][2] = p2; sacc[n][3] = p3;
        }
        sum0 += __shfl_xor_sync(0xffffffffu, sum0, 1);
        sum0 += __shfl_xor_sync(0xffffffffu, sum0, 2);
        sum1 += __shfl_xor_sync(0xffffffffu, sum1, 1);
        sum1 += __shfl_xor_sync(0xffffffffu, sum1, 2);
        l0 = l0 * f0 + sum0;
        l1 = l1 * f1 + sum1;

        // P -> hi/lo A fragments (register repack)
        uint32_t pah[4][4], pal[4][4];
#pragma unroll
        for (int t = 0; t < 4; ++t) {
#pragma unroll
            for (int hw = 0; hw < 2; ++hw) {
                const float* pv = sacc[2 * t + hw];
#pragma unroll
                for (int uu = 0; uu < 2; ++uu) {
                    float v0 = pv[2 * uu], v1 = pv[2 * uu + 1];
                    __half hh0 = __float2half_rn(v0);
                    __half hh1 = __float2half_rn(v1);
                    __half2 hp = __halves2half2(hh0, hh1);
                    __half2 lp = __halves2half2(
                        __float2half_rn(v0 - __half2float(hh0)),
                        __float2half_rn(v1 - __half2float(hh1)));
                    pah[t][hw * 2 + uu] = *(uint32_t*)&hp;
                    pal[t][hw * 2 + uu] = *(uint32_t*)&lp;
                }
            }
        }

#pragma unroll
        for (int nf = 0; nf < 16; ++nf) {
            oacc[nf][0] *= f0; oacc[nf][1] *= f0;
            oacc[nf][2] *= f1; oacc[nf][3] *= f1;
        }

        // ---- O += Ph*(Vh+Vl) + Pl*Vh ----
#pragma unroll
        for (int t = 0; t < 4; ++t) {
#pragma unroll
            for (int nf = 0; nf < 16; ++nf) {
                uint32_t r4[4];
                ldmx4(r4, st + OFF_VH + (nf * 8 + rowlane) * VSTRIDE + t * 32 +
                          poff16 + plo * (OFF_VL - OFF_VH));
                MMA_F16S(oacc[nf], pah[t], r4[0], r4[1]);
                MMA_F16S(oacc[nf], pah[t], r4[2], r4[3]);
                MMA_F16S(oacc[nf], pal[t], r4[0], r4[1]);
            }
        }
        __syncthreads();
    }

    // ---- epilogue: normalize, store fp16 hi only ----
    float inv0 = 1.0f / l0, inv1 = 1.0f / l1;
    int r0 = q0 + w * 16 + g;
#pragma unroll
    for (int nf = 0; nf < 16; ++nf) {
        int col = nf * 8 + 2 * q;
        {
            size_t off = (size_t)(b * S_ + r0) * DIM_ + h * HD_ + col;
            *(__half2*)(Oh + off) =
                __floats2half2_rn(oacc[nf][0] * inv0, oacc[nf][1] * inv0);
        }
        {
            size_t off = (size_t)(b * S_ + r0 + 8) * DIM_ + h * HD_ + col;
            *(__half2*)(Oh + off) =
                __floats2half2_rn(oacc[nf][2] * inv1, oacc[nf][3] * inv1);
        }
    }
}

// ============================================================================
// launch
// ============================================================================
extern "C" void kernel_launch(void* const* d_in, const int* in_sizes, int n_in,
                              void* d_out, int out_size)
{
    const float* x  = (const float*)d_in[0];
    const float* wq = (const float*)d_in[1];
    const float* wk = (const float*)d_in[2];
    const float* wv = (const float*)d_in[3];
    const float* wo = (const float*)d_in[4];
    const float* fc = (const float*)d_in[5];
    const float* fs = (const float*)d_in[6];
    float* out = (float*)d_out;

    float* vp;
    cudaGetSymbolAddress((void**)&vp, g_v);
    __half *xh, *wqh, *wql, *wkh, *wkl, *wvh, *wvl, *woh, *wol, *ah;
    __half *qsh, *qsl, *ksh, *ksl, *vth, *vtl;
    cudaGetSymbolAddress((void**)&xh, g_xh);
    cudaGetSymbolAddress((void**)&wqh, g_wqh); cudaGetSymbolAddress((void**)&wql, g_wql);
    cudaGetSymbolAddress((void**)&wkh, g_wkh); cudaGetSymbolAddress((void**)&wkl, g_wkl);
    cudaGetSymbolAddress((void**)&wvh, g_wvh); cudaGetSymbolAddress((void**)&wvl, g_wvl);
    cudaGetSymbolAddress((void**)&woh, g_woh); cudaGetSymbolAddress((void**)&wol, g_wol);
    cudaGetSymbolAddress((void**)&ah, g_ah);
    cudaGetSymbolAddress((void**)&qsh, g_qsh); cudaGetSymbolAddress((void**)&qsl, g_qsl);
    cudaGetSymbolAddress((void**)&ksh, g_ksh); cudaGetSymbolAddress((void**)&ksl, g_ksl);
    cudaGetSymbolAddress((void**)&vth, g_vth); cudaGetSymbolAddress((void**)&vtl, g_vtl);

    const int GEMM_SMEM = 2 * STAGE_B;   // 110592
    cudaFuncSetAttribute(gemm_mma, cudaFuncAttributeMaxDynamicSharedMemorySize,
                         GEMM_SMEM);
    cudaFuncSetAttribute(gemm_rope, cudaFuncAttributeMaxDynamicSharedMemorySize,
                         GEMM_SMEM);
    const int ATTN_SMEM = 2 * STG;       // 143360
    cudaFuncSetAttribute(attn_mma, cudaFuncAttributeMaxDynamicSharedMemorySize,
                         ATTN_SMEM);

    const int M = B_ * S_;               // 4096

    // launch 0: all prep fused
    prep_all<<<dim3(128, 128, 5), dim3(32, 8)>>>(
        x, wq, wk, wv, wo, xh, wqh, wql, wkh, wkl, wvh, wvl, woh, wol);

    // launch 1-2: V projection + transpose/split
    gemm_mma<<<dim3(NKV_ * HD_ / 128, M / 128), 256, GEMM_SMEM>>>(
        xh, wvh, wvl, vp, M, NKV_ * HD_, DIM_);
    transpose_v<<<dim3(S_ / 32, HD_ / 32, B_ * NKV_), dim3(32, 8)>>>(vp, vth, vtl);

    // launch 3: K projection (fused RoPE+split)
    gemm_rope<<<dim3(NKV_ * HD_ / 128, M / 128), 256, GEMM_SMEM>>>(
        xh, wkh, wkl, fc, fs, ksh, ksl, M, NKV_ * HD_, DIM_, 1.0f);

    // launch 4: Q projection (fused RoPE+scale+split) — ncu capture target
    gemm_rope<<<dim3(DIM_ / 128, M / 128), 256, GEMM_SMEM>>>(
        xh, wqh, wql, fc, fs, qsh, qsl, M, DIM_, DIM_, 0.08838834764831845f);

    // launch 5: attention — alternate ncu capture target
    attn_mma<<<dim3(S_ / 128, NH_, B_), 256, ATTN_SMEM>>>(
        qsh, qsl, ksh, ksl, vth, vtl, ah);

    // launch 6: output projection
    gemm_mma<<<dim3(DIM_ / 128, M / 128), 256, GEMM_SMEM>>>(
        ah, woh, wol, out, M, DIM_, DIM_);
}

// round 12
// speedup vs baseline: 4.3723x; 1.0317x over previous
#include <cuda_runtime.h>
#include <cuda_fp16.h>
#include <cstdint>
#include <cstddef>

#define B_   2
#define S_   2048
#define DIM_ 4096
#define NH_  32
#define NKV_ 8
#define HD_  128
#define NQKV (DIM_ + 2 * NKV_ * HD_)    // 6144

// ---------------- scratch (no allocations allowed) ----------------
__device__ float g_v[(size_t)B_ * S_ * NKV_ * HD_];    // fp32 V (pre-transpose)

__device__ __half g_xh[(size_t)B_ * S_ * DIM_];        // x fp16 (hi only)
__device__ __half g_wbh[(size_t)NQKV * DIM_];          // [wq;wk;wv] transposed hi
__device__ __half g_wbl[(size_t)NQKV * DIM_];          // lo
__device__ __half g_woh[(size_t)DIM_ * DIM_];
__device__ __half g_wol[(size_t)DIM_ * DIM_];
__device__ __half g_ah[(size_t)B_ * S_ * DIM_];        // attention out (hi only)

__device__ __half g_qsh[(size_t)B_ * S_ * NH_ * HD_];  // post-rope Q hi/lo
__device__ __half g_qsl[(size_t)B_ * S_ * NH_ * HD_];
__device__ __half g_ksh[(size_t)B_ * S_ * NKV_ * HD_];
__device__ __half g_ksl[(size_t)B_ * S_ * NKV_ * HD_];
__device__ __half g_vth[(size_t)B_ * NKV_ * HD_ * S_]; // V^T [b][kv][d][s] hi/lo
__device__ __half g_vtl[(size_t)B_ * NKV_ * HD_ * S_];

// ============================ PTX helpers (sm_80-portable) ============================
__device__ __forceinline__ uint32_t smem_u32(const void* p) {
    uint32_t a;
    asm("{ .reg .u64 t; cvta.to.shared.u64 t, %1; cvt.u32.u64 %0, t; }"
        : "=r"(a) : "l"(p));
    return a;
}

__device__ __forceinline__ void cp16(uint32_t dst, const void* src) {
    asm volatile("cp.async.cg.shared.global [%0], [%1], 16;" :: "r"(dst), "l"(src));
}

__device__ __forceinline__ void ldmx4(uint32_t* r, uint32_t addr) {
    asm volatile("ldmatrix.sync.aligned.m8n8.x4.shared.b16 {%0,%1,%2,%3}, [%4];"
        : "=r"(r[0]), "=r"(r[1]), "=r"(r[2]), "=r"(r[3]) : "r"(addr));
}

#define CP_COMMIT() asm volatile("cp.async.commit_group;" ::: "memory")
#define CP_WAIT1()  asm volatile("cp.async.wait_group 1;"  ::: "memory")
#define CP_WAIT0()  asm volatile("cp.async.wait_group 0;"  ::: "memory")

#define MMA_F16(c, A, Bf)                                                         \
    asm volatile(                                                                 \
        "mma.sync.aligned.m16n8k16.row.col.f32.f16.f16.f32 "                      \
        "{%0,%1,%2,%3},{%4,%5,%6,%7},{%8,%9},{%0,%1,%2,%3};"                      \
        : "+f"((c)[0]), "+f"((c)[1]), "+f"((c)[2]), "+f"((c)[3])                  \
        : "r"((A)[0]), "r"((A)[1]), "r"((A)[2]), "r"((A)[3]),                     \
          "r"((Bf)[0]), "r"((Bf)[1]))

#define MMA_F16S(c, A, b0, b1)                                                    \
    asm volatile(                                                                 \
        "mma.sync.aligned.m16n8k16.row.col.f32.f16.f16.f32 "                      \
        "{%0,%1,%2,%3},{%4,%5,%6,%7},{%8,%9},{%0,%1,%2,%3};"                      \
        : "+f"((c)[0]), "+f"((c)[1]), "+f"((c)[2]), "+f"((c)[3])                  \
        : "r"((A)[0]), "r"((A)[1]), "r"((A)[2]), "r"((A)[3]),                     \
          "r"(b0), "r"(b1))

// ============================================================================
// GEMM mainloop: C fp32 = Ah @ (Bh+Bl)^T  (A fp16, B fp16 hi/lo, 2-pass)
// CTA 128x128, BK=64, 8 warps 2x4, ldmatrix, 2 CTAs/SM.
// Single __syncthreads per k-iter (multistage WAR ordering).
// smem: 2 stages x 3 tiles x 128 rows x 144B = 110592B.
// ============================================================================
#define TILE_B   18432          // 128 x 144
#define STAGE_B  (3 * TILE_B)   // 55296

struct GemmCore {
    uint32_t sm0;
    int tid, lane, wid, wm, wn, q, rb;
    int row0, col0;
    const __half* src_[3];
    int K;

    __device__ __forceinline__ void init(char* sm,
        const __half* Ah, const __half* Bh, const __half* Bl, int K_) {
        sm0 = smem_u32(sm);
        tid = threadIdx.x; lane = tid & 31; wid = tid >> 5;
        wm = wid >> 2; wn = wid & 3; q = lane & 3; rb = lane >> 2;
        row0 = blockIdx.y * 128; col0 = blockIdx.x * 128;
        K = K_;
        src_[0] = Ah + (size_t)row0 * K;
        src_[1] = Bh + (size_t)col0 * K;
        src_[2] = Bl + (size_t)col0 * K;
    }

    __device__ __forceinline__ void load_stage(int it, int s) {
        const uint32_t base = sm0 + s * STAGE_B;
        const int kel = it * 64;
#pragma unroll
        for (int t = 0; t < 3; ++t) {
            const __half* g = src_[t] + kel;
#pragma unroll
            for (int i = 0; i < 4; ++i) {
                int idx = tid + i * 256;
                int r = idx >> 3, kc = idx & 7;
                cp16(base + t * TILE_B + r * 144 + kc * 16,
                     g + (size_t)r * K + kc * 8);
            }
        }
        CP_COMMIT();
    }

    __device__ __forceinline__ void mainloop(float acc[4][4][4]) {
#pragma unroll
        for (int i = 0; i < 4; ++i)
#pragma unroll
            for (int j = 0; j < 4; ++j)
#pragma unroll
                for (int u = 0; u < 4; ++u) acc[i][j][u] = 0.f;

        const int KIT = K >> 6;
        load_stage(0, 0);

        const int a_row = lane & 15;
        const int a_off = (lane >> 4) * 16;
        const int b_row = (lane & 7) + (lane >> 4) * 8;
        const int b_off = ((lane >> 3) & 1) * 16;

        for (int it = 0; it < KIT; ++it) {
            CP_WAIT0();           // stage it&1 resident
            __syncthreads();      // everyone done reading stage (it-1)&1
            if (it + 1 < KIT) load_stage(it + 1, (it + 1) & 1);

            const uint32_t base = sm0 + (it & 1) * STAGE_B;
#pragma unroll
            for (int kk = 0; kk < 4; ++kk) {
                const int kb = kk * 32;
                uint32_t ah[4][4], bh[4][2], bl[4][2];
#pragma unroll
                for (int mf = 0; mf < 4; ++mf)
                    ldmx4(ah[mf], base + (wm * 64 + mf * 16 + a_row) * 144 + kb + a_off);
#pragma unroll
                for (int np = 0; np < 2; ++np) {
                    uint32_t rbq = base + TILE_B +
                                   (wn * 32 + np * 16 + b_row) * 144 + kb + b_off;
                    uint32_t t4[4];
                    ldmx4(t4, rbq);
                    bh[2*np][0] = t4[0]; bh[2*np][1] = t4[1];
                    bh[2*np+1][0] = t4[2]; bh[2*np+1][1] = t4[3];
                    ldmx4(t4, rbq + TILE_B);
                    bl[2*np][0] = t4[0]; bl[2*np][1] = t4[1];
                    bl[2*np+1][0] = t4[2]; bl[2*np+1][1] = t4[3];
                }
#pragma unroll
                for (int mf = 0; mf < 4; ++mf)
#pragma unroll
                    for (int nf = 0; nf < 4; ++nf) {
                        MMA_F16(acc[mf][nf], ah[mf], bh[nf]);
                        MMA_F16(acc[mf][nf], ah[mf], bl[nf]);
                    }
            }
            // no trailing sync (WAR protected by next iter's leading sync)
        }
    }
};

// ---- RoPE + scale + fp16 hi/lo split epilogue (shared) ----
__device__ __forceinline__ void rope_epilogue(
    float acc[4][4][4], const GemmCore& gc, int colbase,
    const float* __restrict__ cs, const float* __restrict__ sn,
    __half* __restrict__ Oh, __half* __restrict__ Ol, int Nout, float scale)
{
#pragma unroll
    for (int mf = 0; mf < 4; ++mf) {
        int row = gc.row0 + gc.wm * 64 + mf * 16 + gc.rb;
        int s0 = row & (S_ - 1);
#pragma unroll
        for (int nf = 0; nf < 4; ++nf) {
            int col = colbase + gc.wn * 32 + nf * 8 + gc.q * 2;
            int p = (col & (HD_ - 1)) >> 1;
#pragma unroll
            for (int half = 0; half < 2; ++half) {
                int s = s0 + half * 8;
                float c = cs[(s << 6) + p];
                float si = sn[(s << 6) + p];
                float xr = acc[mf][nf][2 * half];
                float xi = acc[mf][nf][2 * half + 1];
                float o0 = fmaf(xr, c, -xi * si) * scale;
                float o1 = fmaf(xr, si,  xi * c) * scale;
                __half h0 = __float2half_rn(o0);
                __half h1 = __float2half_rn(o1);
                size_t off = (size_t)(row + half * 8) * Nout + col;
                *(__half2*)(Oh + off) = __halves2half2(h0, h1);
                *(__half2*)(Ol + off) = __halves2half2(
                    __float2half_rn(o0 - __half2float(h0)),
                    __float2half_rn(o1 - __half2float(h1)));
            }
        }
    }
}

// ---- fused QKV projection: one GEMM over [6144,4096] weights ----
__global__ __launch_bounds__(256, 2) void gemm_qkv(
    const __half* __restrict__ Ah,
    const __half* __restrict__ Bh, const __half* __restrict__ Bl,
    const float* __restrict__ cs, const float* __restrict__ sn,
    __half* __restrict__ qsh, __half* __restrict__ qsl,
    __half* __restrict__ ksh, __half* __restrict__ ksl,
    float* __restrict__ vout)
{
    extern __shared__ __align__(16) char sm[];
    GemmCore gc; gc.init(sm, Ah, Bh, Bl, DIM_);
    float acc[4][4][4];
    gc.mainloop(acc);

    if (gc.col0 < DIM_) {
        // Q: RoPE + 1/sqrt(HD) scale
        rope_epilogue(acc, gc, gc.col0, cs, sn, qsh, qsl, DIM_,
                      0.08838834764831845f);
    } else if (gc.col0 < DIM_ + NKV_ * HD_) {
        // K: RoPE
        rope_epilogue(acc, gc, gc.col0 - DIM_, cs, sn, ksh, ksl, NKV_ * HD_, 1.0f);
    } else {
        // V: fp32 out
        const int colbase = gc.col0 - (DIM_ + NKV_ * HD_);
        const int Nout = NKV_ * HD_;
#pragma unroll
        for (int mf = 0; mf < 4; ++mf) {
            int row = gc.row0 + gc.wm * 64 + mf * 16 + gc.rb;
#pragma unroll
            for (int nf = 0; nf < 4; ++nf) {
                int col = colbase + gc.wn * 32 + nf * 8 + gc.q * 2;
                *(float2*)(vout + (size_t)row * Nout + col) =
                    make_float2(acc[mf][nf][0], acc[mf][nf][1]);
                *(float2*)(vout + (size_t)(row + 8) * Nout + col) =
                    make_float2(acc[mf][nf][2], acc[mf][nf][3]);
            }
        }
    }
}

// ---- plain GEMM: fp32 output (O projection) ----
__global__ __launch_bounds__(256, 2) void gemm_mma(
    const __half* __restrict__ Ah,
    const __half* __restrict__ Bh, const __half* __restrict__ Bl,
    float* __restrict__ C, int M, int N, int K)
{
    extern __shared__ __align__(16) char sm[];
    GemmCore gc; gc.init(sm, Ah, Bh, Bl, K);
    float acc[4][4][4];
    gc.mainloop(acc);
#pragma unroll
    for (int mf = 0; mf < 4; ++mf) {
        int row = gc.row0 + gc.wm * 64 + mf * 16 + gc.rb;
#pragma unroll
        for (int nf = 0; nf < 4; ++nf) {
            int col = gc.col0 + gc.wn * 32 + nf * 8 + gc.q * 2;
            *(float2*)(C + (size_t)row * N + col) =
                make_float2(acc[mf][nf][0], acc[mf][nf][1]);
            *(float2*)(C + (size_t)(row + 8) * N + col) =
                make_float2(acc[mf][nf][2], acc[mf][nf][3]);
        }
    }
}

// ============================================================================
// Fused prep: z=0 wq, z=1 wk, z=2 wv (into combined buffer), z=3 wo, z=4 x->fp16
// grid (128,128,5), block (32,8).
// ============================================================================
__global__ __launch_bounds__(256) void prep_all(
    const float* __restrict__ x,
    const float* __restrict__ wq, const float* __restrict__ wk,
    const float* __restrict__ wv, const float* __restrict__ wo,
    __half* __restrict__ xh,
    __half* __restrict__ wbh, __half* __restrict__ wbl,
    __half* __restrict__ woh, __half* __restrict__ wol)
{
    const int z = blockIdx.z;
    const int tx = threadIdx.x, ty = threadIdx.y;

    if (z == 4) {
        int i = (blockIdx.y * 128 + blockIdx.x) * 256 + ty * 32 + tx;
        float4 v = ((const float4*)x)[i];
        ((__half2*)xh)[2 * i + 0] = __floats2half2_rn(v.x, v.y);
        ((__half2*)xh)[2 * i + 1] = __floats2half2_rn(v.z, v.w);
        return;
    }

    const float* w; __half* th; __half* tl; int N; int rowbase;
    switch (z) {
        case 0: w = wq; th = wbh; tl = wbl; N = DIM_;        rowbase = 0;     break;
        case 1: w = wk; th = wbh; tl = wbl; N = NKV_ * HD_;  rowbase = DIM_;  break;
        case 2: w = wv; th = wbh; tl = wbl; N = NKV_ * HD_;  rowbase = DIM_ + NKV_ * HD_; break;
        default: w = wo; th = woh; tl = wol; N = DIM_;       rowbase = 0;     break;
    }
    const int K = DIM_;
    int n0 = blockIdx.x * 32, k0 = blockIdx.y * 32;
    if (n0 >= N) return;

    __shared__ float s[32][33];
#pragma unroll
    for (int i = ty; i < 32; i += 8)
        s[i][tx] = w[(size_t)(k0 + i) * N + n0 + tx];
    __syncthreads();
#pragma unroll
    for (int i = ty; i < 32; i += 8) {
        float v = s[tx][i];
        __half hi = __float2half_rn(v);
        size_t o = (size_t)(rowbase + n0 + i) * K + k0 + tx;
        th[o] = hi;
        tl[o] = __float2half_rn(v - __half2float(hi));
    }
}

// ============================================================================
// V fp32 [b][s][kv][d] -> V^T fp16 hi/lo [b][kv][d][s]
// ============================================================================
__global__ __launch_bounds__(256) void transpose_v(const float* __restrict__ v,
                                                   __half* __restrict__ th,
                                                   __half* __restrict__ tl)
{
    __shared__ float s[32][33];
    int s0 = blockIdx.x * 32, d0 = blockIdx.y * 32;
    int b = blockIdx.z / NKV_, kv = blockIdx.z % NKV_;
    int tx = threadIdx.x, ty = threadIdx.y;
#pragma unroll
    for (int i = ty; i < 32; i += 8)
        s[i][tx] = v[(((size_t)(b * S_ + s0 + i) * NKV_) + kv) * HD_ + d0 + tx];
    __syncthreads();
#pragma unroll
    for (int i = ty; i < 32; i += 8) {
        float val = s[tx][i];
        __half hi = __float2half_rn(val);
        size_t o = ((size_t)(b * NKV_ + kv) * HD_ + d0 + i) * S_ + s0 + tx;
        th[o] = hi;
        tl[o] = __float2half_rn(val - __half2float(hi));
    }
}

// ============================================================================
// Tensor-core flash attention (fp16, 3-pass QK and PV, ldmatrix).
// ============================================================================
#define AK       64
#define NKB      (S_ / AK)
#define KSTRIDE  272
#define VSTRIDE  144
#define OFF_KL   17408
#define OFF_VH   34816
#define OFF_VL   53248
#define STG      71680

__global__ __launch_bounds__(256, 1) void attn_mma(
    const __half* __restrict__ Qh, const __half* __restrict__ Ql,
    const __half* __restrict__ Kh, const __half* __restrict__ Kl,
    const __half* __restrict__ Vh, const __half* __restrict__ Vl,
    __half* __restrict__ Oh)
{
    extern __shared__ __align__(16) char sm[];
    const uint32_t sm0 = smem_u32(sm);
    const int tid = threadIdx.x, lane = tid & 31, w = tid >> 5;
    const int g = lane >> 2, q = lane & 3;
    const int q0 = blockIdx.x * 128;
    const int h = blockIdx.y, b = blockIdx.z;
    const int kvh = h >> 2;

    const int rowlane = lane & 7;
    const int part = lane >> 3;
    const int poff16 = (part & 1) * 16;
    const int plo = part >> 1;

    // ---- stage Q through smem, build register fragments ----
    uint32_t fqh[8][4], fql[8][4];
    {
        const __half* srcs[2] = { Qh, Ql };
#pragma unroll
        for (int rep = 0; rep < 2; ++rep) {
#pragma unroll
            for (int i = 0; i < 8; ++i) {
                int c = tid + i * 256;
                int r = c >> 4, cc = c & 15;
                cp16(sm0 + r * KSTRIDE + cc * 16,
                     srcs[rep] + ((size_t)((b * S_ + q0 + r) * NH_) + h) * HD_ + cc * 8);
            }
            CP_COMMIT(); CP_WAIT0();
            __syncthreads();
            uint32_t base = sm0 + (w * 16 + (lane & 15)) * KSTRIDE + (lane >> 4) * 16;
#pragma unroll
            for (int t = 0; t < 8; ++t)
                ldmx4(rep ? fql[t] : fqh[t], base + t * 32);
            __syncthreads();
        }
    }

    auto prefetch = [&](int kb, int s) {
        uint32_t st = sm0 + s * STG;
#pragma unroll
        for (int i = 0; i < 4; ++i) {
            int c = tid + i * 256;
            int r = c >> 4, cc = c & 15;
            size_t go = ((size_t)((b * S_ + kb * AK + r) * NKV_) + kvh) * HD_ + cc * 8;
            cp16(st + r * KSTRIDE + cc * 16, Kh + go);
            cp16(st + OFF_KL + r * KSTRIDE + cc * 16, Kl + go);
        }
#pragma unroll
        for (int i = 0; i < 4; ++i) {
            int c = tid + i * 256;
            int d = c >> 3, cc = c & 7;
            size_t go = ((size_t)(b * NKV_ + kvh) * HD_ + d) * S_ + kb * AK + cc * 8;
            cp16(st + OFF_VH + d * VSTRIDE + cc * 16, Vh + go);
            cp16(st + OFF_VL + d * VSTRIDE + cc * 16, Vl + go);
        }
        CP_COMMIT();
    };

    float oacc[16][4];
#pragma unroll
    for (int i = 0; i < 16; ++i)
#pragma unroll
        for (int u = 0; u < 4; ++u) oacc[i][u] = 0.f;
    float m0 = -1e30f, m1 = -1e30f, l0 = 0.f, l1 = 0.f;

    prefetch(0, 0);

    for (int kb = 0; kb < NKB; ++kb) {
        const int s = kb & 1;
        if (kb + 1 < NKB) { prefetch(kb + 1, s ^ 1); CP_WAIT1(); }
        else              { CP_WAIT0(); }
        __syncthreads();

        const uint32_t st = sm0 + s * STG;

        // ---- S = Q K^T (3-pass split) ----
        float sacc[8][4];
#pragma unroll
        for (int n = 0; n < 8; ++n)
#pragma unroll
            for (int u = 0; u < 4; ++u) sacc[n][u] = 0.f;

#pragma unroll
        for (int t = 0; t < 8; ++t) {
#pragma unroll
            for (int n = 0; n < 8; ++n) {
                uint32_t r4[4];
                ldmx4(r4, st + (n * 8 + rowlane) * KSTRIDE + t * 32 + poff16 +
                          plo * OFF_KL);
                MMA_F16S(sacc[n], fqh[t], r4[0], r4[1]);
                MMA_F16S(sacc[n], fqh[t], r4[2], r4[3]);
                MMA_F16S(sacc[n], fql[t], r4[0], r4[1]);
            }
        }

        // ---- online softmax ----
        float rmax0 = -1e30f, rmax1 = -1e30f;
#pragma unroll
        for (int n = 0; n < 8; ++n) {
            rmax0 = fmaxf(rmax0, fmaxf(sacc[n][0], sacc[n][1]));
            rmax1 = fmaxf(rmax1, fmaxf(sacc[n][2], sacc[n][3]));
        }
        rmax0 = fmaxf(rmax0, __shfl_xor_sync(0xffffffffu, rmax0, 1));
        rmax0 = fmaxf(rmax0, __shfl_xor_sync(0xffffffffu, rmax0, 2));
        rmax1 = fmaxf(rmax1, __shfl_xor_sync(0xffffffffu, rmax1, 1));
        rmax1 = fmaxf(rmax1, __shfl_xor_sync(0xffffffffu, rmax1, 2));

        float nm0 = fmaxf(m0, rmax0), nm1 = fmaxf(m1, rmax1);
        float f0 = __expf(m0 - nm0),  f1 = __expf(m1 - nm1);
        m0 = nm0; m1 = nm1;

        float sum0 = 0.f, sum1 = 0.f;
#pragma unroll
        for (int n = 0; n < 8; ++n) {
            float p0 = __expf(sacc[n][0] - nm0);
            float p1 = __expf(sacc[n][1] - nm0);
            float p2 = __expf(sacc[n][2] - nm1);
            float p3 = __expf(sacc[n][3] - nm1);
            sum0 += p0 + p1; sum1 += p2 + p3;
            sacc[n][0] = p0; sacc[n][1] = p1; sacc[n][2] = p2; sacc[n][3] = p3;
        }
        sum0 += __shfl_xor_sync(0xffffffffu, sum0, 1);
        sum0 += __shfl_xor_sync(0xffffffffu, sum0, 2);
        sum1 += __shfl_xor_sync(0xffffffffu, sum1, 1);
        sum1 += __shfl_xor_sync(0xffffffffu, sum1, 2);
        l0 = l0 * f0 + sum0;
        l1 = l1 * f1 + sum1;

        // P -> hi/lo A fragments (register repack)
        uint32_t pah[4][4], pal[4][4];
#pragma unroll
        for (int t = 0; t < 4; ++t) {
#pragma unroll
            for (int hw = 0; hw < 2; ++hw) {
                const float* pv = sacc[2 * t + hw];
#pragma unroll
                for (int uu = 0; uu < 2; ++uu) {
                    float v0 = pv[2 * uu], v1 = pv[2 * uu + 1];
                    __half hh0 = __float2half_rn(v0);
                    __half hh1 = __float2half_rn(v1);
                    __half2 hp = __halves2half2(hh0, hh1);
                    __half2 lp = __halves2half2(
                        __float2half_rn(v0 - __half2float(hh0)),
                        __float2half_rn(v1 - __half2float(hh1)));
                    pah[t][hw * 2 + uu] = *(uint32_t*)&hp;
                    pal[t][hw * 2 + uu] = *(uint32_t*)&lp;
                }
            }
        }

#pragma unroll
        for (int nf = 0; nf < 16; ++nf) {
            oacc[nf][0] *= f0; oacc[nf][1] *= f0;
            oacc[nf][2] *= f1; oacc[nf][3] *= f1;
        }

        // ---- O += Ph*(Vh+Vl) + Pl*Vh ----
#pragma unroll
        for (int t = 0; t < 4; ++t) {
#pragma unroll
            for (int nf = 0; nf < 16; ++nf) {
                uint32_t r4[4];
                ldmx4(r4, st + OFF_VH + (nf * 8 + rowlane) * VSTRIDE + t * 32 +
                          poff16 + plo * (OFF_VL - OFF_VH));
                MMA_F16S(oacc[nf], pah[t], r4[0], r4[1]);
                MMA_F16S(oacc[nf], pah[t], r4[2], r4[3]);
                MMA_F16S(oacc[nf], pal[t], r4[0], r4[1]);
            }
        }
        __syncthreads();
    }

    // ---- epilogue: normalize, store fp16 hi only ----
    float inv0 = 1.0f / l0, inv1 = 1.0f / l1;
    int r0 = q0 + w * 16 + g;
#pragma unroll
    for (int nf = 0; nf < 16; ++nf) {
        int col = nf * 8 + 2 * q;
        {
            size_t off = (size_t)(b * S_ + r0) * DIM_ + h * HD_ + col;
            *(__half2*)(Oh + off) =
                __floats2half2_rn(oacc[nf][0] * inv0, oacc[nf][1] * inv0);
        }
        {
            size_t off = (size_t)(b * S_ + r0 + 8) * DIM_ + h * HD_ + col;
            *(__half2*)(Oh + off) =
                __floats2half2_rn(oacc[nf][2] * inv1, oacc[nf][3] * inv1);
        }
    }
}

// ============================================================================
// launch
// ============================================================================
extern "C" void kernel_launch(void* const* d_in, const int* in_sizes, int n_in,
                              void* d_out, int out_size)
{
    const float* x  = (const float*)d_in[0];
    const float* wq = (const float*)d_in[1];
    const float* wk = (const float*)d_in[2];
    const float* wv = (const float*)d_in[3];
    const float* wo = (const float*)d_in[4];
    const float* fc = (const float*)d_in[5];
    const float* fs = (const float*)d_in[6];
    float* out = (float*)d_out;

    float* vp;
    cudaGetSymbolAddress((void**)&vp, g_v);
    __half *xh, *wbh, *wbl, *woh, *wol, *ah;
    __half *qsh, *qsl, *ksh, *ksl, *vth, *vtl;
    cudaGetSymbolAddress((void**)&xh, g_xh);
    cudaGetSymbolAddress((void**)&wbh, g_wbh); cudaGetSymbolAddress((void**)&wbl, g_wbl);
    cudaGetSymbolAddress((void**)&woh, g_woh); cudaGetSymbolAddress((void**)&wol, g_wol);
    cudaGetSymbolAddress((void**)&ah, g_ah);
    cudaGetSymbolAddress((void**)&qsh, g_qsh); cudaGetSymbolAddress((void**)&qsl, g_qsl);
    cudaGetSymbolAddress((void**)&ksh, g_ksh); cudaGetSymbolAddress((void**)&ksl, g_ksl);
    cudaGetSymbolAddress((void**)&vth, g_vth); cudaGetSymbolAddress((void**)&vtl, g_vtl);

    const int GEMM_SMEM = 2 * STAGE_B;   // 110592
    cudaFuncSetAttribute(gemm_qkv, cudaFuncAttributeMaxDynamicSharedMemorySize,
                         GEMM_SMEM);
    cudaFuncSetAttribute(gemm_mma, cudaFuncAttributeMaxDynamicSharedMemorySize,
                         GEMM_SMEM);
    const int ATTN_SMEM = 2 * STG;       // 143360
    cudaFuncSetAttribute(attn_mma, cudaFuncAttributeMaxDynamicSharedMemorySize,
                         ATTN_SMEM);

    const int M = B_ * S_;               // 4096

    // launch 0: all prep fused
    prep_all<<<dim3(128, 128, 5), dim3(32, 8)>>>(
        x, wq, wk, wv, wo, xh, wbh, wbl, woh, wol);

    // launch 1: fused QKV projection (RoPE+split for Q/K, fp32 for V)
    gemm_qkv<<<dim3(NQKV / 128, M / 128), 256, GEMM_SMEM>>>(
        xh, wbh, wbl, fc, fs, qsh, qsl, ksh, ksl, vp);

    // launch 2: V transpose/split
    transpose_v<<<dim3(S_ / 32, HD_ / 32, B_ * NKV_), dim3(32, 8)>>>(vp, vth, vtl);

    // launch 3: attention — ncu capture target
    attn_mma<<<dim3(S_ / 128, NH_, B_), 256, ATTN_SMEM>>>(
        qsh, qsl, ksh, ksl, vth, vtl, ah);

    // launch 4: output projection
    gemm_mma<<<dim3(DIM_ / 128, M / 128), 256, GEMM_SMEM>>>(
        ah, woh, wol, out, M, DIM_, DIM_);
}

// round 13
// speedup vs baseline: 4.5869x; 1.0491x over previous
#include <cuda_runtime.h>
#include <cuda_fp16.h>
#include <cstdint>
#include <cstddef>

#define B_   2
#define S_   2048
#define DIM_ 4096
#define NH_  32
#define NKV_ 8
#define HD_  128
#define NQKV (DIM_ + 2 * NKV_ * HD_)    // 6144

// ---------------- scratch (no allocations allowed) ----------------
__device__ __half g_xh[(size_t)B_ * S_ * DIM_];        // x fp16 (hi only)
__device__ __half g_wbh[(size_t)NQKV * DIM_];          // [wq;wk;wv] transposed hi
__device__ __half g_wbl[(size_t)NQKV * DIM_];          // lo
__device__ __half g_woh[(size_t)DIM_ * DIM_];
__device__ __half g_wol[(size_t)DIM_ * DIM_];
__device__ __half g_ah[(size_t)B_ * S_ * DIM_];        // attention out (hi only)

__device__ __half g_qsh[(size_t)B_ * S_ * NH_ * HD_];  // post-rope Q hi/lo
__device__ __half g_qsl[(size_t)B_ * S_ * NH_ * HD_];
__device__ __half g_ksh[(size_t)B_ * S_ * NKV_ * HD_];
__device__ __half g_ksl[(size_t)B_ * S_ * NKV_ * HD_];
__device__ __half g_vth[(size_t)B_ * NKV_ * HD_ * S_]; // V^T [b][kv][d][s] hi/lo
__device__ __half g_vtl[(size_t)B_ * NKV_ * HD_ * S_];

// ============================ PTX helpers (sm_80-portable) ============================
__device__ __forceinline__ uint32_t smem_u32(const void* p) {
    uint32_t a;
    asm("{ .reg .u64 t; cvta.to.shared.u64 t, %1; cvt.u32.u64 %0, t; }"
        : "=r"(a) : "l"(p));
    return a;
}

__device__ __forceinline__ void cp16(uint32_t dst, const void* src) {
    asm volatile("cp.async.cg.shared.global [%0], [%1], 16;" :: "r"(dst), "l"(src));
}

__device__ __forceinline__ void ldmx4(uint32_t* r, uint32_t addr) {
    asm volatile("ldmatrix.sync.aligned.m8n8.x4.shared.b16 {%0,%1,%2,%3}, [%4];"
        : "=r"(r[0]), "=r"(r[1]), "=r"(r[2]), "=r"(r[3]) : "r"(addr));
}

#define CP_COMMIT() asm volatile("cp.async.commit_group;" ::: "memory")
#define CP_WAIT1()  asm volatile("cp.async.wait_group 1;"  ::: "memory")
#define CP_WAIT0()  asm volatile("cp.async.wait_group 0;"  ::: "memory")

#define MMA_F16(c, A, Bf)                                                         \
    asm volatile(                                                                 \
        "mma.sync.aligned.m16n8k16.row.col.f32.f16.f16.f32 "                      \
        "{%0,%1,%2,%3},{%4,%5,%6,%7},{%8,%9},{%0,%1,%2,%3};"                      \
        : "+f"((c)[0]), "+f"((c)[1]), "+f"((c)[2]), "+f"((c)[3])                  \
        : "r"((A)[0]), "r"((A)[1]), "r"((A)[2]), "r"((A)[3]),                     \
          "r"((Bf)[0]), "r"((Bf)[1]))

#define MMA_F16S(c, A, b0, b1)                                                    \
    asm volatile(                                                                 \
        "mma.sync.aligned.m16n8k16.row.col.f32.f16.f16.f32 "                      \
        "{%0,%1,%2,%3},{%4,%5,%6,%7},{%8,%9},{%0,%1,%2,%3};"                      \
        : "+f"((c)[0]), "+f"((c)[1]), "+f"((c)[2]), "+f"((c)[3])                  \
        : "r"((A)[0]), "r"((A)[1]), "r"((A)[2]), "r"((A)[3]),                     \
          "r"(b0), "r"(b1))

// ============================================================================
// GEMM mainloop: C fp32 = Ah @ (Bh+Bl)^T  (A fp16, B fp16 hi/lo, 2-pass)
// CTA 128x128, BK=64, 8 warps 2x4, ldmatrix, 2 CTAs/SM, single sync/iter.
// ============================================================================
#define TILE_B   18432          // 128 x 144
#define STAGE_B  (3 * TILE_B)   // 55296

struct GemmCore {
    uint32_t sm0;
    int tid, lane, wid, wm, wn, q, rb;
    int row0, col0;
    const __half* src_[3];
    int K;

    __device__ __forceinline__ void init(char* sm,
        const __half* Ah, const __half* Bh, const __half* Bl, int K_) {
        sm0 = smem_u32(sm);
        tid = threadIdx.x; lane = tid & 31; wid = tid >> 5;
        wm = wid >> 2; wn = wid & 3; q = lane & 3; rb = lane >> 2;
        row0 = blockIdx.y * 128; col0 = blockIdx.x * 128;
        K = K_;
        src_[0] = Ah + (size_t)row0 * K;
        src_[1] = Bh + (size_t)col0 * K;
        src_[2] = Bl + (size_t)col0 * K;
    }

    __device__ __forceinline__ void load_stage(int it, int s) {
        const uint32_t base = sm0 + s * STAGE_B;
        const int kel = it * 64;
#pragma unroll
        for (int t = 0; t < 3; ++t) {
            const __half* g = src_[t] + kel;
#pragma unroll
            for (int i = 0; i < 4; ++i) {
                int idx = tid + i * 256;
                int r = idx >> 3, kc = idx & 7;
                cp16(base + t * TILE_B + r * 144 + kc * 16,
                     g + (size_t)r * K + kc * 8);
            }
        }
        CP_COMMIT();
    }

    __device__ __forceinline__ void mainloop(float acc[4][4][4]) {
#pragma unroll
        for (int i = 0; i < 4; ++i)
#pragma unroll
            for (int j = 0; j < 4; ++j)
#pragma unroll
                for (int u = 0; u < 4; ++u) acc[i][j][u] = 0.f;

        const int KIT = K >> 6;
        load_stage(0, 0);

        const int a_row = lane & 15;
        const int a_off = (lane >> 4) * 16;
        const int b_row = (lane & 7) + (lane >> 4) * 8;
        const int b_off = ((lane >> 3) & 1) * 16;

        for (int it = 0; it < KIT; ++it) {
            CP_WAIT0();           // stage it&1 resident
            __syncthreads();      // everyone done reading stage (it-1)&1
            if (it + 1 < KIT) load_stage(it + 1, (it + 1) & 1);

            const uint32_t base = sm0 + (it & 1) * STAGE_B;
#pragma unroll
            for (int kk = 0; kk < 4; ++kk) {
                const int kb = kk * 32;
                uint32_t ah[4][4], bh[4][2], bl[4][2];
#pragma unroll
                for (int mf = 0; mf < 4; ++mf)
                    ldmx4(ah[mf], base + (wm * 64 + mf * 16 + a_row) * 144 + kb + a_off);
#pragma unroll
                for (int np = 0; np < 2; ++np) {
                    uint32_t rbq = base + TILE_B +
                                   (wn * 32 + np * 16 + b_row) * 144 + kb + b_off;
                    uint32_t t4[4];
                    ldmx4(t4, rbq);
                    bh[2*np][0] = t4[0]; bh[2*np][1] = t4[1];
                    bh[2*np+1][0] = t4[2]; bh[2*np+1][1] = t4[3];
                    ldmx4(t4, rbq + TILE_B);
                    bl[2*np][0] = t4[0]; bl[2*np][1] = t4[1];
                    bl[2*np+1][0] = t4[2]; bl[2*np+1][1] = t4[3];
                }
#pragma unroll
                for (int mf = 0; mf < 4; ++mf)
#pragma unroll
                    for (int nf = 0; nf < 4; ++nf) {
                        MMA_F16(acc[mf][nf], ah[mf], bh[nf]);
                        MMA_F16(acc[mf][nf], ah[mf], bl[nf]);
                    }
            }
        }
    }
};

// ---- RoPE + scale + fp16 hi/lo split epilogue (shared) ----
__device__ __forceinline__ void rope_epilogue(
    float acc[4][4][4], const GemmCore& gc, int colbase,
    const float* __restrict__ cs, const float* __restrict__ sn,
    __half* __restrict__ Oh, __half* __restrict__ Ol, int Nout, float scale)
{
#pragma unroll
    for (int mf = 0; mf < 4; ++mf) {
        int row = gc.row0 + gc.wm * 64 + mf * 16 + gc.rb;
        int s0 = row & (S_ - 1);
#pragma unroll
        for (int nf = 0; nf < 4; ++nf) {
            int col = colbase + gc.wn * 32 + nf * 8 + gc.q * 2;
            int p = (col & (HD_ - 1)) >> 1;
#pragma unroll
            for (int half = 0; half < 2; ++half) {
                int s = s0 + half * 8;
                float c = cs[(s << 6) + p];
                float si = sn[(s << 6) + p];
                float xr = acc[mf][nf][2 * half];
                float xi = acc[mf][nf][2 * half + 1];
                float o0 = fmaf(xr, c, -xi * si) * scale;
                float o1 = fmaf(xr, si,  xi * c) * scale;
                __half h0 = __float2half_rn(o0);
                __half h1 = __float2half_rn(o1);
                size_t off = (size_t)(row + half * 8) * Nout + col;
                *(__half2*)(Oh + off) = __halves2half2(h0, h1);
                *(__half2*)(Ol + off) = __halves2half2(
                    __float2half_rn(o0 - __half2float(h0)),
                    __float2half_rn(o1 - __half2float(h1)));
            }
        }
    }
}

// ---- fused QKV projection: one GEMM over [6144,4096] weights ----
// Q/K: RoPE + split.  V: split + direct transposed store to V^T.
__global__ __launch_bounds__(256, 2) void gemm_qkv(
    const __half* __restrict__ Ah,
    const __half* __restrict__ Bh, const __half* __restrict__ Bl,
    const float* __restrict__ cs, const float* __restrict__ sn,
    __half* __restrict__ qsh, __half* __restrict__ qsl,
    __half* __restrict__ ksh, __half* __restrict__ ksl,
    __half* __restrict__ vth, __half* __restrict__ vtl)
{
    extern __shared__ __align__(16) char sm[];
    GemmCore gc; gc.init(sm, Ah, Bh, Bl, DIM_);
    float acc[4][4][4];
    gc.mainloop(acc);

    if (gc.col0 < DIM_) {
        rope_epilogue(acc, gc, gc.col0, cs, sn, qsh, qsl, DIM_,
                      0.08838834764831845f);
    } else if (gc.col0 < DIM_ + NKV_ * HD_) {
        rope_epilogue(acc, gc, gc.col0 - DIM_, cs, sn, ksh, ksl, NKV_ * HD_, 1.0f);
    } else {
        // V: split fp16 hi/lo, store transposed: vt[((b*NKV+kv)*HD + d)*S + s]
        const int colbase = gc.col0 - (DIM_ + NKV_ * HD_);
#pragma unroll
        for (int mf = 0; mf < 4; ++mf) {
            int row = gc.row0 + gc.wm * 64 + mf * 16 + gc.rb;
            int b = row >> 11;              // / S_
            int s = row & (S_ - 1);
#pragma unroll
            for (int nf = 0; nf < 4; ++nf) {
                int col = colbase + gc.wn * 32 + nf * 8 + gc.q * 2;
                int kv = col >> 7;          // / HD_
                int d  = col & (HD_ - 1);
                size_t base = ((size_t)(b * NKV_ + kv) * HD_ + d) * S_;
#pragma unroll
                for (int half = 0; half < 2; ++half) {
                    int ss = s + half * 8;
#pragma unroll
                    for (int e = 0; e < 2; ++e) {
                        float v = acc[mf][nf][2 * half + e];
                        __half hi = __float2half_rn(v);
                        size_t off = base + (size_t)e * S_ + ss;
                        vth[off] = hi;
                        vtl[off] = __float2half_rn(v - __half2float(hi));
                    }
                }
            }
        }
    }
}

// ---- plain GEMM: fp32 output (O projection) ----
__global__ __launch_bounds__(256, 2) void gemm_mma(
    const __half* __restrict__ Ah,
    const __half* __restrict__ Bh, const __half* __restrict__ Bl,
    float* __restrict__ C, int M, int N, int K)
{
    extern __shared__ __align__(16) char sm[];
    GemmCore gc; gc.init(sm, Ah, Bh, Bl, K);
    float acc[4][4][4];
    gc.mainloop(acc);
#pragma unroll
    for (int mf = 0; mf < 4; ++mf) {
        int row = gc.row0 + gc.wm * 64 + mf * 16 + gc.rb;
#pragma unroll
        for (int nf = 0; nf < 4; ++nf) {
            int col = gc.col0 + gc.wn * 32 + nf * 8 + gc.q * 2;
            *(float2*)(C + (size_t)row * N + col) =
                make_float2(acc[mf][nf][0], acc[mf][nf][1]);
            *(float2*)(C + (size_t)(row + 8) * N + col) =
                make_float2(acc[mf][nf][2], acc[mf][nf][3]);
        }
    }
}

// ============================================================================
// Fused prep: z=0 wq, z=1 wk, z=2 wv (combined buffer), z=3 wo, z=4 x->fp16
// ============================================================================
__global__ __launch_bounds__(256) void prep_all(
    const float* __restrict__ x,
    const float* __restrict__ wq, const float* __restrict__ wk,
    const float* __restrict__ wv, const float* __restrict__ wo,
    __half* __restrict__ xh,
    __half* __restrict__ wbh, __half* __restrict__ wbl,
    __half* __restrict__ woh, __half* __restrict__ wol)
{
    const int z = blockIdx.z;
    const int tx = threadIdx.x, ty = threadIdx.y;

    if (z == 4) {
        int i = (blockIdx.y * 128 + blockIdx.x) * 256 + ty * 32 + tx;
        float4 v = ((const float4*)x)[i];
        ((__half2*)xh)[2 * i + 0] = __floats2half2_rn(v.x, v.y);
        ((__half2*)xh)[2 * i + 1] = __floats2half2_rn(v.z, v.w);
        return;
    }

    const float* w; __half* th; __half* tl; int N; int rowbase;
    switch (z) {
        case 0: w = wq; th = wbh; tl = wbl; N = DIM_;        rowbase = 0;     break;
        case 1: w = wk; th = wbh; tl = wbl; N = NKV_ * HD_;  rowbase = DIM_;  break;
        case 2: w = wv; th = wbh; tl = wbl; N = NKV_ * HD_;  rowbase = DIM_ + NKV_ * HD_; break;
        default: w = wo; th = woh; tl = wol; N = DIM_;       rowbase = 0;     break;
    }
    const int K = DIM_;
    int n0 = blockIdx.x * 32, k0 = blockIdx.y * 32;
    if (n0 >= N) return;

    __shared__ float s[32][33];
#pragma unroll
    for (int i = ty; i < 32; i += 8)
        s[i][tx] = w[(size_t)(k0 + i) * N + n0 + tx];
    __syncthreads();
#pragma unroll
    for (int i = ty; i < 32; i += 8) {
        float v = s[tx][i];
        __half hi = __float2half_rn(v);
        size_t o = (size_t)(rowbase + n0 + i) * K + k0 + tx;
        th[o] = hi;
        tl[o] = __float2half_rn(v - __half2float(hi));
    }
}

// ============================================================================
// Tensor-core flash attention (fp16, 3-pass QK, 2-pass PV, ldmatrix).
// ============================================================================
#define AK       64
#define NKB      (S_ / AK)
#define KSTRIDE  272
#define VSTRIDE  144
#define OFF_KL   17408
#define OFF_VH   34816
#define OFF_VL   53248
#define STG      71680

__global__ __launch_bounds__(256, 1) void attn_mma(
    const __half* __restrict__ Qh, const __half* __restrict__ Ql,
    const __half* __restrict__ Kh, const __half* __restrict__ Kl,
    const __half* __restrict__ Vh, const __half* __restrict__ Vl,
    __half* __restrict__ Oh)
{
    extern __shared__ __align__(16) char sm[];
    const uint32_t sm0 = smem_u32(sm);
    const int tid = threadIdx.x, lane = tid & 31, w = tid >> 5;
    const int g = lane >> 2, q = lane & 3;
    const int q0 = blockIdx.x * 128;
    const int h = blockIdx.y, b = blockIdx.z;
    const int kvh = h >> 2;

    const int rowlane = lane & 7;
    const int part = lane >> 3;
    const int poff16 = (part & 1) * 16;
    const int plo = part >> 1;

    // ---- stage Q through smem, build register fragments ----
    uint32_t fqh[8][4], fql[8][4];
    {
        const __half* srcs[2] = { Qh, Ql };
#pragma unroll
        for (int rep = 0; rep < 2; ++rep) {
#pragma unroll
            for (int i = 0; i < 8; ++i) {
                int c = tid + i * 256;
                int r = c >> 4, cc = c & 15;
                cp16(sm0 + r * KSTRIDE + cc * 16,
                     srcs[rep] + ((size_t)((b * S_ + q0 + r) * NH_) + h) * HD_ + cc * 8);
            }
            CP_COMMIT(); CP_WAIT0();
            __syncthreads();
            uint32_t base = sm0 + (w * 16 + (lane & 15)) * KSTRIDE + (lane >> 4) * 16;
#pragma unroll
            for (int t = 0; t < 8; ++t)
                ldmx4(rep ? fql[t] : fqh[t], base + t * 32);
            __syncthreads();
        }
    }

    auto prefetch = [&](int kb, int s) {
        uint32_t st = sm0 + s * STG;
#pragma unroll
        for (int i = 0; i < 4; ++i) {
            int c = tid + i * 256;
            int r = c >> 4, cc = c & 15;
            size_t go = ((size_t)((b * S_ + kb * AK + r) * NKV_) + kvh) * HD_ + cc * 8;
            cp16(st + r * KSTRIDE + cc * 16, Kh + go);
            cp16(st + OFF_KL + r * KSTRIDE + cc * 16, Kl + go);
        }
#pragma unroll
        for (int i = 0; i < 4; ++i) {
            int c = tid + i * 256;
            int d = c >> 3, cc = c & 7;
            size_t go = ((size_t)(b * NKV_ + kvh) * HD_ + d) * S_ + kb * AK + cc * 8;
            cp16(st + OFF_VH + d * VSTRIDE + cc * 16, Vh + go);
            cp16(st + OFF_VL + d * VSTRIDE + cc * 16, Vl + go);
        }
        CP_COMMIT();
    };

    float oacc[16][4];
#pragma unroll
    for (int i = 0; i < 16; ++i)
#pragma unroll
        for (int u = 0; u < 4; ++u) oacc[i][u] = 0.f;
    float m0 = -1e30f, m1 = -1e30f, l0 = 0.f, l1 = 0.f;

    prefetch(0, 0);

    for (int kb = 0; kb < NKB; ++kb) {
        const int s = kb & 1;
        if (kb + 1 < NKB) { prefetch(kb + 1, s ^ 1); CP_WAIT1(); }
        else              { CP_WAIT0(); }
        __syncthreads();

        const uint32_t st = sm0 + s * STG;

        // ---- S = Q K^T (3-pass split) ----
        float sacc[8][4];
#pragma unroll
        for (int n = 0; n < 8; ++n)
#pragma unroll
            for (int u = 0; u < 4; ++u) sacc[n][u] = 0.f;

#pragma unroll
        for (int t = 0; t < 8; ++t) {
#pragma unroll
            for (int n = 0; n < 8; ++n) {
                uint32_t r4[4];
                ldmx4(r4, st + (n * 8 + rowlane) * KSTRIDE + t * 32 + poff16 +
                          plo * OFF_KL);
                MMA_F16S(sacc[n], fqh[t], r4[0], r4[1]);
                MMA_F16S(sacc[n], fqh[t], r4[2], r4[3]);
                MMA_F16S(sacc[n], fql[t], r4[0], r4[1]);
            }
        }

        // ---- online softmax ----
        float rmax0 = -1e30f, rmax1 = -1e30f;
#pragma unroll
        for (int n = 0; n < 8; ++n) {
            rmax0 = fmaxf(rmax0, fmaxf(sacc[n][0], sacc[n][1]));
            rmax1 = fmaxf(rmax1, fmaxf(sacc[n][2], sacc[n][3]));
        }
        rmax0 = fmaxf(rmax0, __shfl_xor_sync(0xffffffffu, rmax0, 1));
        rmax0 = fmaxf(rmax0, __shfl_xor_sync(0xffffffffu, rmax0, 2));
        rmax1 = fmaxf(rmax1, __shfl_xor_sync(0xffffffffu, rmax1, 1));
        rmax1 = fmaxf(rmax1, __shfl_xor_sync(0xffffffffu, rmax1, 2));

        float nm0 = fmaxf(m0, rmax0), nm1 = fmaxf(m1, rmax1);
        float f0 = __expf(m0 - nm0),  f1 = __expf(m1 - nm1);
        m0 = nm0; m1 = nm1;

        float sum0 = 0.f, sum1 = 0.f;
#pragma unroll
        for (int n = 0; n < 8; ++n) {
            float p0 = __expf(sacc[n][0] - nm0);
            float p1 = __expf(sacc[n][1] - nm0);
            float p2 = __expf(sacc[n][2] - nm1);
            float p3 = __expf(sacc[n][3] - nm1);
            sum0 += p0 + p1; sum1 += p2 + p3;
            sacc[n][0] = p0; sacc[n][1] = p1; sacc[n][2] = p2; sacc[n][3] = p3;
        }
        sum0 += __shfl_xor_sync(0xffffffffu, sum0, 1);
        sum0 += __shfl_xor_sync(0xffffffffu, sum0, 2);
        sum1 += __shfl_xor_sync(0xffffffffu, sum1, 1);
        sum1 += __shfl_xor_sync(0xffffffffu, sum1, 2);
        l0 = l0 * f0 + sum0;
        l1 = l1 * f1 + sum1;

        // P -> hi A fragments (register repack, hi only)
        uint32_t pah[4][4];
#pragma unroll
        for (int t = 0; t < 4; ++t) {
#pragma unroll
            for (int hw = 0; hw < 2; ++hw) {
                const float* pv = sacc[2 * t + hw];
#pragma unroll
                for (int uu = 0; uu < 2; ++uu) {
                    __half2 hp = __floats2half2_rn(pv[2 * uu], pv[2 * uu + 1]);
                    pah[t][hw * 2 + uu] = *(uint32_t*)&hp;
                }
            }
        }

#pragma unroll
        for (int nf = 0; nf < 16; ++nf) {
            oacc[nf][0] *= f0; oacc[nf][1] *= f0;
            oacc[nf][2] *= f1; oacc[nf][3] *= f1;
        }

        // ---- O += Ph*(Vh+Vl)  (2-pass PV) ----
#pragma unroll
        for (int t = 0; t < 4; ++t) {
#pragma unroll
            for (int nf = 0; nf < 16; ++nf) {
                uint32_t r4[4];
                ldmx4(r4, st + OFF_VH + (nf * 8 + rowlane) * VSTRIDE + t * 32 +
                          poff16 + plo * (OFF_VL - OFF_VH));
                MMA_F16S(oacc[nf], pah[t], r4[0], r4[1]);
                MMA_F16S(oacc[nf], pah[t], r4[2], r4[3]);
            }
        }
        __syncthreads();
    }

    // ---- epilogue: normalize, store fp16 hi only ----
    float inv0 = 1.0f / l0, inv1 = 1.0f / l1;
    int r0 = q0 + w * 16 + g;
#pragma unroll
    for (int nf = 0; nf < 16; ++nf) {
        int col = nf * 8 + 2 * q;
        {
            size_t off = (size_t)(b * S_ + r0) * DIM_ + h * HD_ + col;
            *(__half2*)(Oh + off) =
                __floats2half2_rn(oacc[nf][0] * inv0, oacc[nf][1] * inv0);
        }
        {
            size_t off = (size_t)(b * S_ + r0 + 8) * DIM_ + h * HD_ + col;
            *(__half2*)(Oh + off) =
                __floats2half2_rn(oacc[nf][2] * inv1, oacc[nf][3] * inv1);
        }
    }
}

// ============================================================================
// launch
// ============================================================================
extern "C" void kernel_launch(void* const* d_in, const int* in_sizes, int n_in,
                              void* d_out, int out_size)
{
    const float* x  = (const float*)d_in[0];
    const float* wq = (const float*)d_in[1];
    const float* wk = (const float*)d_in[2];
    const float* wv = (const float*)d_in[3];
    const float* wo = (const float*)d_in[4];
    const float* fc = (const float*)d_in[5];
    const float* fs = (const float*)d_in[6];
    float* out = (float*)d_out;

    __half *xh, *wbh, *wbl, *woh, *wol, *ah;
    __half *qsh, *qsl, *ksh, *ksl, *vth, *vtl;
    cudaGetSymbolAddress((void**)&xh, g_xh);
    cudaGetSymbolAddress((void**)&wbh, g_wbh); cudaGetSymbolAddress((void**)&wbl, g_wbl);
    cudaGetSymbolAddress((void**)&woh, g_woh); cudaGetSymbolAddress((void**)&wol, g_wol);
    cudaGetSymbolAddress((void**)&ah, g_ah);
    cudaGetSymbolAddress((void**)&qsh, g_qsh); cudaGetSymbolAddress((void**)&qsl, g_qsl);
    cudaGetSymbolAddress((void**)&ksh, g_ksh); cudaGetSymbolAddress((void**)&ksl, g_ksl);
    cudaGetSymbolAddress((void**)&vth, g_vth); cudaGetSymbolAddress((void**)&vtl, g_vtl);

    const int GEMM_SMEM = 2 * STAGE_B;   // 110592
    cudaFuncSetAttribute(gemm_qkv, cudaFuncAttributeMaxDynamicSharedMemorySize,
                         GEMM_SMEM);
    cudaFuncSetAttribute(gemm_mma, cudaFuncAttributeMaxDynamicSharedMemorySize,
                         GEMM_SMEM);
    const int ATTN_SMEM = 2 * STG;       // 143360
    cudaFuncSetAttribute(attn_mma, cudaFuncAttributeMaxDynamicSharedMemorySize,
                         ATTN_SMEM);

    const int M = B_ * S_;               // 4096

    // launch 0: all prep fused
    prep_all<<<dim3(128, 128, 5), dim3(32, 8)>>>(
        x, wq, wk, wv, wo, xh, wbh, wbl, woh, wol);

    // launch 1: fused QKV projection (RoPE+split Q/K, transposed split V)
    gemm_qkv<<<dim3(NQKV / 128, M / 128), 256, GEMM_SMEM>>>(
        xh, wbh, wbl, fc, fs, qsh, qsl, ksh, ksl, vth, vtl);

    // launch 2: attention
    attn_mma<<<dim3(S_ / 128, NH_, B_), 256, ATTN_SMEM>>>(
        qsh, qsl, ksh, ksl, vth, vtl, ah);

    // launch 3: output projection
    gemm_mma<<<dim3(DIM_ / 128, M / 128), 256, GEMM_SMEM>>>(
        ah, woh, wol, out, M, DIM_, DIM_);
}

// round 14
// speedup vs baseline: 6.2778x; 1.3686x over previous
#include <cuda_runtime.h>
#include <cuda_fp16.h>
#include <cstdint>
#include <cstddef>

#define B_   2
#define S_   2048
#define DIM_ 4096
#define NH_  32
#define NKV_ 8
#define HD_  128
#define NQKV (DIM_ + 2 * NKV_ * HD_)    // 6144

// ---------------- scratch (no allocations allowed) ----------------
__device__ __half g_xh[(size_t)B_ * S_ * DIM_];        // x fp16 (hi only)
__device__ __half g_wbh[(size_t)NQKV * DIM_];          // [wq;wk;wv] transposed hi
__device__ __half g_woh[(size_t)DIM_ * DIM_];          // wo transposed hi
__device__ __half g_ah[(size_t)B_ * S_ * DIM_];        // attention out (hi only)

__device__ __half g_qsh[(size_t)B_ * S_ * NH_ * HD_];  // post-rope Q hi/lo
__device__ __half g_qsl[(size_t)B_ * S_ * NH_ * HD_];
__device__ __half g_ksh[(size_t)B_ * S_ * NKV_ * HD_];
__device__ __half g_ksl[(size_t)B_ * S_ * NKV_ * HD_];
__device__ __half g_vth[(size_t)B_ * NKV_ * HD_ * S_]; // V^T [b][kv][d][s] hi/lo
__device__ __half g_vtl[(size_t)B_ * NKV_ * HD_ * S_];

// ============================ PTX helpers (sm_80-portable) ============================
__device__ __forceinline__ uint32_t smem_u32(const void* p) {
    uint32_t a;
    asm("{ .reg .u64 t; cvta.to.shared.u64 t, %1; cvt.u32.u64 %0, t; }"
        : "=r"(a) : "l"(p));
    return a;
}

__device__ __forceinline__ void cp16(uint32_t dst, const void* src) {
    asm volatile("cp.async.cg.shared.global [%0], [%1], 16;" :: "r"(dst), "l"(src));
}

__device__ __forceinline__ void ldmx4(uint32_t* r, uint32_t addr) {
    asm volatile("ldmatrix.sync.aligned.m8n8.x4.shared.b16 {%0,%1,%2,%3}, [%4];"
        : "=r"(r[0]), "=r"(r[1]), "=r"(r[2]), "=r"(r[3]) : "r"(addr));
}

#define CP_COMMIT() asm volatile("cp.async.commit_group;" ::: "memory")
#define CP_WAIT1()  asm volatile("cp.async.wait_group 1;"  ::: "memory")
#define CP_WAIT0()  asm volatile("cp.async.wait_group 0;"  ::: "memory")

#define MMA_F16(c, A, Bf)                                                         \
    asm volatile(                                                                 \
        "mma.sync.aligned.m16n8k16.row.col.f32.f16.f16.f32 "                      \
        "{%0,%1,%2,%3},{%4,%5,%6,%7},{%8,%9},{%0,%1,%2,%3};"                      \
        : "+f"((c)[0]), "+f"((c)[1]), "+f"((c)[2]), "+f"((c)[3])                  \
        : "r"((A)[0]), "r"((A)[1]), "r"((A)[2]), "r"((A)[3]),                     \
          "r"((Bf)[0]), "r"((Bf)[1]))

#define MMA_F16S(c, A, b0, b1)                                                    \
    asm volatile(                                                                 \
        "mma.sync.aligned.m16n8k16.row.col.f32.f16.f16.f32 "                      \
        "{%0,%1,%2,%3},{%4,%5,%6,%7},{%8,%9},{%0,%1,%2,%3};"                      \
        : "+f"((c)[0]), "+f"((c)[1]), "+f"((c)[2]), "+f"((c)[3])                  \
        : "r"((A)[0]), "r"((A)[1]), "r"((A)[2]), "r"((A)[3]),                     \
          "r"(b0), "r"(b1))

// ============================================================================
// GEMM mainloop: C fp32 = Ah @ Bh^T  (single-pass fp16, weights hi-only)
// CTA 128x128, BK=64, 8 warps 2x4, ldmatrix, 2 CTAs/SM, 3-stage pipeline.
// smem: 3 stages x 2 tiles x 128 rows x 144B = 110592B.
// ============================================================================
#define TILE_B   18432          // 128 x 144
#define STAGE_B  (2 * TILE_B)   // 36864

struct GemmCore {
    uint32_t sm0;
    int tid, lane, wid, wm, wn, q, rb;
    int row0, col0;
    const __half* src_[2];
    int K;

    __device__ __forceinline__ void init(char* sm,
        const __half* Ah, const __half* Bh, int K_) {
        sm0 = smem_u32(sm);
        tid = threadIdx.x; lane = tid & 31; wid = tid >> 5;
        wm = wid >> 2; wn = wid & 3; q = lane & 3; rb = lane >> 2;
        row0 = blockIdx.y * 128; col0 = blockIdx.x * 128;
        K = K_;
        src_[0] = Ah + (size_t)row0 * K;
        src_[1] = Bh + (size_t)col0 * K;
    }

    __device__ __forceinline__ void load_stage(int it, int s) {
        const uint32_t base = sm0 + s * STAGE_B;
        const int kel = it * 64;
#pragma unroll
        for (int t = 0; t < 2; ++t) {
            const __half* g = src_[t] + kel;
#pragma unroll
            for (int i = 0; i < 4; ++i) {
                int idx = tid + i * 256;
                int r = idx >> 3, kc = idx & 7;
                cp16(base + t * TILE_B + r * 144 + kc * 16,
                     g + (size_t)r * K + kc * 8);
            }
        }
        CP_COMMIT();
    }

    __device__ __forceinline__ void mainloop(float acc[4][4][4]) {
#pragma unroll
        for (int i = 0; i < 4; ++i)
#pragma unroll
            for (int j = 0; j < 4; ++j)
#pragma unroll
                for (int u = 0; u < 4; ++u) acc[i][j][u] = 0.f;

        const int KIT = K >> 6;
        load_stage(0, 0);
        load_stage(1, 1);

        const int a_row = lane & 15;
        const int a_off = (lane >> 4) * 16;
        const int b_row = (lane & 7) + (lane >> 4) * 8;
        const int b_off = ((lane >> 3) & 1) * 16;

        int cur = 0, nxt = 2;
        for (int it = 0; it < KIT; ++it) {
            if (it + 1 < KIT) { CP_WAIT1(); }   // stage it resident, it+1 in flight
            else              { CP_WAIT0(); }
            __syncthreads();                     // all warps done with stage nxt's slot
            if (it + 2 < KIT) load_stage(it + 2, nxt);

            const uint32_t base = sm0 + cur * STAGE_B;
#pragma unroll
            for (int kk = 0; kk < 4; ++kk) {
                const int kb = kk * 32;
                uint32_t ah[4][4], bh[4][2];
#pragma unroll
                for (int mf = 0; mf < 4; ++mf)
                    ldmx4(ah[mf], base + (wm * 64 + mf * 16 + a_row) * 144 + kb + a_off);
#pragma unroll
                for (int np = 0; np < 2; ++np) {
                    uint32_t t4[4];
                    ldmx4(t4, base + TILE_B +
                              (wn * 32 + np * 16 + b_row) * 144 + kb + b_off);
                    bh[2*np][0] = t4[0]; bh[2*np][1] = t4[1];
                    bh[2*np+1][0] = t4[2]; bh[2*np+1][1] = t4[3];
                }
#pragma unroll
                for (int mf = 0; mf < 4; ++mf)
#pragma unroll
                    for (int nf = 0; nf < 4; ++nf)
                        MMA_F16(acc[mf][nf], ah[mf], bh[nf]);
            }
            cur = (cur == 2) ? 0 : cur + 1;
            nxt = (nxt == 2) ? 0 : nxt + 1;
        }
    }
};

// ---- RoPE + scale + fp16 hi/lo split epilogue (shared) ----
__device__ __forceinline__ void rope_epilogue(
    float acc[4][4][4], const GemmCore& gc, int colbase,
    const float* __restrict__ cs, const float* __restrict__ sn,
    __half* __restrict__ Oh, __half* __restrict__ Ol, int Nout, float scale)
{
#pragma unroll
    for (int mf = 0; mf < 4; ++mf) {
        int row = gc.row0 + gc.wm * 64 + mf * 16 + gc.rb;
        int s0 = row & (S_ - 1);
#pragma unroll
        for (int nf = 0; nf < 4; ++nf) {
            int col = colbase + gc.wn * 32 + nf * 8 + gc.q * 2;
            int p = (col & (HD_ - 1)) >> 1;
#pragma unroll
            for (int half = 0; half < 2; ++half) {
                int s = s0 + half * 8;
                float c = cs[(s << 6) + p];
                float si = sn[(s << 6) + p];
                float xr = acc[mf][nf][2 * half];
                float xi = acc[mf][nf][2 * half + 1];
                float o0 = fmaf(xr, c, -xi * si) * scale;
                float o1 = fmaf(xr, si,  xi * c) * scale;
                __half h0 = __float2half_rn(o0);
                __half h1 = __float2half_rn(o1);
                size_t off = (size_t)(row + half * 8) * Nout + col;
                *(__half2*)(Oh + off) = __halves2half2(h0, h1);
                *(__half2*)(Ol + off) = __halves2half2(
                    __float2half_rn(o0 - __half2float(h0)),
                    __float2half_rn(o1 - __half2float(h1)));
            }
        }
    }
}

// ---- fused QKV projection: one GEMM over [6144,4096] weights ----
__global__ __launch_bounds__(256, 2) void gemm_qkv(
    const __half* __restrict__ Ah, const __half* __restrict__ Bh,
    const float* __restrict__ cs, const float* __restrict__ sn,
    __half* __restrict__ qsh, __half* __restrict__ qsl,
    __half* __restrict__ ksh, __half* __restrict__ ksl,
    __half* __restrict__ vth, __half* __restrict__ vtl)
{
    extern __shared__ __align__(16) char sm[];
    GemmCore gc; gc.init(sm, Ah, Bh, DIM_);
    float acc[4][4][4];
    gc.mainloop(acc);

    if (gc.col0 < DIM_) {
        rope_epilogue(acc, gc, gc.col0, cs, sn, qsh, qsl, DIM_,
                      0.08838834764831845f);
    } else if (gc.col0 < DIM_ + NKV_ * HD_) {
        rope_epilogue(acc, gc, gc.col0 - DIM_, cs, sn, ksh, ksl, NKV_ * HD_, 1.0f);
    } else {
        // V: split fp16 hi/lo, store transposed: vt[((b*NKV+kv)*HD + d)*S + s]
        const int colbase = gc.col0 - (DIM_ + NKV_ * HD_);
#pragma unroll
        for (int mf = 0; mf < 4; ++mf) {
            int row = gc.row0 + gc.wm * 64 + mf * 16 + gc.rb;
            int b = row >> 11;
            int s = row & (S_ - 1);
#pragma unroll
            for (int nf = 0; nf < 4; ++nf) {
                int col = colbase + gc.wn * 32 + nf * 8 + gc.q * 2;
                int kv = col >> 7;
                int d  = col & (HD_ - 1);
                size_t base = ((size_t)(b * NKV_ + kv) * HD_ + d) * S_;
#pragma unroll
                for (int half = 0; half < 2; ++half) {
                    int ss = s + half * 8;
#pragma unroll
                    for (int e = 0; e < 2; ++e) {
                        float v = acc[mf][nf][2 * half + e];
                        __half hi = __float2half_rn(v);
                        size_t off = base + (size_t)e * S_ + ss;
                        vth[off] = hi;
                        vtl[off] = __float2half_rn(v - __half2float(hi));
                    }
                }
            }
        }
    }
}

// ---- plain GEMM: fp32 output (O projection) ----
__global__ __launch_bounds__(256, 2) void gemm_mma(
    const __half* __restrict__ Ah, const __half* __restrict__ Bh,
    float* __restrict__ C, int M, int N, int K)
{
    extern __shared__ __align__(16) char sm[];
    GemmCore gc; gc.init(sm, Ah, Bh, K);
    float acc[4][4][4];
    gc.mainloop(acc);
#pragma unroll
    for (int mf = 0; mf < 4; ++mf) {
        int row = gc.row0 + gc.wm * 64 + mf * 16 + gc.rb;
#pragma unroll
        for (int nf = 0; nf < 4; ++nf) {
            int col = gc.col0 + gc.wn * 32 + nf * 8 + gc.q * 2;
            *(float2*)(C + (size_t)row * N + col) =
                make_float2(acc[mf][nf][0], acc[mf][nf][1]);
            *(float2*)(C + (size_t)(row + 8) * N + col) =
                make_float2(acc[mf][nf][2], acc[mf][nf][3]);
        }
    }
}

// ============================================================================
// Fused prep: z=0 wq, z=1 wk, z=2 wv (combined buffer), z=3 wo, z=4 x->fp16
// Weights: hi-only transpose.
// ============================================================================
__global__ __launch_bounds__(256) void prep_all(
    const float* __restrict__ x,
    const float* __restrict__ wq, const float* __restrict__ wk,
    const float* __restrict__ wv, const float* __restrict__ wo,
    __half* __restrict__ xh,
    __half* __restrict__ wbh, __half* __restrict__ woh)
{
    const int z = blockIdx.z;
    const int tx = threadIdx.x, ty = threadIdx.y;

    if (z == 4) {
        int i = (blockIdx.y * 128 + blockIdx.x) * 256 + ty * 32 + tx;
        float4 v = ((const float4*)x)[i];
        ((__half2*)xh)[2 * i + 0] = __floats2half2_rn(v.x, v.y);
        ((__half2*)xh)[2 * i + 1] = __floats2half2_rn(v.z, v.w);
        return;
    }

    const float* w; __half* th; int N; int rowbase;
    switch (z) {
        case 0: w = wq; th = wbh; N = DIM_;        rowbase = 0;     break;
        case 1: w = wk; th = wbh; N = NKV_ * HD_;  rowbase = DIM_;  break;
        case 2: w = wv; th = wbh; N = NKV_ * HD_;  rowbase = DIM_ + NKV_ * HD_; break;
        default: w = wo; th = woh; N = DIM_;       rowbase = 0;     break;
    }
    const int K = DIM_;
    int n0 = blockIdx.x * 32, k0 = blockIdx.y * 32;
    if (n0 >= N) return;

    __shared__ float s[32][33];
#pragma unroll
    for (int i = ty; i < 32; i += 8)
        s[i][tx] = w[(size_t)(k0 + i) * N + n0 + tx];
    __syncthreads();
#pragma unroll
    for (int i = ty; i < 32; i += 8)
        th[(size_t)(rowbase + n0 + i) * K + k0 + tx] = __float2half_rn(s[tx][i]);
}

// ============================================================================
// Tensor-core flash attention (fp16, 3-pass QK, 2-pass PV, ldmatrix).
// ============================================================================
#define AK       64
#define NKB      (S_ / AK)
#define KSTRIDE  272
#define VSTRIDE  144
#define OFF_KL   17408
#define OFF_VH   34816
#define OFF_VL   53248
#define STG      71680

__global__ __launch_bounds__(256, 1) void attn_mma(
    const __half* __restrict__ Qh, const __half* __restrict__ Ql,
    const __half* __restrict__ Kh, const __half* __restrict__ Kl,
    const __half* __restrict__ Vh, const __half* __restrict__ Vl,
    __half* __restrict__ Oh)
{
    extern __shared__ __align__(16) char sm[];
    const uint32_t sm0 = smem_u32(sm);
    const int tid = threadIdx.x, lane = tid & 31, w = tid >> 5;
    const int g = lane >> 2, q = lane & 3;
    const int q0 = blockIdx.x * 128;
    const int h = blockIdx.y, b = blockIdx.z;
    const int kvh = h >> 2;

    const int rowlane = lane & 7;
    const int part = lane >> 3;
    const int poff16 = (part & 1) * 16;
    const int plo = part >> 1;

    // ---- stage Q through smem, build register fragments ----
    uint32_t fqh[8][4], fql[8][4];
    {
        const __half* srcs[2] = { Qh, Ql };
#pragma unroll
        for (int rep = 0; rep < 2; ++rep) {
#pragma unroll
            for (int i = 0; i < 8; ++i) {
                int c = tid + i * 256;
                int r = c >> 4, cc = c & 15;
                cp16(sm0 + r * KSTRIDE + cc * 16,
                     srcs[rep] + ((size_t)((b * S_ + q0 + r) * NH_) + h) * HD_ + cc * 8);
            }
            CP_COMMIT(); CP_WAIT0();
            __syncthreads();
            uint32_t base = sm0 + (w * 16 + (lane & 15)) * KSTRIDE + (lane >> 4) * 16;
#pragma unroll
            for (int t = 0; t < 8; ++t)
                ldmx4(rep ? fql[t] : fqh[t], base + t * 32);
            __syncthreads();
        }
    }

    auto prefetch = [&](int kb, int s) {
        uint32_t st = sm0 + s * STG;
#pragma unroll
        for (int i = 0; i < 4; ++i) {
            int c = tid + i * 256;
            int r = c >> 4, cc = c & 15;
            size_t go = ((size_t)((b * S_ + kb * AK + r) * NKV_) + kvh) * HD_ + cc * 8;
            cp16(st + r * KSTRIDE + cc * 16, Kh + go);
            cp16(st + OFF_KL + r * KSTRIDE + cc * 16, Kl + go);
        }
#pragma unroll
        for (int i = 0; i < 4; ++i) {
            int c = tid + i * 256;
            int d = c >> 3, cc = c & 7;
            size_t go = ((size_t)(b * NKV_ + kvh) * HD_ + d) * S_ + kb * AK + cc * 8;
            cp16(st + OFF_VH + d * VSTRIDE + cc * 16, Vh + go);
            cp16(st + OFF_VL + d * VSTRIDE + cc * 16, Vl + go);
        }
        CP_COMMIT();
    };

    float oacc[16][4];
#pragma unroll
    for (int i = 0; i < 16; ++i)
#pragma unroll
        for (int u = 0; u < 4; ++u) oacc[i][u] = 0.f;
    float m0 = -1e30f, m1 = -1e30f, l0 = 0.f, l1 = 0.f;

    prefetch(0, 0);

    for (int kb = 0; kb < NKB; ++kb) {
        const int s = kb & 1;
        if (kb + 1 < NKB) { prefetch(kb + 1, s ^ 1); CP_WAIT1(); }
        else              { CP_WAIT0(); }
        __syncthreads();

        const uint32_t st = sm0 + s * STG;

        // ---- S = Q K^T (3-pass split) ----
        float sacc[8][4];
#pragma unroll
        for (int n = 0; n < 8; ++n)
#pragma unroll
            for (int u = 0; u < 4; ++u) sacc[n][u] = 0.f;

#pragma unroll
        for (int t = 0; t < 8; ++t) {
#pragma unroll
            for (int n = 0; n < 8; ++n) {
                uint32_t r4[4];
                ldmx4(r4, st + (n * 8 + rowlane) * KSTRIDE + t * 32 + poff16 +
                          plo * OFF_KL);
                MMA_F16S(sacc[n], fqh[t], r4[0], r4[1]);
                MMA_F16S(sacc[n], fqh[t], r4[2], r4[3]);
                MMA_F16S(sacc[n], fql[t], r4[0], r4[1]);
            }
        }

        // ---- online softmax ----
        float rmax0 = -1e30f, rmax1 = -1e30f;
#pragma unroll
        for (int n = 0; n < 8; ++n) {
            rmax0 = fmaxf(rmax0, fmaxf(sacc[n][0], sacc[n][1]));
            rmax1 = fmaxf(rmax1, fmaxf(sacc[n][2], sacc[n][3]));
        }
        rmax0 = fmaxf(rmax0, __shfl_xor_sync(0xffffffffu, rmax0, 1));
        rmax0 = fmaxf(rmax0, __shfl_xor_sync(0xffffffffu, rmax0, 2));
        rmax1 = fmaxf(rmax1, __shfl_xor_sync(0xffffffffu, rmax1, 1));
        rmax1 = fmaxf(rmax1, __shfl_xor_sync(0xffffffffu, rmax1, 2));

        float nm0 = fmaxf(m0, rmax0), nm1 = fmaxf(m1, rmax1);
        float f0 = __expf(m0 - nm0),  f1 = __expf(m1 - nm1);
        m0 = nm0; m1 = nm1;

        float sum0 = 0.f, sum1 = 0.f;
#pragma unroll
        for (int n = 0; n < 8; ++n) {
            float p0 = __expf(sacc[n][0] - nm0);
            float p1 = __expf(sacc[n][1] - nm0);
            float p2 = __expf(sacc[n][2] - nm1);
            float p3 = __expf(sacc[n][3] - nm1);
            sum0 += p0 + p1; sum1 += p2 + p3;
            sacc[n][0] = p0; sacc[n][1] = p1; sacc[n][2] = p2; sacc[n][3] = p3;
        }
        sum0 += __shfl_xor_sync(0xffffffffu, sum0, 1);
        sum0 += __shfl_xor_sync(0xffffffffu, sum0, 2);
        sum1 += __shfl_xor_sync(0xffffffffu, sum1, 1);
        sum1 += __shfl_xor_sync(0xffffffffu, sum1, 2);
        l0 = l0 * f0 + sum0;
        l1 = l1 * f1 + sum1;

        // P -> hi A fragments (register repack, hi only)
        uint32_t pah[4][4];
#pragma unroll
        for (int t = 0; t < 4; ++t) {
#pragma unroll
            for (int hw = 0; hw < 2; ++hw) {
                const float* pv = sacc[2 * t + hw];
#pragma unroll
                for (int uu = 0; uu < 2; ++uu) {
                    __half2 hp = __floats2half2_rn(pv[2 * uu], pv[2 * uu + 1]);
                    pah[t][hw * 2 + uu] = *(uint32_t*)&hp;
                }
            }
        }

#pragma unroll
        for (int nf = 0; nf < 16; ++nf) {
            oacc[nf][0] *= f0; oacc[nf][1] *= f0;
            oacc[nf][2] *= f1; oacc[nf][3] *= f1;
        }

        // ---- O += Ph*(Vh+Vl)  (2-pass PV) ----
#pragma unroll
        for (int t = 0; t < 4; ++t) {
#pragma unroll
            for (int nf = 0; nf < 16; ++nf) {
                uint32_t r4[4];
                ldmx4(r4, st + OFF_VH + (nf * 8 + rowlane) * VSTRIDE + t * 32 +
                          poff16 + plo * (OFF_VL - OFF_VH));
                MMA_F16S(oacc[nf], pah[t], r4[0], r4[1]);
                MMA_F16S(oacc[nf], pah[t], r4[2], r4[3]);
            }
        }
        __syncthreads();
    }

    // ---- epilogue: normalize, store fp16 hi only ----
    float inv0 = 1.0f / l0, inv1 = 1.0f / l1;
    int r0 = q0 + w * 16 + g;
#pragma unroll
    for (int nf = 0; nf < 16; ++nf) {
        int col = nf * 8 + 2 * q;
        {
            size_t off = (size_t)(b * S_ + r0) * DIM_ + h * HD_ + col;
            *(__half2*)(Oh + off) =
                __floats2half2_rn(oacc[nf][0] * inv0, oacc[nf][1] * inv0);
        }
        {
            size_t off = (size_t)(b * S_ + r0 + 8) * DIM_ + h * HD_ + col;
            *(__half2*)(Oh + off) =
                __floats2half2_rn(oacc[nf][2] * inv1, oacc[nf][3] * inv1);
        }
    }
}

// ============================================================================
// launch
// ============================================================================
extern "C" void kernel_launch(void* const* d_in, const int* in_sizes, int n_in,
                              void* d_out, int out_size)
{
    const float* x  = (const float*)d_in[0];
    const float* wq = (const float*)d_in[1];
    const float* wk = (const float*)d_in[2];
    const float* wv = (const float*)d_in[3];
    const float* wo = (const float*)d_in[4];
    const float* fc = (const float*)d_in[5];
    const float* fs = (const float*)d_in[6];
    float* out = (float*)d_out;

    __half *xh, *wbh, *woh, *ah;
    __half *qsh, *qsl, *ksh, *ksl, *vth, *vtl;
    cudaGetSymbolAddress((void**)&xh, g_xh);
    cudaGetSymbolAddress((void**)&wbh, g_wbh);
    cudaGetSymbolAddress((void**)&woh, g_woh);
    cudaGetSymbolAddress((void**)&ah, g_ah);
    cudaGetSymbolAddress((void**)&qsh, g_qsh); cudaGetSymbolAddress((void**)&qsl, g_qsl);
    cudaGetSymbolAddress((void**)&ksh, g_ksh); cudaGetSymbolAddress((void**)&ksl, g_ksl);
    cudaGetSymbolAddress((void**)&vth, g_vth); cudaGetSymbolAddress((void**)&vtl, g_vtl);

    const int GEMM_SMEM = 3 * STAGE_B;   // 110592
    cudaFuncSetAttribute(gemm_qkv, cudaFuncAttributeMaxDynamicSharedMemorySize,
                         GEMM_SMEM);
    cudaFuncSetAttribute(gemm_mma, cudaFuncAttributeMaxDynamicSharedMemorySize,
                         GEMM_SMEM);
    const int ATTN_SMEM = 2 * STG;       // 143360
    cudaFuncSetAttribute(attn_mma, cudaFuncAttributeMaxDynamicSharedMemorySize,
                         ATTN_SMEM);

    const int M = B_ * S_;               // 4096

    // launch 0: all prep fused (weights hi-only)
    prep_all<<<dim3(128, 128, 5), dim3(32, 8)>>>(
        x, wq, wk, wv, wo, xh, wbh, woh);

    // launch 1: fused QKV projection (single-pass weights)
    gemm_qkv<<<dim3(NQKV / 128, M / 128), 256, GEMM_SMEM>>>(
        xh, wbh, fc, fs, qsh, qsl, ksh, ksl, vth, vtl);

    // launch 2: attention
    attn_mma<<<dim3(S_ / 128, NH_, B_), 256, ATTN_SMEM>>>(
        qsh, qsl, ksh, ksl, vth, vtl, ah);

    // launch 3: output projection (single-pass weights)
    gemm_mma<<<dim3(DIM_ / 128, M / 128), 256, GEMM_SMEM>>>(
        ah, woh, out, M, DIM_, DIM_);
}